// round 8
// baseline (speedup 1.0000x reference)
#include <cuda_runtime.h>
#include <math.h>

#define BATCH 4096
#define AGENTS 32
#define NROWS (BATCH*AGENTS)      // 131072
#define NACT 16

// ---------------- scratch (device globals; no allocation) ----------------
__device__ float g_Wemb[384*128];
__device__ float g_bemb[384];
__device__ float g_Wqkv[768*64];
__device__ float g_W1[256*384];
__device__ float g_W2[256*256];
__device__ float g_emb[(size_t)NROWS*384];   // [local(256) | intra(64) | inter->pooled(64)]
__device__ float g_qkv[(size_t)NROWS*768];   // 4 nets x 192
__device__ float g_mha[(size_t)NROWS*256];   // 4 nets x 64 (post-Wo)
__device__ float g_h1[(size_t)NROWS*256];
__device__ float g_h2[(size_t)NROWS*256];

__device__ __forceinline__ float softplusf(float x) {
    return x > 20.0f ? x : log1pf(__expf(x));
}
__device__ __forceinline__ unsigned rna_tf32(float x) {
    unsigned r; asm("cvt.rna.tf32.f32 %0, %1;" : "=r"(r) : "f"(x)); return r;
}
__device__ __forceinline__ float rndf(float x) {
    return __uint_as_float(rna_tf32(x));
}
__device__ __forceinline__ void mma_tf32(float* c, const unsigned* a, unsigned b0, unsigned b1) {
    asm volatile("mma.sync.aligned.m16n8k8.row.col.f32.tf32.tf32.f32 "
                 "{%0,%1,%2,%3},{%4,%5,%6,%7},{%8,%9},{%0,%1,%2,%3};"
                 : "+f"(c[0]), "+f"(c[1]), "+f"(c[2]), "+f"(c[3])
                 : "r"(a[0]), "r"(a[1]), "r"(a[2]), "r"(a[3]), "r"(b0), "r"(b1));
}
__device__ __forceinline__ void cp16(unsigned s, const float* g) {
    asm volatile("cp.async.ca.shared.global [%0], [%1], 16;\n" :: "r"(s), "l"(g));
}

// ---------------- pack + tf32-round weights ----------------
__global__ void pack_w(const float* __restrict__ Wl, const float* __restrict__ bl,
                       const float* __restrict__ Wi, const float* __restrict__ bi,
                       const float* __restrict__ Wt, const float* __restrict__ bt,
                       const float* __restrict__ Wqkv,
                       const float* __restrict__ W1, const float* __restrict__ W2) {
    int idx = blockIdx.x * blockDim.x + threadIdx.x;
    if (idx < 384*128) {
        int row = idx >> 7, col = idx & 127;
        float v;
        if (row < 256)      v = Wl[row*128 + col];
        else if (row < 320) v = Wt[(row-256)*128 + col];
        else                v = Wi[(row-320)*128 + col];
        g_Wemb[idx] = rndf(v);
    }
    if (idx < 768*64)  g_Wqkv[idx] = rndf(Wqkv[idx]);
    if (idx < 256*384) g_W1[idx]   = rndf(W1[idx]);
    if (idx < 256*256) g_W2[idx]   = rndf(W2[idx]);
    if (idx < 384)
        g_bemb[idx] = (idx < 256) ? bl[idx] : (idx < 320 ? bt[idx-256] : bi[idx-320]);
}

// ---------------- TF32 tensor-core GEMM ----------------
// Y = epi(X[m,:K].W[n,:K] + bias[n]).  BM=128, BN=128, BK=32, double-buffered,
// one __syncthreads per stage. 256 thr, warps 2(m)x4(n), warp tile 64x32.
// W pre-rounded tf32; X pre-rounded unless CVTX. z batches via strides.
#define KSTR 36
template<int EPI, int CVTX>   // EPI: 0 = bias, 1 = bias + tanh + tf32-round
__global__ __launch_bounds__(256) void gemm_tc(
    const float* __restrict__ X, int ldx,
    const float* __restrict__ W, const float* __restrict__ bias,
    float* __restrict__ Y, int ldy, int K,
    int bsX, int bsW, int bsB, int bsY)
{
    extern __shared__ float smem[];
    float* Xs = smem;                    // [2][128*KSTR]
    float* Ws = smem + 2*128*KSTR;       // [2][128*KSTR]

    const int z = blockIdx.z;
    X += (size_t)z * bsX; W += (size_t)z * bsW; bias += (size_t)z * bsB; Y += (size_t)z * bsY;

    const int tid = threadIdx.x;
    const int m0 = blockIdx.x * 128, n0 = blockIdx.y * 128;
    const int warp = tid >> 5, lane = tid & 31;
    const int wm = (warp & 1) * 64, wn = (warp >> 1) * 32;
    const int l4 = lane >> 2, l2 = lane & 3;

    // g2s: row = tid/2 (0..127), k base = (tid&1)*16, quarters {0,4,8,12}
    const int grow = tid >> 1, gk = (tid & 1) << 4;

    unsigned xs0 = (unsigned)__cvta_generic_to_shared(Xs);
    unsigned ws0 = (unsigned)__cvta_generic_to_shared(Ws);

    float acc[4][4][4];
#pragma unroll
    for (int a = 0; a < 4; a++)
#pragma unroll
        for (int b = 0; b < 4; b++)
#pragma unroll
            for (int c = 0; c < 4; c++) acc[a][b][c] = 0.0f;

    const int nstage = K >> 5;
    const float* Xrow = X + (size_t)(m0 + grow) * ldx + gk;
    const float* Wrow = W + (size_t)(n0 + grow) * K + gk;

    // prologue: stage 0
#pragma unroll
    for (int q = 0; q < 16; q += 4) {
        cp16(xs0 + (grow*KSTR + gk + q)*4, Xrow + q);
        cp16(ws0 + (grow*KSTR + gk + q)*4, Wrow + q);
    }
    asm volatile("cp.async.commit_group;\n");

    for (int s = 0; s < nstage; s++) {
        asm volatile("cp.async.wait_group 0;\n");
        __syncthreads();   // stage-s data visible; stage-(s-1) readers all done

        if (s + 1 < nstage) {
            int k0 = (s + 1) << 5;
            unsigned xb = xs0 + ((s+1)&1) * 128*KSTR*4;
            unsigned wb = ws0 + ((s+1)&1) * 128*KSTR*4;
#pragma unroll
            for (int q = 0; q < 16; q += 4) {
                cp16(xb + (grow*KSTR + gk + q)*4, Xrow + k0 + q);
                cp16(wb + (grow*KSTR + gk + q)*4, Wrow + k0 + q);
            }
            asm volatile("cp.async.commit_group;\n");
        }

        const float* Xb = Xs + (s & 1) * 128*KSTR;
        const float* Wb = Ws + (s & 1) * 128*KSTR;
#pragma unroll
        for (int k8 = 0; k8 < 32; k8 += 8) {
            unsigned afr[4][4];
#pragma unroll
            for (int mf = 0; mf < 4; mf++) {
                const float* ap = Xb + (wm + mf*16 + l4)*KSTR + k8 + l2;
                if (CVTX) {
                    afr[mf][0] = rna_tf32(ap[0]);
                    afr[mf][1] = rna_tf32(ap[8*KSTR]);
                    afr[mf][2] = rna_tf32(ap[4]);
                    afr[mf][3] = rna_tf32(ap[8*KSTR + 4]);
                } else {
                    afr[mf][0] = *(const unsigned*)&ap[0];
                    afr[mf][1] = *(const unsigned*)&ap[8*KSTR];
                    afr[mf][2] = *(const unsigned*)&ap[4];
                    afr[mf][3] = *(const unsigned*)&ap[8*KSTR + 4];
                }
            }
#pragma unroll
            for (int nf = 0; nf < 4; nf++) {
                const float* bp = Wb + (wn + nf*8 + l4)*KSTR + k8 + l2;
                unsigned b0 = *(const unsigned*)&bp[0];
                unsigned b1 = *(const unsigned*)&bp[4];
#pragma unroll
                for (int mf = 0; mf < 4; mf++)
                    mma_tf32(acc[mf][nf], afr[mf], b0, b1);
            }
        }
    }

    // epilogue
#pragma unroll
    for (int nf = 0; nf < 4; nf++) {
        int col = n0 + wn + nf*8 + l2*2;
        float bb0 = bias[col], bb1 = bias[col + 1];
#pragma unroll
        for (int mf = 0; mf < 4; mf++) {
            int row = m0 + wm + mf*16 + l4;
            float v0 = acc[mf][nf][0] + bb0, v1 = acc[mf][nf][1] + bb1;
            float v2 = acc[mf][nf][2] + bb0, v3 = acc[mf][nf][3] + bb1;
            if (EPI == 1) {
                v0 = rndf(tanhf(v0)); v1 = rndf(tanhf(v1));
                v2 = rndf(tanhf(v2)); v3 = rndf(tanhf(v3));
            }
            float2 o01; o01.x = v0; o01.y = v1;
            float2 o23; o23.x = v2; o23.y = v3;
            *(float2*)(Y + (size_t)row * ldy + col) = o01;
            *(float2*)(Y + (size_t)(row + 8) * ldy + col) = o23;
        }
    }
}
#define GEMM_SMEM (4*128*KSTR*4)   // 73728 bytes

// ---------------- attention + Wo fused: per (b, net) ----------------
__global__ __launch_bounds__(128) void attn_wo_kernel(
    const float* __restrict__ qkv, const float* __restrict__ Wo,
    const float* __restrict__ bo, float* __restrict__ mha)
{
    __shared__ float s[32][196];        // [agent][q(64)|k(64)|v(64)]
    __shared__ float satto[32][65];     // attention output, conflict-free stride
    const int b = blockIdx.x, net = blockIdx.y;
    const int tid = threadIdx.x;

    const float* base = qkv + (size_t)b * 32 * 768 + net * 192;
    for (int i = tid; i < 1536; i += 128) {
        int row = i / 48, col = (i % 48) * 4;
        float4 v = *(const float4*)(base + (size_t)row * 768 + col);
        s[row][col+0] = v.x; s[row][col+1] = v.y; s[row][col+2] = v.z; s[row][col+3] = v.w;
    }
    __syncthreads();

    const int h = tid >> 5, qi = tid & 31;
    float q[16];
#pragma unroll
    for (int d = 0; d < 16; d++) q[d] = s[qi][h*16 + d];

    float sc[32];
#pragma unroll 4
    for (int ki = 0; ki < 32; ki++) {
        float dot = 0.0f;
#pragma unroll
        for (int d = 0; d < 16; d++) dot += q[d] * s[ki][64 + h*16 + d];
        sc[ki] = dot * 0.25f;
    }
    float mx = sc[0];
#pragma unroll
    for (int ki = 1; ki < 32; ki++) mx = fmaxf(mx, sc[ki]);
    float sum = 0.0f;
#pragma unroll
    for (int ki = 0; ki < 32; ki++) { sc[ki] = __expf(sc[ki] - mx); sum += sc[ki]; }
    float rs = 1.0f / sum;

    float o[16];
#pragma unroll
    for (int j = 0; j < 16; j++) o[j] = 0.0f;
#pragma unroll 4
    for (int ki = 0; ki < 32; ki++) {
        float p = sc[ki];
#pragma unroll
        for (int j = 0; j < 16; j++) o[j] += p * s[ki][128 + h*16 + j];
    }
    __syncthreads();   // all reads of s done
#pragma unroll
    for (int j = 0; j < 16; j++) satto[qi][h*16 + j] = o[j] * rs;

    // overlay Wo_net [64][65] into s
    float* sWo = &s[0][0];
    for (int i = tid; i < 4096; i += 128) {
        int n = i >> 6, k = i & 63;
        sWo[n*65 + k] = Wo[(size_t)net*4096 + n*64 + k];
    }
    __syncthreads();

    // mha[qi][net*64 + h*16 + j] = satto[qi][:] . Wo[h*16+j][:] + bo
    float macc[16];
#pragma unroll
    for (int j = 0; j < 16; j++) macc[j] = bo[net*64 + h*16 + j];
#pragma unroll 4
    for (int k = 0; k < 64; k++) {
        float a = satto[qi][k];
#pragma unroll
        for (int j = 0; j < 16; j++) macc[j] += a * sWo[(h*16 + j)*65 + k];
    }
    float* op = mha + (size_t)(b*32 + qi) * 256 + net*64 + h*16;
#pragma unroll
    for (int j = 0; j < 16; j += 4) {
        float4 v; v.x = macc[j]; v.y = macc[j+1]; v.z = macc[j+2]; v.w = macc[j+3];
        *(float4*)(op + j) = v;
    }
}

// ---------------- reparameterise + softmax pooling: per batch ----------------
__global__ __launch_bounds__(256) void reparam_pool_kernel(
    const float* __restrict__ eps_intra, const float* __restrict__ eps_inter,
    const float* __restrict__ att_w, const float* __restrict__ att_b)
{
    __shared__ float sinter[32][65];
    __shared__ float ssc[32];
    const int b = blockIdx.x, tid = threadIdx.x;

    // phase 1: intra -> g_emb, inter -> smem
#pragma unroll
    for (int i = 0; i < 8; i++) {
        int idx = tid + i*256;
        int r = idx >> 6, c = idx & 63;
        const float* mh = g_mha + (size_t)(b*32 + r) * 256;
        float intra = mh[c] + softplusf(mh[64 + c] - 5.0f) * eps_intra[(size_t)(b*32 + r)*64 + c];
        g_emb[(size_t)(b*32 + r)*384 + 256 + c] = rndf(intra);
        float inter = mh[128 + c] + softplusf(mh[192 + c] - 5.0f) * eps_inter[(size_t)(b*32 + r)*64 + c];
        sinter[r][c] = inter;
    }
    __syncthreads();

    // phase 2: per-row pooling logits (warp w does rows 4w..4w+3)
    const int warp = tid >> 5, lane = tid & 31;
#pragma unroll
    for (int rr = 0; rr < 4; rr++) {
        int r = warp*4 + rr;
        float part = sinter[r][lane] * att_w[lane] + sinter[r][lane+32] * att_w[lane+32];
#pragma unroll
        for (int m = 16; m > 0; m >>= 1) part += __shfl_xor_sync(0xffffffffu, part, m);
        if (lane == 0) ssc[r] = part + att_b[0];
    }
    __syncthreads();

    // phase 3: softmax over 32 agents (warp 0)
    if (warp == 0) {
        float l = ssc[lane];
        float mx = l;
#pragma unroll
        for (int m = 16; m > 0; m >>= 1) mx = fmaxf(mx, __shfl_xor_sync(0xffffffffu, mx, m));
        float e = __expf(l - mx);
        float sm = e;
#pragma unroll
        for (int m = 16; m > 0; m >>= 1) sm += __shfl_xor_sync(0xffffffffu, sm, m);
        ssc[lane] = e / sm;
    }
    __syncthreads();

    // phase 4: pooled[c] = sum_r score[r]*inter[r][c]; broadcast to all rows
    if (tid < 64) {
        float pooled = 0.0f;
#pragma unroll
        for (int r = 0; r < 32; r++) pooled += ssc[r] * sinter[r][tid];
        pooled = rndf(pooled);
#pragma unroll
        for (int r = 0; r < 32; r++)
            g_emb[(size_t)(b*32 + r)*384 + 320 + tid] = pooled;
    }
}

// ---------------- fused action/value head: 16 rows per block ----------------
__global__ __launch_bounds__(256) void head_kernel(
    const float* __restrict__ Wa, const float* __restrict__ ba,
    const float* __restrict__ Wv, const float* __restrict__ bv,
    float* __restrict__ out)
{
    __shared__ float4 sh4[16][65];
    __shared__ float4 swa4[16][65];
    __shared__ float4 swv4[64];
    const int tid = threadIdx.x;
    const int r0 = blockIdx.x * 16;

    for (int i = tid; i < 1024; i += 256) {
        int row = i >> 6, c4 = i & 63;
        sh4[row][c4]  = *(const float4*)(g_h2 + (size_t)(r0 + row) * 256 + c4*4);
        swa4[row][c4] = *(const float4*)(Wa + row * 256 + c4*4);
    }
    if (tid < 64) swv4[tid] = *(const float4*)(Wv + tid*4);
    __syncthreads();

    const int r = tid >> 4, o = tid & 15;
    float acc = 0.0f;
#pragma unroll 8
    for (int k = 0; k < 64; k++) {
        float4 h = sh4[r][k], w = swa4[o][k];
        acc += h.x*w.x + h.y*w.y + h.z*w.z + h.w*w.w;
    }
    acc += ba[o];

    float vacc = 0.0f;
#pragma unroll
    for (int k = 0; k < 4; k++) {
        float4 h = sh4[r][o*4 + k], w = swv4[o*4 + k];
        vacc += h.x*w.x + h.y*w.y + h.z*w.z + h.w*w.w;
    }

    float mx = acc;
#pragma unroll
    for (int m = 8; m > 0; m >>= 1) mx = fmaxf(mx, __shfl_xor_sync(0xffffffffu, mx, m));
    float ex = __expf(acc - mx);
    float sum = ex;
#pragma unroll
    for (int m = 8; m > 0; m >>= 1) sum += __shfl_xor_sync(0xffffffffu, sum, m);
    float lse = mx + logf(sum);

    out[(size_t)(r0 + r) * 16 + o] = acc - lse;

    float vs = vacc;
#pragma unroll
    for (int m = 8; m > 0; m >>= 1) vs += __shfl_xor_sync(0xffffffffu, vs, m);
    if (o == 0) out[(size_t)NROWS * 16 + r0 + r] = vs + bv[0];
}

// ---------------- launch ----------------
extern "C" void kernel_launch(void* const* d_in, const int* in_sizes, int n_in,
                              void* d_out, int out_size) {
    const float* obs       = (const float*)d_in[0];
    const float* eps_intra = (const float*)d_in[1];
    const float* eps_inter = (const float*)d_in[2];
    const float* W_local   = (const float*)d_in[3];
    const float* b_local   = (const float*)d_in[4];
    const float* W_inter   = (const float*)d_in[5];
    const float* b_inter   = (const float*)d_in[6];
    const float* W_intra   = (const float*)d_in[7];
    const float* b_intra   = (const float*)d_in[8];
    const float* Wqkv      = (const float*)d_in[9];
    const float* bqkv      = (const float*)d_in[10];
    const float* Wo        = (const float*)d_in[11];
    const float* bo        = (const float*)d_in[12];
    const float* att_w     = (const float*)d_in[13];
    const float* att_b     = (const float*)d_in[14];
    const float* W1        = (const float*)d_in[15];
    const float* b1        = (const float*)d_in[16];
    const float* W2        = (const float*)d_in[17];
    const float* b2        = (const float*)d_in[18];
    const float* Wa        = (const float*)d_in[19];
    const float* ba        = (const float*)d_in[20];
    const float* Wv        = (const float*)d_in[21];
    const float* bv        = (const float*)d_in[22];
    float* out = (float*)d_out;

    float *p_emb, *p_qkv, *p_mha, *p_h1, *p_h2;
    float *p_Wemb, *p_bemb, *p_Wqkv, *p_W1, *p_W2;
    cudaGetSymbolAddress((void**)&p_emb,  g_emb);
    cudaGetSymbolAddress((void**)&p_qkv,  g_qkv);
    cudaGetSymbolAddress((void**)&p_mha,  g_mha);
    cudaGetSymbolAddress((void**)&p_h1,   g_h1);
    cudaGetSymbolAddress((void**)&p_h2,   g_h2);
    cudaGetSymbolAddress((void**)&p_Wemb, g_Wemb);
    cudaGetSymbolAddress((void**)&p_bemb, g_bemb);
    cudaGetSymbolAddress((void**)&p_Wqkv, g_Wqkv);
    cudaGetSymbolAddress((void**)&p_W1,   g_W1);
    cudaGetSymbolAddress((void**)&p_W2,   g_W2);

    cudaFuncSetAttribute(gemm_tc<1,1>, cudaFuncAttributeMaxDynamicSharedMemorySize, GEMM_SMEM);
    cudaFuncSetAttribute(gemm_tc<0,0>, cudaFuncAttributeMaxDynamicSharedMemorySize, GEMM_SMEM);
    cudaFuncSetAttribute(gemm_tc<1,0>, cudaFuncAttributeMaxDynamicSharedMemorySize, GEMM_SMEM);

    const int MB = NROWS / 128;   // 1024

    // 1) pack + round weights
    pack_w<<<384, 256>>>(W_local, b_local, W_inter, b_inter, W_intra, b_intra,
                         Wqkv, W1, W2);

    // 2) embeddings: [local | intra_e | inter_e] = round(tanh(obs @ Wemb^T + b))
    gemm_tc<1,1><<<dim3(MB, 3, 1), 256, GEMM_SMEM>>>(obs, 128, p_Wemb, p_bemb,
                                                     p_emb, 384, 128, 0, 0, 0, 0);

    // 3) qkv: z=0 -> nets 0,1 from intra_e; z=1 -> nets 2,3 from inter_e
    gemm_tc<0,0><<<dim3(MB, 3, 2), 256, GEMM_SMEM>>>(p_emb + 256, 384, p_Wqkv, bqkv,
                                                     p_qkv, 768, 64,
                                                     64, 384*64, 384, 384);

    // 4) attention + Wo fused (writes mha directly)
    attn_wo_kernel<<<dim3(BATCH, 4), 128>>>(p_qkv, Wo, bo, p_mha);

    // 5) reparameterise + softmax pooling per batch
    reparam_pool_kernel<<<BATCH, 256>>>(eps_intra, eps_inter, att_w, att_b);

    // 6) MLP
    gemm_tc<1,0><<<dim3(MB, 2, 1), 256, GEMM_SMEM>>>(p_emb, 384, p_W1, b1,
                                                     p_h1, 256, 384, 0, 0, 0, 0);
    gemm_tc<1,0><<<dim3(MB, 2, 1), 256, GEMM_SMEM>>>(p_h1, 256, p_W2, b2,
                                                     p_h2, 256, 256, 0, 0, 0, 0);

    // 7) fused action/value head with log-softmax
    head_kernel<<<NROWS/16, 256>>>(Wa, ba, Wv, bv, out);
}

// round 9
// speedup vs baseline: 1.0368x; 1.0368x over previous
#include <cuda_runtime.h>
#include <math.h>

#define BATCH 4096
#define AGENTS 32
#define NROWS (BATCH*AGENTS)      // 131072
#define NACT 16

// ---------------- scratch (device globals; no allocation) ----------------
__device__ float g_Wemb[384*128];
__device__ float g_bemb[384];
__device__ float g_Wqkv[768*64];
__device__ float g_Wo256[256*256];           // block-diagonal Wo
__device__ float g_W1[256*384];
__device__ float g_W2[256*256];
__device__ float g_emb[(size_t)NROWS*384];   // [local(256) | intra(64) | inter->pooled(64)]
__device__ float g_qkv[(size_t)NROWS*768];   // 4 nets x 192
__device__ float g_atto[(size_t)NROWS*256];  // attention out (pre-Wo), 4 nets x 64
__device__ float g_mha[(size_t)NROWS*256];   // post-Wo

__device__ __forceinline__ float softplusf(float x) {
    return x > 20.0f ? x : log1pf(__expf(x));
}
__device__ __forceinline__ unsigned rna_tf32(float x) {
    unsigned r; asm("cvt.rna.tf32.f32 %0, %1;" : "=r"(r) : "f"(x)); return r;
}
__device__ __forceinline__ float rndf(float x) {
    return __uint_as_float(rna_tf32(x));
}
__device__ __forceinline__ void mma_tf32(float* c, const unsigned* a, unsigned b0, unsigned b1) {
    asm volatile("mma.sync.aligned.m16n8k8.row.col.f32.tf32.tf32.f32 "
                 "{%0,%1,%2,%3},{%4,%5,%6,%7},{%8,%9},{%0,%1,%2,%3};"
                 : "+f"(c[0]), "+f"(c[1]), "+f"(c[2]), "+f"(c[3])
                 : "r"(a[0]), "r"(a[1]), "r"(a[2]), "r"(a[3]), "r"(b0), "r"(b1));
}
__device__ __forceinline__ void cp16(unsigned s, const float* g) {
    asm volatile("cp.async.ca.shared.global [%0], [%1], 16;\n" :: "r"(s), "l"(g));
}

// ---------------- pack + tf32-round weights ----------------
__global__ void pack_w(const float* __restrict__ Wl, const float* __restrict__ bl,
                       const float* __restrict__ Wi, const float* __restrict__ bi,
                       const float* __restrict__ Wt, const float* __restrict__ bt,
                       const float* __restrict__ Wqkv, const float* __restrict__ Wo,
                       const float* __restrict__ W1, const float* __restrict__ W2) {
    int idx = blockIdx.x * blockDim.x + threadIdx.x;
    if (idx < 384*128) {
        int row = idx >> 7, col = idx & 127;
        float v;
        if (row < 256)      v = Wl[row*128 + col];
        else if (row < 320) v = Wt[(row-256)*128 + col];
        else                v = Wi[(row-320)*128 + col];
        g_Wemb[idx] = rndf(v);
    }
    if (idx < 768*64)  g_Wqkv[idx] = rndf(Wqkv[idx]);
    if (idx < 256*256) {                       // block-diag Wo
        int row = idx >> 8, col = idx & 255;
        int net = row >> 6;
        float v = ((col >> 6) == net) ? Wo[net*4096 + (row & 63)*64 + (col & 63)] : 0.0f;
        g_Wo256[idx] = rndf(v);
    }
    if (idx < 256*384) g_W1[idx] = rndf(W1[idx]);
    if (idx < 256*256) g_W2[idx] = rndf(W2[idx]);
    if (idx < 384)
        g_bemb[idx] = (idx < 256) ? bl[idx] : (idx < 320 ? bt[idx-256] : bi[idx-320]);
}

// ---------------- TF32 tensor-core GEMM (validated round 8) ----------------
// BM=128, BN=128, BK=32, double-buffered, one __syncthreads per stage.
#define KSTR 36
template<int EPI, int CVTX>   // EPI: 0 = bias, 1 = bias + tanh + tf32-round
__global__ __launch_bounds__(256) void gemm_tc(
    const float* __restrict__ X, int ldx,
    const float* __restrict__ W, const float* __restrict__ bias,
    float* __restrict__ Y, int ldy, int K,
    int bsX, int bsW, int bsB, int bsY)
{
    extern __shared__ float smem[];
    float* Xs = smem;
    float* Ws = smem + 2*128*KSTR;

    const int z = blockIdx.z;
    X += (size_t)z * bsX; W += (size_t)z * bsW; bias += (size_t)z * bsB; Y += (size_t)z * bsY;

    const int tid = threadIdx.x;
    const int m0 = blockIdx.x * 128, n0 = blockIdx.y * 128;
    const int warp = tid >> 5, lane = tid & 31;
    const int wm = (warp & 1) * 64, wn = (warp >> 1) * 32;
    const int l4 = lane >> 2, l2 = lane & 3;
    const int grow = tid >> 1, gk = (tid & 1) << 4;

    unsigned xs0 = (unsigned)__cvta_generic_to_shared(Xs);
    unsigned ws0 = (unsigned)__cvta_generic_to_shared(Ws);

    float acc[4][4][4];
#pragma unroll
    for (int a = 0; a < 4; a++)
#pragma unroll
        for (int b = 0; b < 4; b++)
#pragma unroll
            for (int c = 0; c < 4; c++) acc[a][b][c] = 0.0f;

    const int nstage = K >> 5;
    const float* Xrow = X + (size_t)(m0 + grow) * ldx + gk;
    const float* Wrow = W + (size_t)(n0 + grow) * K + gk;

#pragma unroll
    for (int q = 0; q < 16; q += 4) {
        cp16(xs0 + (grow*KSTR + gk + q)*4, Xrow + q);
        cp16(ws0 + (grow*KSTR + gk + q)*4, Wrow + q);
    }
    asm volatile("cp.async.commit_group;\n");

    for (int s = 0; s < nstage; s++) {
        asm volatile("cp.async.wait_group 0;\n");
        __syncthreads();

        if (s + 1 < nstage) {
            int k0 = (s + 1) << 5;
            unsigned xb = xs0 + ((s+1)&1) * 128*KSTR*4;
            unsigned wb = ws0 + ((s+1)&1) * 128*KSTR*4;
#pragma unroll
            for (int q = 0; q < 16; q += 4) {
                cp16(xb + (grow*KSTR + gk + q)*4, Xrow + k0 + q);
                cp16(wb + (grow*KSTR + gk + q)*4, Wrow + k0 + q);
            }
            asm volatile("cp.async.commit_group;\n");
        }

        const float* Xb = Xs + (s & 1) * 128*KSTR;
        const float* Wb = Ws + (s & 1) * 128*KSTR;
#pragma unroll
        for (int k8 = 0; k8 < 32; k8 += 8) {
            unsigned afr[4][4];
#pragma unroll
            for (int mf = 0; mf < 4; mf++) {
                const float* ap = Xb + (wm + mf*16 + l4)*KSTR + k8 + l2;
                if (CVTX) {
                    afr[mf][0] = rna_tf32(ap[0]);
                    afr[mf][1] = rna_tf32(ap[8*KSTR]);
                    afr[mf][2] = rna_tf32(ap[4]);
                    afr[mf][3] = rna_tf32(ap[8*KSTR + 4]);
                } else {
                    afr[mf][0] = *(const unsigned*)&ap[0];
                    afr[mf][1] = *(const unsigned*)&ap[8*KSTR];
                    afr[mf][2] = *(const unsigned*)&ap[4];
                    afr[mf][3] = *(const unsigned*)&ap[8*KSTR + 4];
                }
            }
#pragma unroll
            for (int nf = 0; nf < 4; nf++) {
                const float* bp = Wb + (wn + nf*8 + l4)*KSTR + k8 + l2;
                unsigned b0 = *(const unsigned*)&bp[0];
                unsigned b1 = *(const unsigned*)&bp[4];
#pragma unroll
                for (int mf = 0; mf < 4; mf++)
                    mma_tf32(acc[mf][nf], afr[mf], b0, b1);
            }
        }
    }

#pragma unroll
    for (int nf = 0; nf < 4; nf++) {
        int col = n0 + wn + nf*8 + l2*2;
        float bb0 = bias[col], bb1 = bias[col + 1];
#pragma unroll
        for (int mf = 0; mf < 4; mf++) {
            int row = m0 + wm + mf*16 + l4;
            float v0 = acc[mf][nf][0] + bb0, v1 = acc[mf][nf][1] + bb1;
            float v2 = acc[mf][nf][2] + bb0, v3 = acc[mf][nf][3] + bb1;
            if (EPI == 1) {
                v0 = rndf(tanhf(v0)); v1 = rndf(tanhf(v1));
                v2 = rndf(tanhf(v2)); v3 = rndf(tanhf(v3));
            }
            float2 o01; o01.x = v0; o01.y = v1;
            float2 o23; o23.x = v2; o23.y = v3;
            *(float2*)(Y + (size_t)row * ldy + col) = o01;
            *(float2*)(Y + (size_t)(row + 8) * ldy + col) = o23;
        }
    }
}
#define GEMM_SMEM (4*128*KSTR*4)   // 73728 bytes

// ---------------- attention core (vectorized smem): per (b, net) ----------------
__global__ __launch_bounds__(128) void attn_kernel(const float* __restrict__ qkv,
                                                   float* __restrict__ atto) {
    __shared__ float s[32][200];   // 200*4 = 800B row stride: 16B-aligned rows
    const int b = blockIdx.x, net = blockIdx.y;
    const int tid = threadIdx.x;

    const float* base = qkv + (size_t)b * 32 * 768 + net * 192;
    for (int i = tid; i < 1536; i += 128) {      // 1536 float4s
        int row = i / 48, c4 = i % 48;
        *(float4*)&s[row][c4*4] = *(const float4*)(base + (size_t)row * 768 + c4*4);
    }
    __syncthreads();

    const int h = tid >> 5, qi = tid & 31;
    float4 q4[4];
    {
        const float4* qp = (const float4*)&s[qi][h*16];
#pragma unroll
        for (int i = 0; i < 4; i++) q4[i] = qp[i];
    }

    float sc[32];
#pragma unroll 4
    for (int ki = 0; ki < 32; ki++) {
        const float4* kp = (const float4*)&s[ki][64 + h*16];
        float4 k0 = kp[0], k1 = kp[1], k2 = kp[2], k3 = kp[3];
        float dot = q4[0].x*k0.x + q4[0].y*k0.y + q4[0].z*k0.z + q4[0].w*k0.w
                  + q4[1].x*k1.x + q4[1].y*k1.y + q4[1].z*k1.z + q4[1].w*k1.w
                  + q4[2].x*k2.x + q4[2].y*k2.y + q4[2].z*k2.z + q4[2].w*k2.w
                  + q4[3].x*k3.x + q4[3].y*k3.y + q4[3].z*k3.z + q4[3].w*k3.w;
        sc[ki] = dot * 0.25f;
    }
    float mx = sc[0];
#pragma unroll
    for (int ki = 1; ki < 32; ki++) mx = fmaxf(mx, sc[ki]);
    float sum = 0.0f;
#pragma unroll
    for (int ki = 0; ki < 32; ki++) { sc[ki] = __expf(sc[ki] - mx); sum += sc[ki]; }
    float rs = 1.0f / sum;

    float4 o0 = {0,0,0,0}, o1 = {0,0,0,0}, o2 = {0,0,0,0}, o3 = {0,0,0,0};
#pragma unroll 4
    for (int ki = 0; ki < 32; ki++) {
        float p = sc[ki];
        const float4* vp = (const float4*)&s[ki][128 + h*16];
        float4 v0 = vp[0], v1 = vp[1], v2 = vp[2], v3 = vp[3];
        o0.x += p*v0.x; o0.y += p*v0.y; o0.z += p*v0.z; o0.w += p*v0.w;
        o1.x += p*v1.x; o1.y += p*v1.y; o1.z += p*v1.z; o1.w += p*v1.w;
        o2.x += p*v2.x; o2.y += p*v2.y; o2.z += p*v2.z; o2.w += p*v2.w;
        o3.x += p*v3.x; o3.y += p*v3.y; o3.z += p*v3.z; o3.w += p*v3.w;
    }
    float* op = atto + (size_t)(b*32 + qi) * 256 + net*64 + h*16;
    float4 w0, w1, w2, w3;
    w0.x = rndf(o0.x*rs); w0.y = rndf(o0.y*rs); w0.z = rndf(o0.z*rs); w0.w = rndf(o0.w*rs);
    w1.x = rndf(o1.x*rs); w1.y = rndf(o1.y*rs); w1.z = rndf(o1.z*rs); w1.w = rndf(o1.w*rs);
    w2.x = rndf(o2.x*rs); w2.y = rndf(o2.y*rs); w2.z = rndf(o2.z*rs); w2.w = rndf(o2.w*rs);
    w3.x = rndf(o3.x*rs); w3.y = rndf(o3.y*rs); w3.z = rndf(o3.z*rs); w3.w = rndf(o3.w*rs);
    *(float4*)(op + 0)  = w0; *(float4*)(op + 4)  = w1;
    *(float4*)(op + 8)  = w2; *(float4*)(op + 12) = w3;
}

// ---------------- reparameterise + softmax pooling: per batch ----------------
__global__ __launch_bounds__(256) void reparam_pool_kernel(
    const float* __restrict__ eps_intra, const float* __restrict__ eps_inter,
    const float* __restrict__ att_w, const float* __restrict__ att_b)
{
    __shared__ float sinter[32][65];
    __shared__ float ssc[32];
    const int b = blockIdx.x, tid = threadIdx.x;

#pragma unroll
    for (int i = 0; i < 8; i++) {
        int idx = tid + i*256;
        int r = idx >> 6, c = idx & 63;
        const float* mh = g_mha + (size_t)(b*32 + r) * 256;
        float intra = mh[c] + softplusf(mh[64 + c] - 5.0f) * eps_intra[(size_t)(b*32 + r)*64 + c];
        g_emb[(size_t)(b*32 + r)*384 + 256 + c] = rndf(intra);
        float inter = mh[128 + c] + softplusf(mh[192 + c] - 5.0f) * eps_inter[(size_t)(b*32 + r)*64 + c];
        sinter[r][c] = inter;
    }
    __syncthreads();

    const int warp = tid >> 5, lane = tid & 31;
#pragma unroll
    for (int rr = 0; rr < 4; rr++) {
        int r = warp*4 + rr;
        float part = sinter[r][lane] * att_w[lane] + sinter[r][lane+32] * att_w[lane+32];
#pragma unroll
        for (int m = 16; m > 0; m >>= 1) part += __shfl_xor_sync(0xffffffffu, part, m);
        if (lane == 0) ssc[r] = part + att_b[0];
    }
    __syncthreads();

    if (warp == 0) {
        float l = ssc[lane];
        float mx = l;
#pragma unroll
        for (int m = 16; m > 0; m >>= 1) mx = fmaxf(mx, __shfl_xor_sync(0xffffffffu, mx, m));
        float e = __expf(l - mx);
        float sm = e;
#pragma unroll
        for (int m = 16; m > 0; m >>= 1) sm += __shfl_xor_sync(0xffffffffu, sm, m);
        ssc[lane] = e / sm;
    }
    __syncthreads();

    if (tid < 64) {
        float pooled = 0.0f;
#pragma unroll
        for (int r = 0; r < 32; r++) pooled += ssc[r] * sinter[r][tid];
        pooled = rndf(pooled);
#pragma unroll
        for (int r = 0; r < 32; r++)
            g_emb[(size_t)(b*32 + r)*384 + 320 + tid] = pooled;
    }
}

// ---------------- fused MLP + head: 64 rows per block, h1/h2 smem-resident ----------------
// smem: h1s[64*260] | Xs[2][64*36] | Ws[2][256*36]
#define MH_H1   (64*260)
#define MH_XS   (2*64*36)
#define MH_WS   (2*256*36)
#define MH_SMEM ((MH_H1 + MH_XS + MH_WS)*4)   // 158720 bytes

__global__ __launch_bounds__(256, 1) void mlp_head_kernel(
    const float* __restrict__ b1, const float* __restrict__ b2,
    const float* __restrict__ Wa, const float* __restrict__ ba,
    const float* __restrict__ Wv, const float* __restrict__ bv,
    float* __restrict__ out)
{
    extern __shared__ float smem[];
    float* h1s = smem;                       // [64][260]
    float* Xs  = smem + MH_H1;               // [2][64*36]
    float* Ws  = smem + MH_H1 + MH_XS;       // [2][256*36]

    const int tid = threadIdx.x;
    const int m0 = blockIdx.x * 64;
    const int warp = tid >> 5, lane = tid & 31;
    const int wn = warp * 32;
    const int l4 = lane >> 2, l2 = lane & 3;
    const int grow = tid >> 2, gk = (tid & 3) << 3;   // row 0..63, k {0,8,16,24}

    unsigned xs0 = (unsigned)__cvta_generic_to_shared(Xs);
    unsigned ws0 = (unsigned)__cvta_generic_to_shared(Ws);

    float acc[4][4][4];

    // ================= Phase A: h1 = rnd(tanh(emb @ W1^T + b1)), K=384, N=256 ========
#pragma unroll
    for (int a = 0; a < 4; a++)
#pragma unroll
        for (int b = 0; b < 4; b++)
#pragma unroll
            for (int c = 0; c < 4; c++) acc[a][b][c] = 0.0f;

    const float* Xrow = g_emb + (size_t)(m0 + grow) * 384 + gk;

    // prologue
#pragma unroll
    for (int q = 0; q < 8; q += 4)
        cp16(xs0 + (grow*36 + gk + q)*4, Xrow + q);
#pragma unroll
    for (int i = 0; i < 4; i++) {
        const float* wr = g_W1 + (size_t)(grow + 64*i) * 384 + gk;
#pragma unroll
        for (int q = 0; q < 8; q += 4)
            cp16(ws0 + ((grow + 64*i)*36 + gk + q)*4, wr + q);
    }
    asm volatile("cp.async.commit_group;\n");

    for (int s = 0; s < 12; s++) {
        asm volatile("cp.async.wait_group 0;\n");
        __syncthreads();

        if (s + 1 < 12) {
            int k0 = (s + 1) << 5;
            unsigned xb = xs0 + ((s+1)&1) * 64*36*4;
            unsigned wb = ws0 + ((s+1)&1) * 256*36*4;
#pragma unroll
            for (int q = 0; q < 8; q += 4)
                cp16(xb + (grow*36 + gk + q)*4, Xrow + k0 + q);
#pragma unroll
            for (int i = 0; i < 4; i++) {
                const float* wr = g_W1 + (size_t)(grow + 64*i) * 384 + k0 + gk;
#pragma unroll
                for (int q = 0; q < 8; q += 4)
                    cp16(wb + ((grow + 64*i)*36 + gk + q)*4, wr + q);
            }
            asm volatile("cp.async.commit_group;\n");
        }

        const float* Xb = Xs + (s & 1) * 64*36;
        const float* Wb = Ws + (s & 1) * 256*36;
#pragma unroll
        for (int k8 = 0; k8 < 32; k8 += 8) {
            unsigned afr[4][4];
#pragma unroll
            for (int mf = 0; mf < 4; mf++) {
                const float* ap = Xb + (mf*16 + l4)*36 + k8 + l2;
                afr[mf][0] = *(const unsigned*)&ap[0];
                afr[mf][1] = *(const unsigned*)&ap[8*36];
                afr[mf][2] = *(const unsigned*)&ap[4];
                afr[mf][3] = *(const unsigned*)&ap[8*36 + 4];
            }
#pragma unroll
            for (int nf = 0; nf < 4; nf++) {
                const float* bp = Wb + (wn + nf*8 + l4)*36 + k8 + l2;
                unsigned b0 = *(const unsigned*)&bp[0];
                unsigned b1r = *(const unsigned*)&bp[4];
#pragma unroll
                for (int mf = 0; mf < 4; mf++)
                    mma_tf32(acc[mf][nf], afr[mf], b0, b1r);
            }
        }
    }

    // epilogue A -> h1s
#pragma unroll
    for (int nf = 0; nf < 4; nf++) {
        int col = wn + nf*8 + l2*2;
        float bb0 = b1[col], bb1 = b1[col + 1];
#pragma unroll
        for (int mf = 0; mf < 4; mf++) {
            int row = mf*16 + l4;
            h1s[row*260 + col]       = rndf(tanhf(acc[mf][nf][0] + bb0));
            h1s[row*260 + col + 1]   = rndf(tanhf(acc[mf][nf][1] + bb1));
            h1s[(row+8)*260 + col]   = rndf(tanhf(acc[mf][nf][2] + bb0));
            h1s[(row+8)*260 + col+1] = rndf(tanhf(acc[mf][nf][3] + bb1));
        }
    }
    __syncthreads();   // h1s complete; Xs/Ws free

    // ================= Phase B: h2 = tanh(h1 @ W2^T + b2), K=256, N=256 ==============
#pragma unroll
    for (int a = 0; a < 4; a++)
#pragma unroll
        for (int b = 0; b < 4; b++)
#pragma unroll
            for (int c = 0; c < 4; c++) acc[a][b][c] = 0.0f;

#pragma unroll
    for (int i = 0; i < 4; i++) {
        const float* wr = g_W2 + (size_t)(grow + 64*i) * 256 + gk;
#pragma unroll
        for (int q = 0; q < 8; q += 4)
            cp16(ws0 + ((grow + 64*i)*36 + gk + q)*4, wr + q);
    }
    asm volatile("cp.async.commit_group;\n");

    for (int s = 0; s < 8; s++) {
        asm volatile("cp.async.wait_group 0;\n");
        __syncthreads();

        if (s + 1 < 8) {
            int k0 = (s + 1) << 5;
            unsigned wb = ws0 + ((s+1)&1) * 256*36*4;
#pragma unroll
            for (int i = 0; i < 4; i++) {
                const float* wr = g_W2 + (size_t)(grow + 64*i) * 256 + k0 + gk;
#pragma unroll
                for (int q = 0; q < 8; q += 4)
                    cp16(wb + ((grow + 64*i)*36 + gk + q)*4, wr + q);
            }
            asm volatile("cp.async.commit_group;\n");
        }

        const float* Wb = Ws + (s & 1) * 256*36;
        const int kbase = s << 5;
#pragma unroll
        for (int k8 = 0; k8 < 32; k8 += 8) {
            unsigned afr[4][4];
#pragma unroll
            for (int mf = 0; mf < 4; mf++) {
                const float* ap = h1s + (mf*16 + l4)*260 + kbase + k8 + l2;
                afr[mf][0] = *(const unsigned*)&ap[0];
                afr[mf][1] = *(const unsigned*)&ap[8*260];
                afr[mf][2] = *(const unsigned*)&ap[4];
                afr[mf][3] = *(const unsigned*)&ap[8*260 + 4];
            }
#pragma unroll
            for (int nf = 0; nf < 4; nf++) {
                const float* bp = Wb + (wn + nf*8 + l4)*36 + k8 + l2;
                unsigned b0 = *(const unsigned*)&bp[0];
                unsigned b1r = *(const unsigned*)&bp[4];
#pragma unroll
                for (int mf = 0; mf < 4; mf++)
                    mma_tf32(acc[mf][nf], afr[mf], b0, b1r);
            }
        }
    }
    __syncthreads();   // all h1s reads done before overwrite

    // epilogue B -> h1s (reuse as h2 buffer, full fp32)
#pragma unroll
    for (int nf = 0; nf < 4; nf++) {
        int col = wn + nf*8 + l2*2;
        float bb0 = b2[col], bb1 = b2[col + 1];
#pragma unroll
        for (int mf = 0; mf < 4; mf++) {
            int row = mf*16 + l4;
            h1s[row*260 + col]       = tanhf(acc[mf][nf][0] + bb0);
            h1s[row*260 + col + 1]   = tanhf(acc[mf][nf][1] + bb1);
            h1s[(row+8)*260 + col]   = tanhf(acc[mf][nf][2] + bb0);
            h1s[(row+8)*260 + col+1] = tanhf(acc[mf][nf][3] + bb1);
        }
    }

    // load Wa/Wv into Xs region (dead)
    float* sWa = Xs;                 // [16][260]
    float* sWv = Xs + 16*260;        // [256]
    for (int i = tid; i < 16*256; i += 256) {
        int o = i >> 8, k = i & 255;
        sWa[o*260 + k] = Wa[o*256 + k];
    }
    sWv[tid] = Wv[tid];
    __syncthreads();

    // ================= Phase C: head (log-softmax + value) ==========================
    const int r_ = tid >> 4, o = tid & 15;
#pragma unroll
    for (int rr = 0; rr < 4; rr++) {
        int r = rr*16 + r_;
        const float4* hp = (const float4*)&h1s[r*260];
        const float4* wp = (const float4*)&sWa[o*260];
        float a = 0.0f;
#pragma unroll 8
        for (int k = 0; k < 64; k++) {
            float4 h = hp[k], w = wp[k];
            a += h.x*w.x + h.y*w.y + h.z*w.z + h.w*w.w;
        }
        a += ba[o];

        float vacc = 0.0f;
#pragma unroll
        for (int k = 0; k < 4; k++) {
            float4 h = hp[o*4 + k];
            float4 w = *(const float4*)&sWv[o*16 + k*4];
            vacc += h.x*w.x + h.y*w.y + h.z*w.z + h.w*w.w;
        }

        float mx = a;
#pragma unroll
        for (int m = 8; m > 0; m >>= 1) mx = fmaxf(mx, __shfl_xor_sync(0xffffffffu, mx, m));
        float ex = __expf(a - mx);
        float sum = ex;
#pragma unroll
        for (int m = 8; m > 0; m >>= 1) sum += __shfl_xor_sync(0xffffffffu, sum, m);
        float lse = mx + logf(sum);

        out[(size_t)(m0 + r) * 16 + o] = a - lse;

        float vs = vacc;
#pragma unroll
        for (int m = 8; m > 0; m >>= 1) vs += __shfl_xor_sync(0xffffffffu, vs, m);
        if (o == 0) out[(size_t)NROWS * 16 + m0 + r] = vs + bv[0];
    }
}

// ---------------- launch ----------------
extern "C" void kernel_launch(void* const* d_in, const int* in_sizes, int n_in,
                              void* d_out, int out_size) {
    const float* obs       = (const float*)d_in[0];
    const float* eps_intra = (const float*)d_in[1];
    const float* eps_inter = (const float*)d_in[2];
    const float* W_local   = (const float*)d_in[3];
    const float* b_local   = (const float*)d_in[4];
    const float* W_inter   = (const float*)d_in[5];
    const float* b_inter   = (const float*)d_in[6];
    const float* W_intra   = (const float*)d_in[7];
    const float* b_intra   = (const float*)d_in[8];
    const float* Wqkv      = (const float*)d_in[9];
    const float* bqkv      = (const float*)d_in[10];
    const float* Wo        = (const float*)d_in[11];
    const float* bo        = (const float*)d_in[12];
    const float* att_w     = (const float*)d_in[13];
    const float* att_b     = (const float*)d_in[14];
    const float* W1        = (const float*)d_in[15];
    const float* b1        = (const float*)d_in[16];
    const float* W2        = (const float*)d_in[17];
    const float* b2        = (const float*)d_in[18];
    const float* Wa        = (const float*)d_in[19];
    const float* ba        = (const float*)d_in[20];
    const float* Wv        = (const float*)d_in[21];
    const float* bv        = (const float*)d_in[22];
    float* out = (float*)d_out;

    float *p_emb, *p_qkv, *p_atto, *p_mha;
    float *p_Wemb, *p_bemb, *p_Wqkv, *p_Wo256, *p_W1, *p_W2;
    cudaGetSymbolAddress((void**)&p_emb,   g_emb);
    cudaGetSymbolAddress((void**)&p_qkv,   g_qkv);
    cudaGetSymbolAddress((void**)&p_atto,  g_atto);
    cudaGetSymbolAddress((void**)&p_mha,   g_mha);
    cudaGetSymbolAddress((void**)&p_Wemb,  g_Wemb);
    cudaGetSymbolAddress((void**)&p_bemb,  g_bemb);
    cudaGetSymbolAddress((void**)&p_Wqkv,  g_Wqkv);
    cudaGetSymbolAddress((void**)&p_Wo256, g_Wo256);
    cudaGetSymbolAddress((void**)&p_W1,    g_W1);
    cudaGetSymbolAddress((void**)&p_W2,    g_W2);

    cudaFuncSetAttribute(gemm_tc<1,1>, cudaFuncAttributeMaxDynamicSharedMemorySize, GEMM_SMEM);
    cudaFuncSetAttribute(gemm_tc<0,0>, cudaFuncAttributeMaxDynamicSharedMemorySize, GEMM_SMEM);
    cudaFuncSetAttribute(mlp_head_kernel, cudaFuncAttributeMaxDynamicSharedMemorySize, MH_SMEM);

    const int MB = NROWS / 128;   // 1024

    // 1) pack + round weights (incl. block-diag Wo)
    pack_w<<<384, 256>>>(W_local, b_local, W_inter, b_inter, W_intra, b_intra,
                         Wqkv, Wo, W1, W2);

    // 2) embeddings
    gemm_tc<1,1><<<dim3(MB, 3, 1), 256, GEMM_SMEM>>>(obs, 128, p_Wemb, p_bemb,
                                                     p_emb, 384, 128, 0, 0, 0, 0);

    // 3) qkv: z=0 nets 0,1 from intra_e; z=1 nets 2,3 from inter_e
    gemm_tc<0,0><<<dim3(MB, 3, 2), 256, GEMM_SMEM>>>(p_emb + 256, 384, p_Wqkv, bqkv,
                                                     p_qkv, 768, 64,
                                                     64, 384*64, 384, 384);

    // 4) attention core (vectorized, writes rounded atto)
    attn_kernel<<<dim3(BATCH, 4), 128>>>(p_qkv, p_atto);

    // 5) Wo projection: block-diagonal tensor GEMM, one launch
    gemm_tc<0,0><<<dim3(MB, 2, 1), 256, GEMM_SMEM>>>(p_atto, 256, p_Wo256, bo,
                                                     p_mha, 256, 256, 0, 0, 0, 0);

    // 6) reparameterise + softmax pooling
    reparam_pool_kernel<<<BATCH, 256>>>(eps_intra, eps_inter, att_w, att_b);

    // 7) fused MLP (W1+W2) + action/value head
    mlp_head_kernel<<<NROWS/64, 256, MH_SMEM>>>(b1, b2, Wa, ba, Wv, bv, out);
}

// round 10
// speedup vs baseline: 1.0843x; 1.0458x over previous
#include <cuda_runtime.h>
#include <math.h>

#define BATCH 4096
#define AGENTS 32
#define NROWS (BATCH*AGENTS)      // 131072
#define NACT 16

// ---------------- scratch (device globals; no allocation) ----------------
__device__ float g_Wemb[384*128];
__device__ float g_bemb[384];
__device__ float g_Wqkv[768*64];             // [net][192][64], tf32-rounded
__device__ float g_Wo[4*64*64];              // [net][64][64],  tf32-rounded
__device__ float g_W1[256*384];
__device__ float g_W2[256*256];
__device__ float g_emb[(size_t)NROWS*384];   // [local(256) | intra(64) | inter->pooled(64)]
__device__ float g_mha[(size_t)NROWS*256];   // post-Wo, 4 nets x 64
__device__ float g_h1[(size_t)NROWS*256];
__device__ float g_h2[(size_t)NROWS*256];

__device__ __forceinline__ float softplusf(float x) {
    return x > 20.0f ? x : log1pf(__expf(x));
}
__device__ __forceinline__ unsigned rna_tf32(float x) {
    unsigned r; asm("cvt.rna.tf32.f32 %0, %1;" : "=r"(r) : "f"(x)); return r;
}
__device__ __forceinline__ float rndf(float x) {
    return __uint_as_float(rna_tf32(x));
}
__device__ __forceinline__ void mma_tf32(float* c, const unsigned* a, unsigned b0, unsigned b1) {
    asm volatile("mma.sync.aligned.m16n8k8.row.col.f32.tf32.tf32.f32 "
                 "{%0,%1,%2,%3},{%4,%5,%6,%7},{%8,%9},{%0,%1,%2,%3};"
                 : "+f"(c[0]), "+f"(c[1]), "+f"(c[2]), "+f"(c[3])
                 : "r"(a[0]), "r"(a[1]), "r"(a[2]), "r"(a[3]), "r"(b0), "r"(b1));
}
__device__ __forceinline__ void cp16(unsigned s, const float* g) {
    asm volatile("cp.async.ca.shared.global [%0], [%1], 16;\n" :: "r"(s), "l"(g));
}

// ---------------- pack + tf32-round weights ----------------
__global__ void pack_w(const float* __restrict__ Wl, const float* __restrict__ bl,
                       const float* __restrict__ Wi, const float* __restrict__ bi,
                       const float* __restrict__ Wt, const float* __restrict__ bt,
                       const float* __restrict__ Wqkv, const float* __restrict__ Wo,
                       const float* __restrict__ W1, const float* __restrict__ W2) {
    int idx = blockIdx.x * blockDim.x + threadIdx.x;
    if (idx < 384*128) {
        int row = idx >> 7, col = idx & 127;
        float v;
        if (row < 256)      v = Wl[row*128 + col];
        else if (row < 320) v = Wt[(row-256)*128 + col];
        else                v = Wi[(row-320)*128 + col];
        g_Wemb[idx] = rndf(v);
    }
    if (idx < 768*64)   g_Wqkv[idx] = rndf(Wqkv[idx]);
    if (idx < 4*64*64)  g_Wo[idx]   = rndf(Wo[idx]);
    if (idx < 256*384)  g_W1[idx]   = rndf(W1[idx]);
    if (idx < 256*256)  g_W2[idx]   = rndf(W2[idx]);
    if (idx < 384)
        g_bemb[idx] = (idx < 256) ? bl[idx] : (idx < 320 ? bt[idx-256] : bi[idx-320]);
}

// ---------------- TF32 tensor-core GEMM (validated r8/r9) ----------------
// BM=128, BN=128, BK=32, double-buffered, one __syncthreads per stage.
#define KSTR 36
template<int EPI, int CVTX>   // EPI: 0 = bias, 1 = bias + tanh + tf32-round
__global__ __launch_bounds__(256) void gemm_tc(
    const float* __restrict__ X, int ldx,
    const float* __restrict__ W, const float* __restrict__ bias,
    float* __restrict__ Y, int ldy, int K,
    int bsX, int bsW, int bsB, int bsY)
{
    extern __shared__ float smem[];
    float* Xs = smem;
    float* Ws = smem + 2*128*KSTR;

    const int z = blockIdx.z;
    X += (size_t)z * bsX; W += (size_t)z * bsW; bias += (size_t)z * bsB; Y += (size_t)z * bsY;

    const int tid = threadIdx.x;
    const int m0 = blockIdx.x * 128, n0 = blockIdx.y * 128;
    const int warp = tid >> 5, lane = tid & 31;
    const int wm = (warp & 1) * 64, wn = (warp >> 1) * 32;
    const int l4 = lane >> 2, l2 = lane & 3;
    const int grow = tid >> 1, gk = (tid & 1) << 4;

    unsigned xs0 = (unsigned)__cvta_generic_to_shared(Xs);
    unsigned ws0 = (unsigned)__cvta_generic_to_shared(Ws);

    float acc[4][4][4];
#pragma unroll
    for (int a = 0; a < 4; a++)
#pragma unroll
        for (int b = 0; b < 4; b++)
#pragma unroll
            for (int c = 0; c < 4; c++) acc[a][b][c] = 0.0f;

    const int nstage = K >> 5;
    const float* Xrow = X + (size_t)(m0 + grow) * ldx + gk;
    const float* Wrow = W + (size_t)(n0 + grow) * K + gk;

#pragma unroll
    for (int q = 0; q < 16; q += 4) {
        cp16(xs0 + (grow*KSTR + gk + q)*4, Xrow + q);
        cp16(ws0 + (grow*KSTR + gk + q)*4, Wrow + q);
    }
    asm volatile("cp.async.commit_group;\n");

    for (int s = 0; s < nstage; s++) {
        asm volatile("cp.async.wait_group 0;\n");
        __syncthreads();

        if (s + 1 < nstage) {
            int k0 = (s + 1) << 5;
            unsigned xb = xs0 + ((s+1)&1) * 128*KSTR*4;
            unsigned wb = ws0 + ((s+1)&1) * 128*KSTR*4;
#pragma unroll
            for (int q = 0; q < 16; q += 4) {
                cp16(xb + (grow*KSTR + gk + q)*4, Xrow + k0 + q);
                cp16(wb + (grow*KSTR + gk + q)*4, Wrow + k0 + q);
            }
            asm volatile("cp.async.commit_group;\n");
        }

        const float* Xb = Xs + (s & 1) * 128*KSTR;
        const float* Wb = Ws + (s & 1) * 128*KSTR;
#pragma unroll
        for (int k8 = 0; k8 < 32; k8 += 8) {
            unsigned afr[4][4];
#pragma unroll
            for (int mf = 0; mf < 4; mf++) {
                const float* ap = Xb + (wm + mf*16 + l4)*KSTR + k8 + l2;
                if (CVTX) {
                    afr[mf][0] = rna_tf32(ap[0]);
                    afr[mf][1] = rna_tf32(ap[8*KSTR]);
                    afr[mf][2] = rna_tf32(ap[4]);
                    afr[mf][3] = rna_tf32(ap[8*KSTR + 4]);
                } else {
                    afr[mf][0] = *(const unsigned*)&ap[0];
                    afr[mf][1] = *(const unsigned*)&ap[8*KSTR];
                    afr[mf][2] = *(const unsigned*)&ap[4];
                    afr[mf][3] = *(const unsigned*)&ap[8*KSTR + 4];
                }
            }
#pragma unroll
            for (int nf = 0; nf < 4; nf++) {
                const float* bp = Wb + (wn + nf*8 + l4)*KSTR + k8 + l2;
                unsigned b0 = *(const unsigned*)&bp[0];
                unsigned b1 = *(const unsigned*)&bp[4];
#pragma unroll
                for (int mf = 0; mf < 4; mf++)
                    mma_tf32(acc[mf][nf], afr[mf], b0, b1);
            }
        }
    }

#pragma unroll
    for (int nf = 0; nf < 4; nf++) {
        int col = n0 + wn + nf*8 + l2*2;
        float bb0 = bias[col], bb1 = bias[col + 1];
#pragma unroll
        for (int mf = 0; mf < 4; mf++) {
            int row = m0 + wm + mf*16 + l4;
            float v0 = acc[mf][nf][0] + bb0, v1 = acc[mf][nf][1] + bb1;
            float v2 = acc[mf][nf][2] + bb0, v3 = acc[mf][nf][3] + bb1;
            if (EPI == 1) {
                v0 = rndf(tanhf(v0)); v1 = rndf(tanhf(v1));
                v2 = rndf(tanhf(v2)); v3 = rndf(tanhf(v3));
            }
            float2 o01; o01.x = v0; o01.y = v1;
            float2 o23; o23.x = v2; o23.y = v3;
            *(float2*)(Y + (size_t)row * ldy + col) = o01;
            *(float2*)(Y + (size_t)(row + 8) * ldy + col) = o23;
        }
    }
}
#define GEMM_SMEM (4*128*KSTR*4)   // 73728 bytes

// ---------------- fused qkv GEMM + attention + Wo GEMM ----------------
// One block per (128 rows = 4 batches, net). Phases:
//   A: qkv[128,192] = emb_slice[128,64] @ Wqkv_net^T  (tensor core, smem out)
//   B: attention per (batch, head): 16 warp-tasks on 8 warps (scalar fp32)
//   C: mha[128,64] = satto[128,64] @ Wo_net^T         (tensor core)
#define FQ_QSTR  196
#define FQ_XSTR  68
#define FQ_ASTR  76
#define FQ_XS_OFF   (128*FQ_QSTR)               // 25088
#define FQ_WS_OFF   (FQ_XS_OFF + 128*FQ_XSTR)   // 33792
#define FQ_SA_OFF   FQ_XS_OFF                   // overlay Xs/Ws (dead after A)
#define FQ_WO_OFF   (FQ_SA_OFF + 128*FQ_ASTR)   // 34816
#define FQ_END      (FQ_WS_OFF + 192*FQ_XSTR)   // 46848
#define FQ_SMEM     (FQ_END*4)                  // 187392 bytes

__global__ __launch_bounds__(256, 1) void qkv_attn_wo_kernel(
    const float* __restrict__ bqkv, const float* __restrict__ bo)
{
    extern __shared__ float sm[];
    float* Qs = sm;                    // [128][196]  q|k|v
    float* Xs = sm + FQ_XS_OFF;        // [128][68]
    float* Ws = sm + FQ_WS_OFF;        // [192][68]
    float* Sa = sm + FQ_SA_OFF;        // [128][76]   attn out (overlay)
    float* Wo = sm + FQ_WO_OFF;        // [64][68]

    const int tid = threadIdx.x, warp = tid >> 5, lane = tid & 31;
    const int net = blockIdx.y;
    const int m0 = blockIdx.x * 128;
    const int l4 = lane >> 2, l2 = lane & 3;

    // ---- load X (emb slice) and W (qkv weights, L2-resident) ----
    const int xoff = 256 + ((net >= 2) ? 64 : 0);
    {
        int row = tid >> 1, kb = (tid & 1) * 32;
        const float* src = g_emb + (size_t)(m0 + row) * 384 + xoff + kb;
        unsigned dst = (unsigned)__cvta_generic_to_shared(Xs + row*FQ_XSTR + kb);
#pragma unroll
        for (int q = 0; q < 32; q += 4) cp16(dst + q*4, src + q);
        if (row < 64) {   // W rows 128..191 by tid < 128
            int wrow = row + 128;
            const float* wsrc = g_Wqkv + ((size_t)net*192 + wrow) * 64 + kb;
            unsigned wdst = (unsigned)__cvta_generic_to_shared(Ws + wrow*FQ_XSTR + kb);
#pragma unroll
            for (int q = 0; q < 32; q += 4) cp16(wdst + q*4, wsrc + q);
        }
        const float* wsrc = g_Wqkv + ((size_t)net*192 + row) * 64 + kb;
        unsigned wdst = (unsigned)__cvta_generic_to_shared(Ws + row*FQ_XSTR + kb);
#pragma unroll
        for (int q = 0; q < 32; q += 4) cp16(wdst + q*4, wsrc + q);
    }
    asm volatile("cp.async.commit_group;\n");
    asm volatile("cp.async.wait_group 0;\n");
    __syncthreads();

    // ---- Phase A: qkv mma. warps 2(m) x 4(n), warp tile 64x48 ----
    {
        const int wm = (warp & 1) * 64, wn = (warp >> 1) * 48;
        float acc[4][6][4];
#pragma unroll
        for (int a = 0; a < 4; a++)
#pragma unroll
            for (int b = 0; b < 6; b++)
#pragma unroll
                for (int c = 0; c < 4; c++) acc[a][b][c] = 0.0f;

#pragma unroll
        for (int k8 = 0; k8 < 64; k8 += 8) {
            unsigned afr[4][4];
#pragma unroll
            for (int mf = 0; mf < 4; mf++) {
                const float* ap = Xs + (wm + mf*16 + l4)*FQ_XSTR + k8 + l2;
                afr[mf][0] = *(const unsigned*)&ap[0];
                afr[mf][1] = *(const unsigned*)&ap[8*FQ_XSTR];
                afr[mf][2] = *(const unsigned*)&ap[4];
                afr[mf][3] = *(const unsigned*)&ap[8*FQ_XSTR + 4];
            }
#pragma unroll
            for (int nf = 0; nf < 6; nf++) {
                const float* bp = Ws + (wn + nf*8 + l4)*FQ_XSTR + k8 + l2;
                unsigned b0 = *(const unsigned*)&bp[0];
                unsigned b1 = *(const unsigned*)&bp[4];
#pragma unroll
                for (int mf = 0; mf < 4; mf++)
                    mma_tf32(acc[mf][nf], afr[mf], b0, b1);
            }
        }
        // epilogue -> Qs (fp32 + bias)
#pragma unroll
        for (int nf = 0; nf < 6; nf++) {
            int col = wn + nf*8 + l2*2;
            float bb0 = bqkv[net*192 + col], bb1 = bqkv[net*192 + col + 1];
#pragma unroll
            for (int mf = 0; mf < 4; mf++) {
                int row = wm + mf*16 + l4;
                float2 o01; o01.x = acc[mf][nf][0] + bb0; o01.y = acc[mf][nf][1] + bb1;
                float2 o23; o23.x = acc[mf][nf][2] + bb0; o23.y = acc[mf][nf][3] + bb1;
                *(float2*)&Qs[row*FQ_QSTR + col] = o01;
                *(float2*)&Qs[(row + 8)*FQ_QSTR + col] = o23;
            }
        }
    }
    __syncthreads();   // Qs complete; Xs/Ws dead

    // ---- Phase B: attention. 16 tasks (4 batches x 4 heads) over 8 warps ----
    for (int t = warp; t < 16; t += 8) {
        const int g = t >> 2, h = t & 3;
        const int qi = lane;
        const float* base = Qs + (size_t)(g*32) * FQ_QSTR;

        float4 q4[4];
        {
            const float4* qp = (const float4*)&base[qi*FQ_QSTR + h*16];
#pragma unroll
            for (int i = 0; i < 4; i++) q4[i] = qp[i];
        }
        float sc[32];
#pragma unroll 4
        for (int ki = 0; ki < 32; ki++) {
            const float4* kp = (const float4*)&base[ki*FQ_QSTR + 64 + h*16];
            float4 k0 = kp[0], k1 = kp[1], k2 = kp[2], k3 = kp[3];
            float dot = q4[0].x*k0.x + q4[0].y*k0.y + q4[0].z*k0.z + q4[0].w*k0.w
                      + q4[1].x*k1.x + q4[1].y*k1.y + q4[1].z*k1.z + q4[1].w*k1.w
                      + q4[2].x*k2.x + q4[2].y*k2.y + q4[2].z*k2.z + q4[2].w*k2.w
                      + q4[3].x*k3.x + q4[3].y*k3.y + q4[3].z*k3.z + q4[3].w*k3.w;
            sc[ki] = dot * 0.25f;
        }
        float mx = sc[0];
#pragma unroll
        for (int ki = 1; ki < 32; ki++) mx = fmaxf(mx, sc[ki]);
        float sum = 0.0f;
#pragma unroll
        for (int ki = 0; ki < 32; ki++) { sc[ki] = __expf(sc[ki] - mx); sum += sc[ki]; }
        float rs = 1.0f / sum;

        float4 o0 = {0,0,0,0}, o1 = {0,0,0,0}, o2 = {0,0,0,0}, o3 = {0,0,0,0};
#pragma unroll 4
        for (int ki = 0; ki < 32; ki++) {
            float p = sc[ki];
            const float4* vp = (const float4*)&base[ki*FQ_QSTR + 128 + h*16];
            float4 v0 = vp[0], v1 = vp[1], v2 = vp[2], v3 = vp[3];
            o0.x += p*v0.x; o0.y += p*v0.y; o0.z += p*v0.z; o0.w += p*v0.w;
            o1.x += p*v1.x; o1.y += p*v1.y; o1.z += p*v1.z; o1.w += p*v1.w;
            o2.x += p*v2.x; o2.y += p*v2.y; o2.z += p*v2.z; o2.w += p*v2.w;
            o3.x += p*v3.x; o3.y += p*v3.y; o3.z += p*v3.z; o3.w += p*v3.w;
        }
        float* op = Sa + (size_t)(g*32 + qi) * FQ_ASTR + h*16;
        float4 w0, w1, w2, w3;
        w0.x = rndf(o0.x*rs); w0.y = rndf(o0.y*rs); w0.z = rndf(o0.z*rs); w0.w = rndf(o0.w*rs);
        w1.x = rndf(o1.x*rs); w1.y = rndf(o1.y*rs); w1.z = rndf(o1.z*rs); w1.w = rndf(o1.w*rs);
        w2.x = rndf(o2.x*rs); w2.y = rndf(o2.y*rs); w2.z = rndf(o2.z*rs); w2.w = rndf(o2.w*rs);
        w3.x = rndf(o3.x*rs); w3.y = rndf(o3.y*rs); w3.z = rndf(o3.z*rs); w3.w = rndf(o3.w*rs);
        *(float4*)(op + 0)  = w0; *(float4*)(op + 4)  = w1;
        *(float4*)(op + 8)  = w2; *(float4*)(op + 12) = w3;
    }

    // load Wo_net into smem (region after Sa; Ws dead)
    for (int idx = tid; idx < 4096; idx += 256) {
        int row = idx >> 6, col = idx & 63;
        Wo[row*FQ_XSTR + col] = g_Wo[(size_t)net*4096 + idx];
    }
    __syncthreads();   // Sa + Wo ready

    // ---- Phase C: Wo mma. M=128 (2 m-warps x 4 mf), N=64 (4 n-warps x 2 nf), K=64 ----
    {
        const int wm = (warp & 1) * 64, wn = (warp >> 1) * 16;
        float acc[4][2][4];
#pragma unroll
        for (int a = 0; a < 4; a++)
#pragma unroll
            for (int b = 0; b < 2; b++)
#pragma unroll
                for (int c = 0; c < 4; c++) acc[a][b][c] = 0.0f;

#pragma unroll
        for (int k8 = 0; k8 < 64; k8 += 8) {
            unsigned afr[4][4];
#pragma unroll
            for (int mf = 0; mf < 4; mf++) {
                const float* ap = Sa + (wm + mf*16 + l4)*FQ_ASTR + k8 + l2;
                afr[mf][0] = *(const unsigned*)&ap[0];
                afr[mf][1] = *(const unsigned*)&ap[8*FQ_ASTR];
                afr[mf][2] = *(const unsigned*)&ap[4];
                afr[mf][3] = *(const unsigned*)&ap[8*FQ_ASTR + 4];
            }
#pragma unroll
            for (int nf = 0; nf < 2; nf++) {
                const float* bp = Wo + (wn + nf*8 + l4)*FQ_XSTR + k8 + l2;
                unsigned b0 = *(const unsigned*)&bp[0];
                unsigned b1 = *(const unsigned*)&bp[4];
#pragma unroll
                for (int mf = 0; mf < 4; mf++)
                    mma_tf32(acc[mf][nf], afr[mf], b0, b1);
            }
        }
        // epilogue -> g_mha
#pragma unroll
        for (int nf = 0; nf < 2; nf++) {
            int col = wn + nf*8 + l2*2;
            float bb0 = bo[net*64 + col], bb1 = bo[net*64 + col + 1];
#pragma unroll
            for (int mf = 0; mf < 4; mf++) {
                int row = wm + mf*16 + l4;
                float2 o01; o01.x = acc[mf][nf][0] + bb0; o01.y = acc[mf][nf][1] + bb1;
                float2 o23; o23.x = acc[mf][nf][2] + bb0; o23.y = acc[mf][nf][3] + bb1;
                *(float2*)(g_mha + (size_t)(m0 + row) * 256 + net*64 + col) = o01;
                *(float2*)(g_mha + (size_t)(m0 + row + 8) * 256 + net*64 + col) = o23;
            }
        }
    }
}

// ---------------- reparameterise + softmax pooling: per batch (validated r8/r9) ----------------
__global__ __launch_bounds__(256) void reparam_pool_kernel(
    const float* __restrict__ eps_intra, const float* __restrict__ eps_inter,
    const float* __restrict__ att_w, const float* __restrict__ att_b)
{
    __shared__ float sinter[32][65];
    __shared__ float ssc[32];
    const int b = blockIdx.x, tid = threadIdx.x;

#pragma unroll
    for (int i = 0; i < 8; i++) {
        int idx = tid + i*256;
        int r = idx >> 6, c = idx & 63;
        const float* mh = g_mha + (size_t)(b*32 + r) * 256;
        float intra = mh[c] + softplusf(mh[64 + c] - 5.0f) * eps_intra[(size_t)(b*32 + r)*64 + c];
        g_emb[(size_t)(b*32 + r)*384 + 256 + c] = rndf(intra);
        float inter = mh[128 + c] + softplusf(mh[192 + c] - 5.0f) * eps_inter[(size_t)(b*32 + r)*64 + c];
        sinter[r][c] = inter;
    }
    __syncthreads();

    const int warp = tid >> 5, lane = tid & 31;
#pragma unroll
    for (int rr = 0; rr < 4; rr++) {
        int r = warp*4 + rr;
        float part = sinter[r][lane] * att_w[lane] + sinter[r][lane+32] * att_w[lane+32];
#pragma unroll
        for (int m = 16; m > 0; m >>= 1) part += __shfl_xor_sync(0xffffffffu, part, m);
        if (lane == 0) ssc[r] = part + att_b[0];
    }
    __syncthreads();

    if (warp == 0) {
        float l = ssc[lane];
        float mx = l;
#pragma unroll
        for (int m = 16; m > 0; m >>= 1) mx = fmaxf(mx, __shfl_xor_sync(0xffffffffu, mx, m));
        float e = __expf(l - mx);
        float sm = e;
#pragma unroll
        for (int m = 16; m > 0; m >>= 1) sm += __shfl_xor_sync(0xffffffffu, sm, m);
        ssc[lane] = e / sm;
    }
    __syncthreads();

    if (tid < 64) {
        float pooled = 0.0f;
#pragma unroll
        for (int r = 0; r < 32; r++) pooled += ssc[r] * sinter[r][tid];
        pooled = rndf(pooled);
#pragma unroll
        for (int r = 0; r < 32; r++)
            g_emb[(size_t)(b*32 + r)*384 + 320 + tid] = pooled;
    }
}

// ---------------- fused action/value head: 16 rows per block (validated r5) ----------------
__global__ __launch_bounds__(256) void head_kernel(
    const float* __restrict__ Wa, const float* __restrict__ ba,
    const float* __restrict__ Wv, const float* __restrict__ bv,
    float* __restrict__ out)
{
    __shared__ float4 sh4[16][65];
    __shared__ float4 swa4[16][65];
    __shared__ float4 swv4[64];
    const int tid = threadIdx.x;
    const int r0 = blockIdx.x * 16;

    for (int i = tid; i < 1024; i += 256) {
        int row = i >> 6, c4 = i & 63;
        sh4[row][c4]  = *(const float4*)(g_h2 + (size_t)(r0 + row) * 256 + c4*4);
        swa4[row][c4] = *(const float4*)(Wa + row * 256 + c4*4);
    }
    if (tid < 64) swv4[tid] = *(const float4*)(Wv + tid*4);
    __syncthreads();

    const int r = tid >> 4, o = tid & 15;
    float acc = 0.0f;
#pragma unroll 8
    for (int k = 0; k < 64; k++) {
        float4 h = sh4[r][k], w = swa4[o][k];
        acc += h.x*w.x + h.y*w.y + h.z*w.z + h.w*w.w;
    }
    acc += ba[o];

    float vacc = 0.0f;
#pragma unroll
    for (int k = 0; k < 4; k++) {
        float4 h = sh4[r][o*4 + k], w = swv4[o*4 + k];
        vacc += h.x*w.x + h.y*w.y + h.z*w.z + h.w*w.w;
    }

    float mx = acc;
#pragma unroll
    for (int m = 8; m > 0; m >>= 1) mx = fmaxf(mx, __shfl_xor_sync(0xffffffffu, mx, m));
    float ex = __expf(acc - mx);
    float sum = ex;
#pragma unroll
    for (int m = 8; m > 0; m >>= 1) sum += __shfl_xor_sync(0xffffffffu, sum, m);
    float lse = mx + logf(sum);

    out[(size_t)(r0 + r) * 16 + o] = acc - lse;

    float vs = vacc;
#pragma unroll
    for (int m = 8; m > 0; m >>= 1) vs += __shfl_xor_sync(0xffffffffu, vs, m);
    if (o == 0) out[(size_t)NROWS * 16 + r0 + r] = vs + bv[0];
}

// ---------------- launch ----------------
extern "C" void kernel_launch(void* const* d_in, const int* in_sizes, int n_in,
                              void* d_out, int out_size) {
    const float* obs       = (const float*)d_in[0];
    const float* eps_intra = (const float*)d_in[1];
    const float* eps_inter = (const float*)d_in[2];
    const float* W_local   = (const float*)d_in[3];
    const float* b_local   = (const float*)d_in[4];
    const float* W_inter   = (const float*)d_in[5];
    const float* b_inter   = (const float*)d_in[6];
    const float* W_intra   = (const float*)d_in[7];
    const float* b_intra   = (const float*)d_in[8];
    const float* Wqkv      = (const float*)d_in[9];
    const float* bqkv      = (const float*)d_in[10];
    const float* Wo        = (const float*)d_in[11];
    const float* bo        = (const float*)d_in[12];
    const float* att_w     = (const float*)d_in[13];
    const float* att_b     = (const float*)d_in[14];
    const float* W1        = (const float*)d_in[15];
    const float* b1        = (const float*)d_in[16];
    const float* W2        = (const float*)d_in[17];
    const float* b2        = (const float*)d_in[18];
    const float* Wa        = (const float*)d_in[19];
    const float* ba        = (const float*)d_in[20];
    const float* Wv        = (const float*)d_in[21];
    const float* bv        = (const float*)d_in[22];
    float* out = (float*)d_out;

    float *p_emb, *p_h1, *p_h2;
    float *p_Wemb, *p_bemb, *p_W1, *p_W2;
    cudaGetSymbolAddress((void**)&p_emb,  g_emb);
    cudaGetSymbolAddress((void**)&p_h1,   g_h1);
    cudaGetSymbolAddress((void**)&p_h2,   g_h2);
    cudaGetSymbolAddress((void**)&p_Wemb, g_Wemb);
    cudaGetSymbolAddress((void**)&p_bemb, g_bemb);
    cudaGetSymbolAddress((void**)&p_W1,   g_W1);
    cudaGetSymbolAddress((void**)&p_W2,   g_W2);

    cudaFuncSetAttribute(gemm_tc<1,1>, cudaFuncAttributeMaxDynamicSharedMemorySize, GEMM_SMEM);
    cudaFuncSetAttribute(gemm_tc<1,0>, cudaFuncAttributeMaxDynamicSharedMemorySize, GEMM_SMEM);
    cudaFuncSetAttribute(qkv_attn_wo_kernel, cudaFuncAttributeMaxDynamicSharedMemorySize, FQ_SMEM);

    const int MB = NROWS / 128;   // 1024

    // 1) pack + round weights
    pack_w<<<384, 256>>>(W_local, b_local, W_inter, b_inter, W_intra, b_intra,
                         Wqkv, Wo, W1, W2);

    // 2) embeddings: [local | intra_e | inter_e]
    gemm_tc<1,1><<<dim3(MB, 3, 1), 256, GEMM_SMEM>>>(obs, 128, p_Wemb, p_bemb,
                                                     p_emb, 384, 128, 0, 0, 0, 0);

    // 3) fused qkv + attention + Wo (writes g_mha; no qkv/atto round-trips)
    qkv_attn_wo_kernel<<<dim3(MB, 4), 256, FQ_SMEM>>>(bqkv, bo);

    // 4) reparameterise + softmax pooling
    reparam_pool_kernel<<<BATCH, 256>>>(eps_intra, eps_inter, att_w, att_b);

    // 5) MLP
    gemm_tc<1,0><<<dim3(MB, 2, 1), 256, GEMM_SMEM>>>(p_emb, 384, p_W1, b1,
                                                     p_h1, 256, 384, 0, 0, 0, 0);
    gemm_tc<1,0><<<dim3(MB, 2, 1), 256, GEMM_SMEM>>>(p_h1, 256, p_W2, b2,
                                                     p_h2, 256, 256, 0, 0, 0, 0);

    // 6) fused action/value head with log-softmax
    head_kernel<<<NROWS/16, 256>>>(Wa, ba, Wv, bv, out);
}

// round 11
// speedup vs baseline: 1.4365x; 1.3248x over previous
#include <cuda_runtime.h>
#include <cuda_fp16.h>
#include <math.h>

#define BATCH 4096
#define AGENTS 32
#define NROWS (BATCH*AGENTS)      // 131072
#define NACT 16

// ---------------- scratch (device globals; no allocation) ----------------
__device__ __half g_obs_h[(size_t)NROWS*128];
__device__ __half g_Wemb_h[384*128];
__device__ float  g_bemb[384];
__device__ __half g_Wqkv_h[768*64];            // [net][192][64]
__device__ __half g_Wo_h[4*64*64];             // [net][64][64]
__device__ __half g_W1_h[256*384];
__device__ __half g_W2_h[256*256];
__device__ __half g_emb_h[(size_t)NROWS*384];  // [local(256) | intra(64) | inter->pooled(64)]
__device__ float  g_mha[(size_t)NROWS*256];    // post-Wo fp32
__device__ __half g_h1_h[(size_t)NROWS*256];
__device__ float  g_h2[(size_t)NROWS*256];

__device__ __forceinline__ float softplusf(float x) {
    return x > 20.0f ? x : log1pf(__expf(x));
}
__device__ __forceinline__ unsigned ldw(const __half* p) {   // aligned half2 word
    return *(const unsigned*)p;
}
__device__ __forceinline__ void mma_f16(float* c, const unsigned* a, unsigned b0, unsigned b1) {
    asm volatile("mma.sync.aligned.m16n8k16.row.col.f32.f16.f16.f32 "
                 "{%0,%1,%2,%3},{%4,%5,%6,%7},{%8,%9},{%0,%1,%2,%3};"
                 : "+f"(c[0]), "+f"(c[1]), "+f"(c[2]), "+f"(c[3])
                 : "r"(a[0]), "r"(a[1]), "r"(a[2]), "r"(a[3]), "r"(b0), "r"(b1));
}
__device__ __forceinline__ void cp16(unsigned s, const void* g) {
    asm volatile("cp.async.ca.shared.global [%0], [%1], 16;\n" :: "r"(s), "l"(g));
}

// ---------------- obs -> fp16 ----------------
__global__ void conv_obs(const float* __restrict__ obs) {
    size_t i = ((size_t)blockIdx.x * 256 + threadIdx.x) * 4;
    float4 v = *(const float4*)(obs + i);
    __half2* o = (__half2*)(g_obs_h + i);
    o[0] = __floats2half2_rn(v.x, v.y);
    o[1] = __floats2half2_rn(v.z, v.w);
}

// ---------------- pack weights -> fp16 ----------------
__global__ void pack_w(const float* __restrict__ Wl, const float* __restrict__ bl,
                       const float* __restrict__ Wi, const float* __restrict__ bi,
                       const float* __restrict__ Wt, const float* __restrict__ bt,
                       const float* __restrict__ Wqkv, const float* __restrict__ Wo,
                       const float* __restrict__ W1, const float* __restrict__ W2) {
    int idx = blockIdx.x * blockDim.x + threadIdx.x;
    if (idx < 384*128) {
        int row = idx >> 7, col = idx & 127;
        float v;
        if (row < 256)      v = Wl[row*128 + col];
        else if (row < 320) v = Wt[(row-256)*128 + col];
        else                v = Wi[(row-320)*128 + col];
        g_Wemb_h[idx] = __float2half_rn(v);
    }
    if (idx < 768*64)   g_Wqkv_h[idx] = __float2half_rn(Wqkv[idx]);
    if (idx < 4*64*64)  g_Wo_h[idx]   = __float2half_rn(Wo[idx]);
    if (idx < 256*384)  g_W1_h[idx]   = __float2half_rn(W1[idx]);
    if (idx < 256*256)  g_W2_h[idx]   = __float2half_rn(W2[idx]);
    if (idx < 384)
        g_bemb[idx] = (idx < 256) ? bl[idx] : (idx < 320 ? bt[idx-256] : bi[idx-320]);
}

// ---------------- FP16 tensor-core GEMM ----------------
// Y = epi(X[m,:K].W[n,:K] + bias[n]).  BM=128, BN=128, BK=32 halves, 2-stage,
// one __syncthreads per stage. 256 thr, warps 2(m)x4(n), warp tile 64x32.
// smem rows stride 40 halves (conflict-free fragment LDS).
#define HSTR 40
template<int EPI, int OUTH>  // EPI: 1 = tanh; OUTH: 1 = half out, 0 = float out
__global__ __launch_bounds__(256, 2) void gemm_h(
    const __half* __restrict__ X, int ldx,
    const __half* __restrict__ W, const float* __restrict__ bias,
    void* __restrict__ Yv, int ldy, int K)
{
    extern __shared__ __half hsm[];
    __half* Xs = hsm;                        // [2][128*HSTR]
    __half* Ws = hsm + 2*128*HSTR;           // [2][128*HSTR]

    const int tid = threadIdx.x;
    const int m0 = blockIdx.x * 128, n0 = blockIdx.y * 128;
    const int warp = tid >> 5, lane = tid & 31;
    const int wm = (warp & 1) * 64, wn = (warp >> 1) * 32;
    const int l4 = lane >> 2, l2 = lane & 3;

    const int grow = tid & 127, gmat = tid >> 7;   // 128 X rows, 128 W rows
    const __half* grsrc = gmat ? (W + (size_t)(n0 + grow) * K)
                               : (X + (size_t)(m0 + grow) * ldx);
    unsigned gdst0 = (unsigned)__cvta_generic_to_shared(
        (gmat ? Ws : Xs) + grow*HSTR);

    float acc[4][4][4];
#pragma unroll
    for (int a = 0; a < 4; a++)
#pragma unroll
        for (int b = 0; b < 4; b++)
#pragma unroll
            for (int c = 0; c < 4; c++) acc[a][b][c] = 0.0f;

    const int nstage = K >> 5;

    // prologue: stage 0 (32 halves = 4x16B per row)
#pragma unroll
    for (int q = 0; q < 4; q++)
        cp16(gdst0 + q*16, grsrc + q*8);
    asm volatile("cp.async.commit_group;\n");

    for (int s = 0; s < nstage; s++) {
        asm volatile("cp.async.wait_group 0;\n");
        __syncthreads();

        if (s + 1 < nstage) {
            int k0 = (s + 1) << 5;
            unsigned gd = gdst0 + ((s+1)&1) * 128*HSTR*2;
#pragma unroll
            for (int q = 0; q < 4; q++)
                cp16(gd + q*16, grsrc + k0 + q*8);
            asm volatile("cp.async.commit_group;\n");
        }

        const __half* Xb = Xs + (s & 1) * 128*HSTR;
        const __half* Wb = Ws + (s & 1) * 128*HSTR;
#pragma unroll
        for (int kb = 0; kb < 32; kb += 16) {
            unsigned afr[4][4];
#pragma unroll
            for (int mf = 0; mf < 4; mf++) {
                const __half* ap = Xb + (wm + mf*16 + l4)*HSTR + kb + 2*l2;
                afr[mf][0] = ldw(ap);
                afr[mf][1] = ldw(ap + 8*HSTR);
                afr[mf][2] = ldw(ap + 8);
                afr[mf][3] = ldw(ap + 8*HSTR + 8);
            }
#pragma unroll
            for (int nf = 0; nf < 4; nf++) {
                const __half* bp = Wb + (wn + nf*8 + l4)*HSTR + kb + 2*l2;
                unsigned b0 = ldw(bp);
                unsigned b1 = ldw(bp + 8);
#pragma unroll
                for (int mf = 0; mf < 4; mf++)
                    mma_f16(acc[mf][nf], afr[mf], b0, b1);
            }
        }
    }

    // epilogue
#pragma unroll
    for (int nf = 0; nf < 4; nf++) {
        int col = n0 + wn + nf*8 + l2*2;
        float bb0 = bias[col], bb1 = bias[col + 1];
#pragma unroll
        for (int mf = 0; mf < 4; mf++) {
            int row = m0 + wm + mf*16 + l4;
            float v0 = acc[mf][nf][0] + bb0, v1 = acc[mf][nf][1] + bb1;
            float v2 = acc[mf][nf][2] + bb0, v3 = acc[mf][nf][3] + bb1;
            if (EPI == 1) { v0 = tanhf(v0); v1 = tanhf(v1); v2 = tanhf(v2); v3 = tanhf(v3); }
            if (OUTH) {
                __half* Y = (__half*)Yv;
                *(__half2*)(Y + (size_t)row * ldy + col)       = __floats2half2_rn(v0, v1);
                *(__half2*)(Y + (size_t)(row + 8) * ldy + col) = __floats2half2_rn(v2, v3);
            } else {
                float* Y = (float*)Yv;
                float2 o01; o01.x = v0; o01.y = v1;
                float2 o23; o23.x = v2; o23.y = v3;
                *(float2*)(Y + (size_t)row * ldy + col) = o01;
                *(float2*)(Y + (size_t)(row + 8) * ldy + col) = o23;
            }
        }
    }
}
#define GEMMH_SMEM (4*128*HSTR*2)   // 40960 bytes

// ---------------- fused qkv GEMM + attention + Wo GEMM (fp16 MMA, BM=64) ----------------
// One block per (64 rows = 2 batches, net).
#define QSTR 196                     // Qs fp32 row stride (floats)
#define FSTR 72                      // half-matrix row stride (halves)
#define FQ_QS_BYTES (64*QSTR*4)      // 50176
#define FQ_XS_OFF   FQ_QS_BYTES
#define FQ_WS_OFF   (FQ_XS_OFF + 64*FSTR*2)    // +9216
#define FQ_WO_OFF   (FQ_WS_OFF + 192*FSTR*2)   // +27648
#define FQ_SMEM     (FQ_WO_OFF + 64*FSTR*2)    // 96256 bytes

__global__ __launch_bounds__(256, 2) void qkv_attn_wo_kernel(
    const float* __restrict__ bqkv, const float* __restrict__ bo)
{
    extern __shared__ char sm[];
    float*  Qs = (float*)sm;                       // [64][196] fp32 q|k|v
    __half* Xs = (__half*)(sm + FQ_XS_OFF);        // [64][72]
    __half* Sa = Xs;                               // overlay (Xs dead after A)
    __half* Ws = (__half*)(sm + FQ_WS_OFF);        // [192][72]
    __half* Wo = (__half*)(sm + FQ_WO_OFF);        // [64][72]

    const int tid = threadIdx.x, warp = tid >> 5, lane = tid & 31;
    const int net = blockIdx.y;
    const int m0 = blockIdx.x * 64;
    const int l4 = lane >> 2, l2 = lane & 3;

    // ---- prologue loads: X slice (64x64h), Wqkv net (192x64h), Wo net (64x64h) ----
    const int xoff = 256 + ((net >= 2) ? 64 : 0);
    {
        int xrow = tid >> 2, seg = tid & 3;        // 4 threads per X row
        const __half* src = g_emb_h + (size_t)(m0 + xrow) * 384 + xoff + seg*16;
        unsigned dst = (unsigned)__cvta_generic_to_shared(Xs + xrow*FSTR + seg*16);
        cp16(dst, src); cp16(dst + 16, src + 8);
        if (tid < 192) {
            const __half* ws = g_Wqkv_h + ((size_t)net*192 + tid) * 64;
            unsigned wd = (unsigned)__cvta_generic_to_shared(Ws + tid*FSTR);
#pragma unroll
            for (int q = 0; q < 8; q++) cp16(wd + q*16, ws + q*8);
        } else {
            int row = tid - 192;
            const __half* os = g_Wo_h + (size_t)net*4096 + row*64;
            unsigned od = (unsigned)__cvta_generic_to_shared(Wo + row*FSTR);
#pragma unroll
            for (int q = 0; q < 8; q++) cp16(od + q*16, os + q*8);
        }
    }
    asm volatile("cp.async.commit_group;\n");
    asm volatile("cp.async.wait_group 0;\n");
    __syncthreads();

    // ---- Phase A: qkv mma. M=64 (mf=4), N=192 (8 warps x 24), K=64 ----
    {
        const int wn = warp * 24;
        float acc[4][3][4];
#pragma unroll
        for (int a = 0; a < 4; a++)
#pragma unroll
            for (int b = 0; b < 3; b++)
#pragma unroll
                for (int c = 0; c < 4; c++) acc[a][b][c] = 0.0f;

#pragma unroll
        for (int kb = 0; kb < 64; kb += 16) {
            unsigned afr[4][4];
#pragma unroll
            for (int mf = 0; mf < 4; mf++) {
                const __half* ap = Xs + (mf*16 + l4)*FSTR + kb + 2*l2;
                afr[mf][0] = ldw(ap);
                afr[mf][1] = ldw(ap + 8*FSTR);
                afr[mf][2] = ldw(ap + 8);
                afr[mf][3] = ldw(ap + 8*FSTR + 8);
            }
#pragma unroll
            for (int nf = 0; nf < 3; nf++) {
                const __half* bp = Ws + (wn + nf*8 + l4)*FSTR + kb + 2*l2;
                unsigned b0 = ldw(bp);
                unsigned b1 = ldw(bp + 8);
#pragma unroll
                for (int mf = 0; mf < 4; mf++)
                    mma_f16(acc[mf][nf], afr[mf], b0, b1);
            }
        }
        // epilogue -> Qs fp32 (+bias)
#pragma unroll
        for (int nf = 0; nf < 3; nf++) {
            int col = wn + nf*8 + l2*2;
            float bb0 = bqkv[net*192 + col], bb1 = bqkv[net*192 + col + 1];
#pragma unroll
            for (int mf = 0; mf < 4; mf++) {
                int row = mf*16 + l4;
                float2 o01; o01.x = acc[mf][nf][0] + bb0; o01.y = acc[mf][nf][1] + bb1;
                float2 o23; o23.x = acc[mf][nf][2] + bb0; o23.y = acc[mf][nf][3] + bb1;
                *(float2*)&Qs[row*QSTR + col]       = o01;
                *(float2*)&Qs[(row + 8)*QSTR + col] = o23;
            }
        }
    }
    __syncthreads();   // Qs ready; Xs dead

    // ---- Phase B: attention, 8 tasks (2 batches x 4 heads), one per warp ----
    {
        const int g = warp >> 2, h = warp & 3;
        const int qi = lane;
        const float* base = Qs + (size_t)(g*32) * QSTR;

        float4 q4[4];
        {
            const float4* qp = (const float4*)&base[qi*QSTR + h*16];
#pragma unroll
            for (int i = 0; i < 4; i++) q4[i] = qp[i];
        }
        float sc[32];
#pragma unroll 4
        for (int ki = 0; ki < 32; ki++) {
            const float4* kp = (const float4*)&base[ki*QSTR + 64 + h*16];
            float4 k0 = kp[0], k1 = kp[1], k2 = kp[2], k3 = kp[3];
            float dot = q4[0].x*k0.x + q4[0].y*k0.y + q4[0].z*k0.z + q4[0].w*k0.w
                      + q4[1].x*k1.x + q4[1].y*k1.y + q4[1].z*k1.z + q4[1].w*k1.w
                      + q4[2].x*k2.x + q4[2].y*k2.y + q4[2].z*k2.z + q4[2].w*k2.w
                      + q4[3].x*k3.x + q4[3].y*k3.y + q4[3].z*k3.z + q4[3].w*k3.w;
            sc[ki] = dot * 0.25f;
        }
        float mx = sc[0];
#pragma unroll
        for (int ki = 1; ki < 32; ki++) mx = fmaxf(mx, sc[ki]);
        float sum = 0.0f;
#pragma unroll
        for (int ki = 0; ki < 32; ki++) { sc[ki] = __expf(sc[ki] - mx); sum += sc[ki]; }
        float rs = 1.0f / sum;

        float4 o0 = {0,0,0,0}, o1 = {0,0,0,0}, o2 = {0,0,0,0}, o3 = {0,0,0,0};
#pragma unroll 4
        for (int ki = 0; ki < 32; ki++) {
            float p = sc[ki];
            const float4* vp = (const float4*)&base[ki*QSTR + 128 + h*16];
            float4 v0 = vp[0], v1 = vp[1], v2 = vp[2], v3 = vp[3];
            o0.x += p*v0.x; o0.y += p*v0.y; o0.z += p*v0.z; o0.w += p*v0.w;
            o1.x += p*v1.x; o1.y += p*v1.y; o1.z += p*v1.z; o1.w += p*v1.w;
            o2.x += p*v2.x; o2.y += p*v2.y; o2.z += p*v2.z; o2.w += p*v2.w;
            o3.x += p*v3.x; o3.y += p*v3.y; o3.z += p*v3.z; o3.w += p*v3.w;
        }
        __syncthreads();   // all Qs reads done before Sa (overlay) is written
        __half2* op = (__half2*)(Sa + (size_t)(g*32 + qi) * FSTR + h*16);
        op[0] = __floats2half2_rn(o0.x*rs, o0.y*rs);
        op[1] = __floats2half2_rn(o0.z*rs, o0.w*rs);
        op[2] = __floats2half2_rn(o1.x*rs, o1.y*rs);
        op[3] = __floats2half2_rn(o1.z*rs, o1.w*rs);
        op[4] = __floats2half2_rn(o2.x*rs, o2.y*rs);
        op[5] = __floats2half2_rn(o2.z*rs, o2.w*rs);
        op[6] = __floats2half2_rn(o3.x*rs, o3.y*rs);
        op[7] = __floats2half2_rn(o3.z*rs, o3.w*rs);
    }
    __syncthreads();   // Sa ready

    // ---- Phase C: Wo mma. M=64 (mf=4), N=64 (8 warps x 8), K=64 ----
    {
        const int wn = warp * 8;
        float acc[4][4];
#pragma unroll
        for (int a = 0; a < 4; a++)
#pragma unroll
            for (int c = 0; c < 4; c++) acc[a][c] = 0.0f;

#pragma unroll
        for (int kb = 0; kb < 64; kb += 16) {
            unsigned afr[4][4];
#pragma unroll
            for (int mf = 0; mf < 4; mf++) {
                const __half* ap = Sa + (mf*16 + l4)*FSTR + kb + 2*l2;
                afr[mf][0] = ldw(ap);
                afr[mf][1] = ldw(ap + 8*FSTR);
                afr[mf][2] = ldw(ap + 8);
                afr[mf][3] = ldw(ap + 8*FSTR + 8);
            }
            const __half* bp = Wo + (wn + l4)*FSTR + kb + 2*l2;
            unsigned b0 = ldw(bp);
            unsigned b1 = ldw(bp + 8);
#pragma unroll
            for (int mf = 0; mf < 4; mf++)
                mma_f16(acc[mf], afr[mf], b0, b1);
        }
        // epilogue -> g_mha fp32
        int col = wn + l2*2;
        float bb0 = bo[net*64 + col], bb1 = bo[net*64 + col + 1];
#pragma unroll
        for (int mf = 0; mf < 4; mf++) {
            int row = mf*16 + l4;
            float2 o01; o01.x = acc[mf][0] + bb0; o01.y = acc[mf][1] + bb1;
            float2 o23; o23.x = acc[mf][2] + bb0; o23.y = acc[mf][3] + bb1;
            *(float2*)(g_mha + (size_t)(m0 + row) * 256 + net*64 + col) = o01;
            *(float2*)(g_mha + (size_t)(m0 + row + 8) * 256 + net*64 + col) = o23;
        }
    }
}

// ---------------- reparameterise + softmax pooling: per batch ----------------
__global__ __launch_bounds__(256) void reparam_pool_kernel(
    const float* __restrict__ eps_intra, const float* __restrict__ eps_inter,
    const float* __restrict__ att_w, const float* __restrict__ att_b)
{
    __shared__ float sinter[32][65];
    __shared__ float ssc[32];
    const int b = blockIdx.x, tid = threadIdx.x;

#pragma unroll
    for (int i = 0; i < 8; i++) {
        int idx = tid + i*256;
        int r = idx >> 6, c = idx & 63;
        const float* mh = g_mha + (size_t)(b*32 + r) * 256;
        float intra = mh[c] + softplusf(mh[64 + c] - 5.0f) * eps_intra[(size_t)(b*32 + r)*64 + c];
        g_emb_h[(size_t)(b*32 + r)*384 + 256 + c] = __float2half_rn(intra);
        float inter = mh[128 + c] + softplusf(mh[192 + c] - 5.0f) * eps_inter[(size_t)(b*32 + r)*64 + c];
        sinter[r][c] = inter;
    }
    __syncthreads();

    const int warp = tid >> 5, lane = tid & 31;
#pragma unroll
    for (int rr = 0; rr < 4; rr++) {
        int r = warp*4 + rr;
        float part = sinter[r][lane] * att_w[lane] + sinter[r][lane+32] * att_w[lane+32];
#pragma unroll
        for (int m = 16; m > 0; m >>= 1) part += __shfl_xor_sync(0xffffffffu, part, m);
        if (lane == 0) ssc[r] = part + att_b[0];
    }
    __syncthreads();

    if (warp == 0) {
        float l = ssc[lane];
        float mx = l;
#pragma unroll
        for (int m = 16; m > 0; m >>= 1) mx = fmaxf(mx, __shfl_xor_sync(0xffffffffu, mx, m));
        float e = __expf(l - mx);
        float sm = e;
#pragma unroll
        for (int m = 16; m > 0; m >>= 1) sm += __shfl_xor_sync(0xffffffffu, sm, m);
        ssc[lane] = e / sm;
    }
    __syncthreads();

    if (tid < 64) {
        float pooled = 0.0f;
#pragma unroll
        for (int r = 0; r < 32; r++) pooled += ssc[r] * sinter[r][tid];
        __half ph = __float2half_rn(pooled);
#pragma unroll
        for (int r = 0; r < 32; r++)
            g_emb_h[(size_t)(b*32 + r)*384 + 320 + tid] = ph;
    }
}

// ---------------- fused action/value head: 16 rows per block ----------------
__global__ __launch_bounds__(256) void head_kernel(
    const float* __restrict__ Wa, const float* __restrict__ ba,
    const float* __restrict__ Wv, const float* __restrict__ bv,
    float* __restrict__ out)
{
    __shared__ float4 sh4[16][65];
    __shared__ float4 swa4[16][65];
    __shared__ float4 swv4[64];
    const int tid = threadIdx.x;
    const int r0 = blockIdx.x * 16;

    for (int i = tid; i < 1024; i += 256) {
        int row = i >> 6, c4 = i & 63;
        sh4[row][c4]  = *(const float4*)(g_h2 + (size_t)(r0 + row) * 256 + c4*4);
        swa4[row][c4] = *(const float4*)(Wa + row * 256 + c4*4);
    }
    if (tid < 64) swv4[tid] = *(const float4*)(Wv + tid*4);
    __syncthreads();

    const int r = tid >> 4, o = tid & 15;
    float acc = 0.0f;
#pragma unroll 8
    for (int k = 0; k < 64; k++) {
        float4 h = sh4[r][k], w = swa4[o][k];
        acc += h.x*w.x + h.y*w.y + h.z*w.z + h.w*w.w;
    }
    acc += ba[o];

    float vacc = 0.0f;
#pragma unroll
    for (int k = 0; k < 4; k++) {
        float4 h = sh4[r][o*4 + k], w = swv4[o*4 + k];
        vacc += h.x*w.x + h.y*w.y + h.z*w.z + h.w*w.w;
    }

    float mx = acc;
#pragma unroll
    for (int m = 8; m > 0; m >>= 1) mx = fmaxf(mx, __shfl_xor_sync(0xffffffffu, mx, m));
    float ex = __expf(acc - mx);
    float sum = ex;
#pragma unroll
    for (int m = 8; m > 0; m >>= 1) sum += __shfl_xor_sync(0xffffffffu, sum, m);
    float lse = mx + logf(sum);

    out[(size_t)(r0 + r) * 16 + o] = acc - lse;

    float vs = vacc;
#pragma unroll
    for (int m = 8; m > 0; m >>= 1) vs += __shfl_xor_sync(0xffffffffu, vs, m);
    if (o == 0) out[(size_t)NROWS * 16 + r0 + r] = vs + bv[0];
}

// ---------------- launch ----------------
extern "C" void kernel_launch(void* const* d_in, const int* in_sizes, int n_in,
                              void* d_out, int out_size) {
    const float* obs       = (const float*)d_in[0];
    const float* eps_intra = (const float*)d_in[1];
    const float* eps_inter = (const float*)d_in[2];
    const float* W_local   = (const float*)d_in[3];
    const float* b_local   = (const float*)d_in[4];
    const float* W_inter   = (const float*)d_in[5];
    const float* b_inter   = (const float*)d_in[6];
    const float* W_intra   = (const float*)d_in[7];
    const float* b_intra   = (const float*)d_in[8];
    const float* Wqkv      = (const float*)d_in[9];
    const float* bqkv      = (const float*)d_in[10];
    const float* Wo        = (const float*)d_in[11];
    const float* bo        = (const float*)d_in[12];
    const float* att_w     = (const float*)d_in[13];
    const float* att_b     = (const float*)d_in[14];
    const float* W1        = (const float*)d_in[15];
    const float* b1        = (const float*)d_in[16];
    const float* W2        = (const float*)d_in[17];
    const float* b2        = (const float*)d_in[18];
    const float* Wa        = (const float*)d_in[19];
    const float* ba        = (const float*)d_in[20];
    const float* Wv        = (const float*)d_in[21];
    const float* bv        = (const float*)d_in[22];
    float* out = (float*)d_out;

    __half *p_obs_h, *p_Wemb_h, *p_W1_h, *p_W2_h, *p_emb_h, *p_h1_h;
    float  *p_bemb, *p_h2;
    cudaGetSymbolAddress((void**)&p_obs_h,  g_obs_h);
    cudaGetSymbolAddress((void**)&p_Wemb_h, g_Wemb_h);
    cudaGetSymbolAddress((void**)&p_W1_h,   g_W1_h);
    cudaGetSymbolAddress((void**)&p_W2_h,   g_W2_h);
    cudaGetSymbolAddress((void**)&p_emb_h,  g_emb_h);
    cudaGetSymbolAddress((void**)&p_h1_h,   g_h1_h);
    cudaGetSymbolAddress((void**)&p_bemb,   g_bemb);
    cudaGetSymbolAddress((void**)&p_h2,     g_h2);

    cudaFuncSetAttribute(qkv_attn_wo_kernel, cudaFuncAttributeMaxDynamicSharedMemorySize, FQ_SMEM);

    const int MB = NROWS / 128;   // 1024

    // 1) convert obs + pack weights
    conv_obs<<<NROWS*128/1024, 256>>>(obs);
    pack_w<<<384, 256>>>(W_local, b_local, W_inter, b_inter, W_intra, b_intra,
                         Wqkv, Wo, W1, W2);

    // 2) embeddings: [local | intra_e | inter_e] = tanh(obs @ Wemb^T + b) -> half
    gemm_h<1,1><<<dim3(MB, 3), 256, GEMMH_SMEM>>>(p_obs_h, 128, p_Wemb_h, p_bemb,
                                                  p_emb_h, 384, 128);

    // 3) fused qkv + attention + Wo (writes g_mha fp32)
    qkv_attn_wo_kernel<<<dim3(NROWS/64, 4), 256, FQ_SMEM>>>(bqkv, bo);

    // 4) reparameterise + softmax pooling (writes halves into emb)
    reparam_pool_kernel<<<BATCH, 256>>>(eps_intra, eps_inter, att_w, att_b);

    // 5) MLP: W1 (half out), W2 (float out for head)
    gemm_h<1,1><<<dim3(MB, 2), 256, GEMMH_SMEM>>>(p_emb_h, 384, p_W1_h, b1,
                                                  p_h1_h, 256, 384);
    gemm_h<1,0><<<dim3(MB, 2), 256, GEMMH_SMEM>>>(p_h1_h, 256, p_W2_h, b2,
                                                  p_h2, 256, 256);

    // 6) fused action/value head with log-softmax
    head_kernel<<<NROWS/16, 256>>>(Wa, ba, Wv, bv, out);
}

// round 12
// speedup vs baseline: 1.7199x; 1.1972x over previous
#include <cuda_runtime.h>
#include <cuda_fp16.h>
#include <math.h>

#define BATCH 4096
#define AGENTS 32
#define NROWS (BATCH*AGENTS)      // 131072
#define NACT 16

// ---------------- scratch (device globals; no allocation) ----------------
__device__ __half g_obs_h[(size_t)NROWS*128];
__device__ __half g_Wemb_h[384*128];
__device__ float  g_bemb[384];
__device__ __half g_Wqkv_h[768*64];            // [net][192][64]
__device__ __half g_Wo_h[4*64*64];             // [net][64][64]
__device__ __half g_W1_h[256*384];
__device__ __half g_W2_h[256*256];
__device__ __half g_emb_h[(size_t)NROWS*384];  // [local(256) | intra(64) | inter->pooled(64)]
__device__ float  g_mha[(size_t)NROWS*256];    // post-Wo fp32
__device__ __half g_h1_h[(size_t)NROWS*256];
__device__ float  g_h2[(size_t)NROWS*256];

__device__ __forceinline__ float softplusf(float x) {
    return x > 20.0f ? x : log1pf(__expf(x));
}
__device__ __forceinline__ unsigned ldw(const __half* p) {   // aligned half2 word
    return *(const unsigned*)p;
}
__device__ __forceinline__ unsigned pk(float a, float b) {
    __half2 t = __floats2half2_rn(a, b);
    return *(unsigned*)&t;
}
__device__ __forceinline__ void mma_f16(float* c, const unsigned* a, unsigned b0, unsigned b1) {
    asm volatile("mma.sync.aligned.m16n8k16.row.col.f32.f16.f16.f32 "
                 "{%0,%1,%2,%3},{%4,%5,%6,%7},{%8,%9},{%0,%1,%2,%3};"
                 : "+f"(c[0]), "+f"(c[1]), "+f"(c[2]), "+f"(c[3])
                 : "r"(a[0]), "r"(a[1]), "r"(a[2]), "r"(a[3]), "r"(b0), "r"(b1));
}
__device__ __forceinline__ void cp16(unsigned s, const void* g) {
    asm volatile("cp.async.ca.shared.global [%0], [%1], 16;\n" :: "r"(s), "l"(g));
}

// ---------------- obs -> fp16 ----------------
__global__ void conv_obs(const float* __restrict__ obs) {
    size_t i = ((size_t)blockIdx.x * 256 + threadIdx.x) * 4;
    float4 v = *(const float4*)(obs + i);
    __half2* o = (__half2*)(g_obs_h + i);
    o[0] = __floats2half2_rn(v.x, v.y);
    o[1] = __floats2half2_rn(v.z, v.w);
}

// ---------------- pack weights -> fp16 ----------------
__global__ void pack_w(const float* __restrict__ Wl, const float* __restrict__ bl,
                       const float* __restrict__ Wi, const float* __restrict__ bi,
                       const float* __restrict__ Wt, const float* __restrict__ bt,
                       const float* __restrict__ Wqkv, const float* __restrict__ Wo,
                       const float* __restrict__ W1, const float* __restrict__ W2) {
    int idx = blockIdx.x * blockDim.x + threadIdx.x;
    if (idx < 384*128) {
        int row = idx >> 7, col = idx & 127;
        float v;
        if (row < 256)      v = Wl[row*128 + col];
        else if (row < 320) v = Wt[(row-256)*128 + col];
        else                v = Wi[(row-320)*128 + col];
        g_Wemb_h[idx] = __float2half_rn(v);
    }
    if (idx < 768*64)   g_Wqkv_h[idx] = __float2half_rn(Wqkv[idx]);
    if (idx < 4*64*64)  g_Wo_h[idx]   = __float2half_rn(Wo[idx]);
    if (idx < 256*384)  g_W1_h[idx]   = __float2half_rn(W1[idx]);
    if (idx < 256*256)  g_W2_h[idx]   = __float2half_rn(W2[idx]);
    if (idx < 384)
        g_bemb[idx] = (idx < 256) ? bl[idx] : (idx < 320 ? bt[idx-256] : bi[idx-320]);
}

// ---------------- FP16 tensor-core GEMM (validated r11) ----------------
#define HSTR 40
template<int EPI, int OUTH>  // EPI: 1 = tanh; OUTH: 1 = half out, 0 = float out
__global__ __launch_bounds__(256, 2) void gemm_h(
    const __half* __restrict__ X, int ldx,
    const __half* __restrict__ W, const float* __restrict__ bias,
    void* __restrict__ Yv, int ldy, int K)
{
    extern __shared__ __half hsm[];
    __half* Xs = hsm;                        // [2][128*HSTR]
    __half* Ws = hsm + 2*128*HSTR;           // [2][128*HSTR]

    const int tid = threadIdx.x;
    const int m0 = blockIdx.x * 128, n0 = blockIdx.y * 128;
    const int warp = tid >> 5, lane = tid & 31;
    const int wm = (warp & 1) * 64, wn = (warp >> 1) * 32;
    const int l4 = lane >> 2, l2 = lane & 3;

    const int grow = tid & 127, gmat = tid >> 7;
    const __half* grsrc = gmat ? (W + (size_t)(n0 + grow) * K)
                               : (X + (size_t)(m0 + grow) * ldx);
    unsigned gdst0 = (unsigned)__cvta_generic_to_shared(
        (gmat ? Ws : Xs) + grow*HSTR);

    float acc[4][4][4];
#pragma unroll
    for (int a = 0; a < 4; a++)
#pragma unroll
        for (int b = 0; b < 4; b++)
#pragma unroll
            for (int c = 0; c < 4; c++) acc[a][b][c] = 0.0f;

    const int nstage = K >> 5;

#pragma unroll
    for (int q = 0; q < 4; q++)
        cp16(gdst0 + q*16, grsrc + q*8);
    asm volatile("cp.async.commit_group;\n");

    for (int s = 0; s < nstage; s++) {
        asm volatile("cp.async.wait_group 0;\n");
        __syncthreads();

        if (s + 1 < nstage) {
            int k0 = (s + 1) << 5;
            unsigned gd = gdst0 + ((s+1)&1) * 128*HSTR*2;
#pragma unroll
            for (int q = 0; q < 4; q++)
                cp16(gd + q*16, grsrc + k0 + q*8);
            asm volatile("cp.async.commit_group;\n");
        }

        const __half* Xb = Xs + (s & 1) * 128*HSTR;
        const __half* Wb = Ws + (s & 1) * 128*HSTR;
#pragma unroll
        for (int kb = 0; kb < 32; kb += 16) {
            unsigned afr[4][4];
#pragma unroll
            for (int mf = 0; mf < 4; mf++) {
                const __half* ap = Xb + (wm + mf*16 + l4)*HSTR + kb + 2*l2;
                afr[mf][0] = ldw(ap);
                afr[mf][1] = ldw(ap + 8*HSTR);
                afr[mf][2] = ldw(ap + 8);
                afr[mf][3] = ldw(ap + 8*HSTR + 8);
            }
#pragma unroll
            for (int nf = 0; nf < 4; nf++) {
                const __half* bp = Wb + (wn + nf*8 + l4)*HSTR + kb + 2*l2;
                unsigned b0 = ldw(bp);
                unsigned b1 = ldw(bp + 8);
#pragma unroll
                for (int mf = 0; mf < 4; mf++)
                    mma_f16(acc[mf][nf], afr[mf], b0, b1);
            }
        }
    }

#pragma unroll
    for (int nf = 0; nf < 4; nf++) {
        int col = n0 + wn + nf*8 + l2*2;
        float bb0 = bias[col], bb1 = bias[col + 1];
#pragma unroll
        for (int mf = 0; mf < 4; mf++) {
            int row = m0 + wm + mf*16 + l4;
            float v0 = acc[mf][nf][0] + bb0, v1 = acc[mf][nf][1] + bb1;
            float v2 = acc[mf][nf][2] + bb0, v3 = acc[mf][nf][3] + bb1;
            if (EPI == 1) { v0 = tanhf(v0); v1 = tanhf(v1); v2 = tanhf(v2); v3 = tanhf(v3); }
            if (OUTH) {
                __half* Y = (__half*)Yv;
                *(__half2*)(Y + (size_t)row * ldy + col)       = __floats2half2_rn(v0, v1);
                *(__half2*)(Y + (size_t)(row + 8) * ldy + col) = __floats2half2_rn(v2, v3);
            } else {
                float* Y = (float*)Yv;
                float2 o01; o01.x = v0; o01.y = v1;
                float2 o23; o23.x = v2; o23.y = v3;
                *(float2*)(Y + (size_t)row * ldy + col) = o01;
                *(float2*)(Y + (size_t)(row + 8) * ldy + col) = o23;
            }
        }
    }
}
#define GEMMH_SMEM (4*128*HSTR*2)   // 40960 bytes

// ---------------- fused qkv + MMA-attention + Wo (all tensor-core) ----------------
// One block per (64 rows = 2 batches, net).
#define QKSTR 136                    // q|k fp16 rows (halves)
#define VTSTR 72                     // Vt rows (halves)
#define FSTR  72                     // Xs / Sa / Ws / Wo rows (halves)
#define SM_QK 0
#define SM_VT (64*QKSTR*2)                 // 17408
#define SM_SA (SM_VT + 64*VTSTR*2)         // 26624
#define SM_XS (SM_SA + 64*FSTR*2)          // 35840
#define SM_WS (SM_XS + 64*FSTR*2)          // 45056
#define SM_WO (SM_WS + 192*FSTR*2)         // 72704
#define FQ_SMEM (SM_WO + 64*FSTR*2)        // 81920

__global__ __launch_bounds__(256, 2) void qkv_attn_wo_kernel(
    const float* __restrict__ bqkv, const float* __restrict__ bo)
{
    extern __shared__ char sm[];
    __half* QKs = (__half*)(sm + SM_QK);    // [64][136]: q cols 0..63, k cols 64..127
    __half* Vt  = (__half*)(sm + SM_VT);    // [64 vcols][72 keys]
    __half* Sa  = (__half*)(sm + SM_SA);    // [64][72] attn out
    __half* Xs  = (__half*)(sm + SM_XS);    // [64][72] input slice
    __half* Ws  = (__half*)(sm + SM_WS);    // [192][72]
    __half* Wo  = (__half*)(sm + SM_WO);    // [64][72]

    const int tid = threadIdx.x, warp = tid >> 5, lane = tid & 31;
    const int net = blockIdx.y;
    const int m0 = blockIdx.x * 64;
    const int l4 = lane >> 2, l2 = lane & 3;

    // ---- prologue loads: X slice (64x64h), Wqkv net (192x64h), Wo net (64x64h) ----
    const int xoff = 256 + ((net >= 2) ? 64 : 0);
    {
        int xrow = tid >> 2, seg = tid & 3;
        const __half* src = g_emb_h + (size_t)(m0 + xrow) * 384 + xoff + seg*16;
        unsigned dst = (unsigned)__cvta_generic_to_shared(Xs + xrow*FSTR + seg*16);
        cp16(dst, src); cp16(dst + 16, src + 8);
        if (tid < 192) {
            const __half* ws = g_Wqkv_h + ((size_t)net*192 + tid) * 64;
            unsigned wd = (unsigned)__cvta_generic_to_shared(Ws + tid*FSTR);
#pragma unroll
            for (int q = 0; q < 8; q++) cp16(wd + q*16, ws + q*8);
        } else {
            int row = tid - 192;
            const __half* os = g_Wo_h + (size_t)net*4096 + row*64;
            unsigned od = (unsigned)__cvta_generic_to_shared(Wo + row*FSTR);
#pragma unroll
            for (int q = 0; q < 8; q++) cp16(od + q*16, os + q*8);
        }
    }
    asm volatile("cp.async.commit_group;\n");
    asm volatile("cp.async.wait_group 0;\n");
    __syncthreads();

    // ---- Phase A: qkv mma. M=64 (mf=4), N=192 (8 warps x 24), K=64 ----
    {
        const int wn = warp * 24;
        float acc[4][3][4];
#pragma unroll
        for (int a = 0; a < 4; a++)
#pragma unroll
            for (int b = 0; b < 3; b++)
#pragma unroll
                for (int c = 0; c < 4; c++) acc[a][b][c] = 0.0f;

#pragma unroll
        for (int kb = 0; kb < 64; kb += 16) {
            unsigned afr[4][4];
#pragma unroll
            for (int mf = 0; mf < 4; mf++) {
                const __half* ap = Xs + (mf*16 + l4)*FSTR + kb + 2*l2;
                afr[mf][0] = ldw(ap);
                afr[mf][1] = ldw(ap + 8*FSTR);
                afr[mf][2] = ldw(ap + 8);
                afr[mf][3] = ldw(ap + 8*FSTR + 8);
            }
#pragma unroll
            for (int nf = 0; nf < 3; nf++) {
                const __half* bp = Ws + (wn + nf*8 + l4)*FSTR + kb + 2*l2;
                unsigned b0 = ldw(bp);
                unsigned b1 = ldw(bp + 8);
#pragma unroll
                for (int mf = 0; mf < 4; mf++)
                    mma_f16(acc[mf][nf], afr[mf], b0, b1);
            }
        }
        // epilogue: q,k -> QKs fp16; v -> Vt (transposed) fp16
#pragma unroll
        for (int nf = 0; nf < 3; nf++) {
            int col = wn + nf*8 + l2*2;
            float bb0 = bqkv[net*192 + col], bb1 = bqkv[net*192 + col + 1];
#pragma unroll
            for (int mf = 0; mf < 4; mf++) {
                int row = mf*16 + l4;
                float v0 = acc[mf][nf][0] + bb0, v1 = acc[mf][nf][1] + bb1;
                float v2 = acc[mf][nf][2] + bb0, v3 = acc[mf][nf][3] + bb1;
                if (col < 128) {
                    *(__half2*)(QKs + row*QKSTR + col)       = __floats2half2_rn(v0, v1);
                    *(__half2*)(QKs + (row + 8)*QKSTR + col) = __floats2half2_rn(v2, v3);
                } else {
                    int vc = col - 128;
                    Vt[vc*VTSTR + row]           = __float2half_rn(v0);
                    Vt[(vc + 1)*VTSTR + row]     = __float2half_rn(v1);
                    Vt[vc*VTSTR + row + 8]       = __float2half_rn(v2);
                    Vt[(vc + 1)*VTSTR + row + 8] = __float2half_rn(v3);
                }
            }
        }
    }
    __syncthreads();   // QKs + Vt ready

    // ---- Phase B: MMA attention. 8 tasks (2 batches x 4 heads), one per warp ----
    {
        const int g = warp >> 2, h = warp & 3;

        // S = Q.K^T : M=32 (mf2), N=32 (nf4), K=16
        unsigned qa[2][4];
#pragma unroll
        for (int mf = 0; mf < 2; mf++) {
            const __half* ap = QKs + (g*32 + mf*16 + l4)*QKSTR + h*16 + 2*l2;
            qa[mf][0] = ldw(ap);
            qa[mf][1] = ldw(ap + 8*QKSTR);
            qa[mf][2] = ldw(ap + 8);
            qa[mf][3] = ldw(ap + 8*QKSTR + 8);
        }
        float sacc[2][4][4];
#pragma unroll
        for (int a = 0; a < 2; a++)
#pragma unroll
            for (int b = 0; b < 4; b++)
#pragma unroll
                for (int c = 0; c < 4; c++) sacc[a][b][c] = 0.0f;
#pragma unroll
        for (int nf = 0; nf < 4; nf++) {
            const __half* bp = QKs + (g*32 + nf*8 + l4)*QKSTR + 64 + h*16 + 2*l2;
            unsigned b0 = ldw(bp), b1 = ldw(bp + 8);
#pragma unroll
            for (int mf = 0; mf < 2; mf++)
                mma_f16(sacc[mf][nf], qa[mf], b0, b1);
        }

        // softmax (scale 1/4) in registers; C-frag -> A-frag pack
        float rs[2][2];
        unsigned pa[2][2][4];
#pragma unroll
        for (int mf = 0; mf < 2; mf++) {
            float m0x = -1e30f, m1x = -1e30f;
#pragma unroll
            for (int nf = 0; nf < 4; nf++) {
                m0x = fmaxf(m0x, fmaxf(sacc[mf][nf][0], sacc[mf][nf][1]));
                m1x = fmaxf(m1x, fmaxf(sacc[mf][nf][2], sacc[mf][nf][3]));
            }
            m0x = fmaxf(m0x, __shfl_xor_sync(0xffffffffu, m0x, 1));
            m0x = fmaxf(m0x, __shfl_xor_sync(0xffffffffu, m0x, 2));
            m1x = fmaxf(m1x, __shfl_xor_sync(0xffffffffu, m1x, 1));
            m1x = fmaxf(m1x, __shfl_xor_sync(0xffffffffu, m1x, 2));

            float p[4][4];
            float s0 = 0.0f, s1 = 0.0f;
#pragma unroll
            for (int nf = 0; nf < 4; nf++) {
                p[nf][0] = __expf(0.25f * (sacc[mf][nf][0] - m0x));
                p[nf][1] = __expf(0.25f * (sacc[mf][nf][1] - m0x));
                p[nf][2] = __expf(0.25f * (sacc[mf][nf][2] - m1x));
                p[nf][3] = __expf(0.25f * (sacc[mf][nf][3] - m1x));
                s0 += p[nf][0] + p[nf][1];
                s1 += p[nf][2] + p[nf][3];
            }
            s0 += __shfl_xor_sync(0xffffffffu, s0, 1);
            s0 += __shfl_xor_sync(0xffffffffu, s0, 2);
            s1 += __shfl_xor_sync(0xffffffffu, s1, 1);
            s1 += __shfl_xor_sync(0xffffffffu, s1, 2);
            rs[mf][0] = 1.0f / s0;
            rs[mf][1] = 1.0f / s1;

            // kstep0 <- nf0,nf1 ; kstep1 <- nf2,nf3
            pa[mf][0][0] = pk(p[0][0], p[0][1]);
            pa[mf][0][1] = pk(p[0][2], p[0][3]);
            pa[mf][0][2] = pk(p[1][0], p[1][1]);
            pa[mf][0][3] = pk(p[1][2], p[1][3]);
            pa[mf][1][0] = pk(p[2][0], p[2][1]);
            pa[mf][1][1] = pk(p[2][2], p[2][3]);
            pa[mf][1][2] = pk(p[3][0], p[3][1]);
            pa[mf][1][3] = pk(p[3][2], p[3][3]);
        }

        // O = P.V : M=32 (mf2), N=16 (nf2), K=32 (ks2); B from Vt (transposed V)
        float oacc[2][2][4];
#pragma unroll
        for (int a = 0; a < 2; a++)
#pragma unroll
            for (int b = 0; b < 2; b++)
#pragma unroll
                for (int c = 0; c < 4; c++) oacc[a][b][c] = 0.0f;
#pragma unroll
        for (int ks = 0; ks < 2; ks++)
#pragma unroll
            for (int nf = 0; nf < 2; nf++) {
                const __half* bp = Vt + (h*16 + nf*8 + l4)*VTSTR + g*32 + ks*16 + 2*l2;
                unsigned b0 = ldw(bp), b1 = ldw(bp + 8);
#pragma unroll
                for (int mf = 0; mf < 2; mf++)
                    mma_f16(oacc[mf][nf], pa[mf][ks], b0, b1);
            }

        // normalize + store Sa fp16
#pragma unroll
        for (int nf = 0; nf < 2; nf++) {
            int col = h*16 + nf*8 + 2*l2;
#pragma unroll
            for (int mf = 0; mf < 2; mf++) {
                int row = g*32 + mf*16 + l4;
                *(__half2*)(Sa + row*FSTR + col) =
                    __floats2half2_rn(oacc[mf][nf][0]*rs[mf][0], oacc[mf][nf][1]*rs[mf][0]);
                *(__half2*)(Sa + (row + 8)*FSTR + col) =
                    __floats2half2_rn(oacc[mf][nf][2]*rs[mf][1], oacc[mf][nf][3]*rs[mf][1]);
            }
        }
    }
    __syncthreads();   // Sa ready

    // ---- Phase C: Wo mma. M=64 (mf=4), N=64 (8 warps x 8), K=64 ----
    {
        const int wn = warp * 8;
        float acc[4][4];
#pragma unroll
        for (int a = 0; a < 4; a++)
#pragma unroll
            for (int c = 0; c < 4; c++) acc[a][c] = 0.0f;

#pragma unroll
        for (int kb = 0; kb < 64; kb += 16) {
            unsigned afr[4][4];
#pragma unroll
            for (int mf = 0; mf < 4; mf++) {
                const __half* ap = Sa + (mf*16 + l4)*FSTR + kb + 2*l2;
                afr[mf][0] = ldw(ap);
                afr[mf][1] = ldw(ap + 8*FSTR);
                afr[mf][2] = ldw(ap + 8);
                afr[mf][3] = ldw(ap + 8*FSTR + 8);
            }
            const __half* bp = Wo + (wn + l4)*FSTR + kb + 2*l2;
            unsigned b0 = ldw(bp);
            unsigned b1 = ldw(bp + 8);
#pragma unroll
            for (int mf = 0; mf < 4; mf++)
                mma_f16(acc[mf], afr[mf], b0, b1);
        }
        int col = wn + l2*2;
        float bb0 = bo[net*64 + col], bb1 = bo[net*64 + col + 1];
#pragma unroll
        for (int mf = 0; mf < 4; mf++) {
            int row = mf*16 + l4;
            float2 o01; o01.x = acc[mf][0] + bb0; o01.y = acc[mf][1] + bb1;
            float2 o23; o23.x = acc[mf][2] + bb0; o23.y = acc[mf][3] + bb1;
            *(float2*)(g_mha + (size_t)(m0 + row) * 256 + net*64 + col) = o01;
            *(float2*)(g_mha + (size_t)(m0 + row + 8) * 256 + net*64 + col) = o23;
        }
    }
}

// ---------------- reparameterise + softmax pooling: per batch ----------------
__global__ __launch_bounds__(256) void reparam_pool_kernel(
    const float* __restrict__ eps_intra, const float* __restrict__ eps_inter,
    const float* __restrict__ att_w, const float* __restrict__ att_b)
{
    __shared__ float sinter[32][65];
    __shared__ float ssc[32];
    const int b = blockIdx.x, tid = threadIdx.x;

#pragma unroll
    for (int i = 0; i < 8; i++) {
        int idx = tid + i*256;
        int r = idx >> 6, c = idx & 63;
        const float* mh = g_mha + (size_t)(b*32 + r) * 256;
        float intra = mh[c] + softplusf(mh[64 + c] - 5.0f) * eps_intra[(size_t)(b*32 + r)*64 + c];
        g_emb_h[(size_t)(b*32 + r)*384 + 256 + c] = __float2half_rn(intra);
        float inter = mh[128 + c] + softplusf(mh[192 + c] - 5.0f) * eps_inter[(size_t)(b*32 + r)*64 + c];
        sinter[r][c] = inter;
    }
    __syncthreads();

    const int warp = tid >> 5, lane = tid & 31;
#pragma unroll
    for (int rr = 0; rr < 4; rr++) {
        int r = warp*4 + rr;
        float part = sinter[r][lane] * att_w[lane] + sinter[r][lane+32] * att_w[lane+32];
#pragma unroll
        for (int m = 16; m > 0; m >>= 1) part += __shfl_xor_sync(0xffffffffu, part, m);
        if (lane == 0) ssc[r] = part + att_b[0];
    }
    __syncthreads();

    if (warp == 0) {
        float l = ssc[lane];
        float mx = l;
#pragma unroll
        for (int m = 16; m > 0; m >>= 1) mx = fmaxf(mx, __shfl_xor_sync(0xffffffffu, mx, m));
        float e = __expf(l - mx);
        float sm = e;
#pragma unroll
        for (int m = 16; m > 0; m >>= 1) sm += __shfl_xor_sync(0xffffffffu, sm, m);
        ssc[lane] = e / sm;
    }
    __syncthreads();

    if (tid < 64) {
        float pooled = 0.0f;
#pragma unroll
        for (int r = 0; r < 32; r++) pooled += ssc[r] * sinter[r][tid];
        __half ph = __float2half_rn(pooled);
#pragma unroll
        for (int r = 0; r < 32; r++)
            g_emb_h[(size_t)(b*32 + r)*384 + 320 + tid] = ph;
    }
}

// ---------------- fused action/value head: 16 rows per block ----------------
__global__ __launch_bounds__(256) void head_kernel(
    const float* __restrict__ Wa, const float* __restrict__ ba,
    const float* __restrict__ Wv, const float* __restrict__ bv,
    float* __restrict__ out)
{
    __shared__ float4 sh4[16][65];
    __shared__ float4 swa4[16][65];
    __shared__ float4 swv4[64];
    const int tid = threadIdx.x;
    const int r0 = blockIdx.x * 16;

    for (int i = tid; i < 1024; i += 256) {
        int row = i >> 6, c4 = i & 63;
        sh4[row][c4]  = *(const float4*)(g_h2 + (size_t)(r0 + row) * 256 + c4*4);
        swa4[row][c4] = *(const float4*)(Wa + row * 256 + c4*4);
    }
    if (tid < 64) swv4[tid] = *(const float4*)(Wv + tid*4);
    __syncthreads();

    const int r = tid >> 4, o = tid & 15;
    float acc = 0.0f;
#pragma unroll 8
    for (int k = 0; k < 64; k++) {
        float4 h = sh4[r][k], w = swa4[o][k];
        acc += h.x*w.x + h.y*w.y + h.z*w.z + h.w*w.w;
    }
    acc += ba[o];

    float vacc = 0.0f;
#pragma unroll
    for (int k = 0; k < 4; k++) {
        float4 h = sh4[r][o*4 + k], w = swv4[o*4 + k];
        vacc += h.x*w.x + h.y*w.y + h.z*w.z + h.w*w.w;
    }

    float mx = acc;
#pragma unroll
    for (int m = 8; m > 0; m >>= 1) mx = fmaxf(mx, __shfl_xor_sync(0xffffffffu, mx, m));
    float ex = __expf(acc - mx);
    float sum = ex;
#pragma unroll
    for (int m = 8; m > 0; m >>= 1) sum += __shfl_xor_sync(0xffffffffu, sum, m);
    float lse = mx + logf(sum);

    out[(size_t)(r0 + r) * 16 + o] = acc - lse;

    float vs = vacc;
#pragma unroll
    for (int m = 8; m > 0; m >>= 1) vs += __shfl_xor_sync(0xffffffffu, vs, m);
    if (o == 0) out[(size_t)NROWS * 16 + r0 + r] = vs + bv[0];
}

// ---------------- launch ----------------
extern "C" void kernel_launch(void* const* d_in, const int* in_sizes, int n_in,
                              void* d_out, int out_size) {
    const float* obs       = (const float*)d_in[0];
    const float* eps_intra = (const float*)d_in[1];
    const float* eps_inter = (const float*)d_in[2];
    const float* W_local   = (const float*)d_in[3];
    const float* b_local   = (const float*)d_in[4];
    const float* W_inter   = (const float*)d_in[5];
    const float* b_inter   = (const float*)d_in[6];
    const float* W_intra   = (const float*)d_in[7];
    const float* b_intra   = (const float*)d_in[8];
    const float* Wqkv      = (const float*)d_in[9];
    const float* bqkv      = (const float*)d_in[10];
    const float* Wo        = (const float*)d_in[11];
    const float* bo        = (const float*)d_in[12];
    const float* att_w     = (const float*)d_in[13];
    const float* att_b     = (const float*)d_in[14];
    const float* W1        = (const float*)d_in[15];
    const float* b1        = (const float*)d_in[16];
    const float* W2        = (const float*)d_in[17];
    const float* b2        = (const float*)d_in[18];
    const float* Wa        = (const float*)d_in[19];
    const float* ba        = (const float*)d_in[20];
    const float* Wv        = (const float*)d_in[21];
    const float* bv        = (const float*)d_in[22];
    float* out = (float*)d_out;

    __half *p_obs_h, *p_Wemb_h, *p_W1_h, *p_W2_h, *p_emb_h, *p_h1_h;
    float  *p_bemb, *p_h2;
    cudaGetSymbolAddress((void**)&p_obs_h,  g_obs_h);
    cudaGetSymbolAddress((void**)&p_Wemb_h, g_Wemb_h);
    cudaGetSymbolAddress((void**)&p_W1_h,   g_W1_h);
    cudaGetSymbolAddress((void**)&p_W2_h,   g_W2_h);
    cudaGetSymbolAddress((void**)&p_emb_h,  g_emb_h);
    cudaGetSymbolAddress((void**)&p_h1_h,   g_h1_h);
    cudaGetSymbolAddress((void**)&p_bemb,   g_bemb);
    cudaGetSymbolAddress((void**)&p_h2,     g_h2);

    cudaFuncSetAttribute(qkv_attn_wo_kernel, cudaFuncAttributeMaxDynamicSharedMemorySize, FQ_SMEM);

    const int MB = NROWS / 128;   // 1024

    // 1) convert obs + pack weights
    conv_obs<<<NROWS*128/1024, 256>>>(obs);
    pack_w<<<384, 256>>>(W_local, b_local, W_inter, b_inter, W_intra, b_intra,
                         Wqkv, Wo, W1, W2);

    // 2) embeddings: [local | intra_e | inter_e] = tanh(obs @ Wemb^T + b) -> half
    gemm_h<1,1><<<dim3(MB, 3), 256, GEMMH_SMEM>>>(p_obs_h, 128, p_Wemb_h, p_bemb,
                                                  p_emb_h, 384, 128);

    // 3) fused qkv + MMA attention + Wo (writes g_mha fp32)
    qkv_attn_wo_kernel<<<dim3(NROWS/64, 4), 256, FQ_SMEM>>>(bqkv, bo);

    // 4) reparameterise + softmax pooling (writes halves into emb)
    reparam_pool_kernel<<<BATCH, 256>>>(eps_intra, eps_inter, att_w, att_b);

    // 5) MLP: W1 (half out), W2 (float out for head)
    gemm_h<1,1><<<dim3(MB, 2), 256, GEMMH_SMEM>>>(p_emb_h, 384, p_W1_h, b1,
                                                  p_h1_h, 256, 384);
    gemm_h<1,0><<<dim3(MB, 2), 256, GEMMH_SMEM>>>(p_h1_h, 256, p_W2_h, b2,
                                                  p_h2, 256, 256);

    // 6) fused action/value head with log-softmax
    head_kernel<<<NROWS/16, 256>>>(Wa, ba, Wv, bv, out);
}

// round 13
// speedup vs baseline: 1.9934x; 1.1590x over previous
#include <cuda_runtime.h>
#include <cuda_fp16.h>
#include <math.h>

#define BATCH 4096
#define AGENTS 32
#define NROWS (BATCH*AGENTS)      // 131072
#define NACT 16

// ---------------- scratch (device globals; no allocation) ----------------
__device__ __half g_obs_h[(size_t)NROWS*128];
__device__ __half g_Wemb_h[384*128];
__device__ float  g_bemb[384];
__device__ __half g_Wqkv_h[768*64];            // [net][192][64]
__device__ __half g_Wo_h[4*64*64];             // [net][64][64]
__device__ __half g_W1_h[256*384];
__device__ __half g_W2_h[256*256];
__device__ __half g_WaV_h[24*256];             // rows 0..15 Wa, 16 Wv, 17..23 zero
__device__ __half g_emb_h[(size_t)NROWS*384];  // [local(256) | intra(64) | inter->pooled(64)]
__device__ __half g_mha_h[(size_t)NROWS*256];  // post-Wo fp16
__device__ __half g_h1_h[(size_t)NROWS*256];
__device__ __half g_h2_h[(size_t)NROWS*256];

__device__ __forceinline__ float softplusf(float x) {
    return x > 20.0f ? x : log1pf(__expf(x));
}
__device__ __forceinline__ unsigned ldw(const __half* p) {   // aligned half2 word
    return *(const unsigned*)p;
}
__device__ __forceinline__ unsigned pk(float a, float b) {
    __half2 t = __floats2half2_rn(a, b);
    return *(unsigned*)&t;
}
__device__ __forceinline__ void mma_f16(float* c, const unsigned* a, unsigned b0, unsigned b1) {
    asm volatile("mma.sync.aligned.m16n8k16.row.col.f32.f16.f16.f32 "
                 "{%0,%1,%2,%3},{%4,%5,%6,%7},{%8,%9},{%0,%1,%2,%3};"
                 : "+f"(c[0]), "+f"(c[1]), "+f"(c[2]), "+f"(c[3])
                 : "r"(a[0]), "r"(a[1]), "r"(a[2]), "r"(a[3]), "r"(b0), "r"(b1));
}
__device__ __forceinline__ void cp16(unsigned s, const void* g) {
    asm volatile("cp.async.ca.shared.global [%0], [%1], 16;\n" :: "r"(s), "l"(g));
}

// ---------------- obs -> fp16 ----------------
__global__ void conv_obs(const float* __restrict__ obs) {
    size_t i = ((size_t)blockIdx.x * 256 + threadIdx.x) * 4;
    float4 v = *(const float4*)(obs + i);
    __half2* o = (__half2*)(g_obs_h + i);
    o[0] = __floats2half2_rn(v.x, v.y);
    o[1] = __floats2half2_rn(v.z, v.w);
}

// ---------------- pack weights -> fp16 ----------------
__global__ void pack_w(const float* __restrict__ Wl, const float* __restrict__ bl,
                       const float* __restrict__ Wi, const float* __restrict__ bi,
                       const float* __restrict__ Wt, const float* __restrict__ bt,
                       const float* __restrict__ Wqkv, const float* __restrict__ Wo,
                       const float* __restrict__ W1, const float* __restrict__ W2,
                       const float* __restrict__ Wa, const float* __restrict__ Wv) {
    int idx = blockIdx.x * blockDim.x + threadIdx.x;
    if (idx < 384*128) {
        int row = idx >> 7, col = idx & 127;
        float v;
        if (row < 256)      v = Wl[row*128 + col];
        else if (row < 320) v = Wt[(row-256)*128 + col];
        else                v = Wi[(row-320)*128 + col];
        g_Wemb_h[idx] = __float2half_rn(v);
    }
    if (idx < 768*64)   g_Wqkv_h[idx] = __float2half_rn(Wqkv[idx]);
    if (idx < 4*64*64)  g_Wo_h[idx]   = __float2half_rn(Wo[idx]);
    if (idx < 256*384)  g_W1_h[idx]   = __float2half_rn(W1[idx]);
    if (idx < 256*256)  g_W2_h[idx]   = __float2half_rn(W2[idx]);
    if (idx < 24*256) {
        int row = idx >> 8, col = idx & 255;
        float v = (row < 16) ? Wa[row*256 + col] : (row == 16 ? Wv[col] : 0.0f);
        g_WaV_h[idx] = __float2half_rn(v);
    }
    if (idx < 384)
        g_bemb[idx] = (idx < 256) ? bl[idx] : (idx < 320 ? bt[idx-256] : bi[idx-320]);
}

// ---------------- FP16 tensor-core GEMM (validated r11/r12) ----------------
#define HSTR 40
template<int EPI, int OUTH>  // EPI: 1 = tanh; OUTH: 1 = half out, 0 = float out
__global__ __launch_bounds__(256, 2) void gemm_h(
    const __half* __restrict__ X, int ldx,
    const __half* __restrict__ W, const float* __restrict__ bias,
    void* __restrict__ Yv, int ldy, int K)
{
    extern __shared__ __half hsm[];
    __half* Xs = hsm;                        // [2][128*HSTR]
    __half* Ws = hsm + 2*128*HSTR;           // [2][128*HSTR]

    const int tid = threadIdx.x;
    const int m0 = blockIdx.x * 128, n0 = blockIdx.y * 128;
    const int warp = tid >> 5, lane = tid & 31;
    const int wm = (warp & 1) * 64, wn = (warp >> 1) * 32;
    const int l4 = lane >> 2, l2 = lane & 3;

    const int grow = tid & 127, gmat = tid >> 7;
    const __half* grsrc = gmat ? (W + (size_t)(n0 + grow) * K)
                               : (X + (size_t)(m0 + grow) * ldx);
    unsigned gdst0 = (unsigned)__cvta_generic_to_shared(
        (gmat ? Ws : Xs) + grow*HSTR);

    float acc[4][4][4];
#pragma unroll
    for (int a = 0; a < 4; a++)
#pragma unroll
        for (int b = 0; b < 4; b++)
#pragma unroll
            for (int c = 0; c < 4; c++) acc[a][b][c] = 0.0f;

    const int nstage = K >> 5;

#pragma unroll
    for (int q = 0; q < 4; q++)
        cp16(gdst0 + q*16, grsrc + q*8);
    asm volatile("cp.async.commit_group;\n");

    for (int s = 0; s < nstage; s++) {
        asm volatile("cp.async.wait_group 0;\n");
        __syncthreads();

        if (s + 1 < nstage) {
            int k0 = (s + 1) << 5;
            unsigned gd = gdst0 + ((s+1)&1) * 128*HSTR*2;
#pragma unroll
            for (int q = 0; q < 4; q++)
                cp16(gd + q*16, grsrc + k0 + q*8);
            asm volatile("cp.async.commit_group;\n");
        }

        const __half* Xb = Xs + (s & 1) * 128*HSTR;
        const __half* Wb = Ws + (s & 1) * 128*HSTR;
#pragma unroll
        for (int kb = 0; kb < 32; kb += 16) {
            unsigned afr[4][4];
#pragma unroll
            for (int mf = 0; mf < 4; mf++) {
                const __half* ap = Xb + (wm + mf*16 + l4)*HSTR + kb + 2*l2;
                afr[mf][0] = ldw(ap);
                afr[mf][1] = ldw(ap + 8*HSTR);
                afr[mf][2] = ldw(ap + 8);
                afr[mf][3] = ldw(ap + 8*HSTR + 8);
            }
#pragma unroll
            for (int nf = 0; nf < 4; nf++) {
                const __half* bp = Wb + (wn + nf*8 + l4)*HSTR + kb + 2*l2;
                unsigned b0 = ldw(bp);
                unsigned b1 = ldw(bp + 8);
#pragma unroll
                for (int mf = 0; mf < 4; mf++)
                    mma_f16(acc[mf][nf], afr[mf], b0, b1);
            }
        }
    }

#pragma unroll
    for (int nf = 0; nf < 4; nf++) {
        int col = n0 + wn + nf*8 + l2*2;
        float bb0 = bias[col], bb1 = bias[col + 1];
#pragma unroll
        for (int mf = 0; mf < 4; mf++) {
            int row = m0 + wm + mf*16 + l4;
            float v0 = acc[mf][nf][0] + bb0, v1 = acc[mf][nf][1] + bb1;
            float v2 = acc[mf][nf][2] + bb0, v3 = acc[mf][nf][3] + bb1;
            if (EPI == 1) { v0 = tanhf(v0); v1 = tanhf(v1); v2 = tanhf(v2); v3 = tanhf(v3); }
            if (OUTH) {
                __half* Y = (__half*)Yv;
                *(__half2*)(Y + (size_t)row * ldy + col)       = __floats2half2_rn(v0, v1);
                *(__half2*)(Y + (size_t)(row + 8) * ldy + col) = __floats2half2_rn(v2, v3);
            } else {
                float* Y = (float*)Yv;
                float2 o01; o01.x = v0; o01.y = v1;
                float2 o23; o23.x = v2; o23.y = v3;
                *(float2*)(Y + (size_t)row * ldy + col) = o01;
                *(float2*)(Y + (size_t)(row + 8) * ldy + col) = o23;
            }
        }
    }
}
#define GEMMH_SMEM (4*128*HSTR*2)   // 40960 bytes

// ---------------- fused qkv + MMA-attention + Wo (validated r12; Sa overlays Xs) ----------------
#define QKSTR 136
#define VTSTR 72
#define FSTR  72
#define SM_QK 0
#define SM_VT (64*QKSTR*2)                 // 17408
#define SM_XS (SM_VT + 64*VTSTR*2)         // 26624  (Xs in phase A, Sa in phase B/C)
#define SM_WS (SM_XS + 64*FSTR*2)          // 35840
#define SM_WO (SM_WS + 192*FSTR*2)         // 63488
#define FQ_SMEM (SM_WO + 64*FSTR*2)        // 72704

__global__ __launch_bounds__(256, 2) void qkv_attn_wo_kernel(
    const float* __restrict__ bqkv, const float* __restrict__ bo)
{
    extern __shared__ char sm[];
    __half* QKs = (__half*)(sm + SM_QK);    // [64][136]: q 0..63, k 64..127
    __half* Vt  = (__half*)(sm + SM_VT);    // [64 vcols][72 keys]
    __half* Xs  = (__half*)(sm + SM_XS);    // [64][72] input slice (phase A)
    __half* Sa  = Xs;                       // [64][72] attn out (overlays Xs)
    __half* Ws  = (__half*)(sm + SM_WS);    // [192][72]
    __half* Wo  = (__half*)(sm + SM_WO);    // [64][72]

    const int tid = threadIdx.x, warp = tid >> 5, lane = tid & 31;
    const int net = blockIdx.y;
    const int m0 = blockIdx.x * 64;
    const int l4 = lane >> 2, l2 = lane & 3;

    // ---- prologue loads ----
    const int xoff = 256 + ((net >= 2) ? 64 : 0);
    {
        int xrow = tid >> 2, seg = tid & 3;
        const __half* src = g_emb_h + (size_t)(m0 + xrow) * 384 + xoff + seg*16;
        unsigned dst = (unsigned)__cvta_generic_to_shared(Xs + xrow*FSTR + seg*16);
        cp16(dst, src); cp16(dst + 16, src + 8);
        if (tid < 192) {
            const __half* ws = g_Wqkv_h + ((size_t)net*192 + tid) * 64;
            unsigned wd = (unsigned)__cvta_generic_to_shared(Ws + tid*FSTR);
#pragma unroll
            for (int q = 0; q < 8; q++) cp16(wd + q*16, ws + q*8);
        } else {
            int row = tid - 192;
            const __half* os = g_Wo_h + (size_t)net*4096 + row*64;
            unsigned od = (unsigned)__cvta_generic_to_shared(Wo + row*FSTR);
#pragma unroll
            for (int q = 0; q < 8; q++) cp16(od + q*16, os + q*8);
        }
    }
    asm volatile("cp.async.commit_group;\n");
    asm volatile("cp.async.wait_group 0;\n");
    __syncthreads();

    // ---- Phase A: qkv mma. M=64 (mf=4), N=192 (8 warps x 24), K=64 ----
    {
        const int wn = warp * 24;
        float acc[4][3][4];
#pragma unroll
        for (int a = 0; a < 4; a++)
#pragma unroll
            for (int b = 0; b < 3; b++)
#pragma unroll
                for (int c = 0; c < 4; c++) acc[a][b][c] = 0.0f;

#pragma unroll
        for (int kb = 0; kb < 64; kb += 16) {
            unsigned afr[4][4];
#pragma unroll
            for (int mf = 0; mf < 4; mf++) {
                const __half* ap = Xs + (mf*16 + l4)*FSTR + kb + 2*l2;
                afr[mf][0] = ldw(ap);
                afr[mf][1] = ldw(ap + 8*FSTR);
                afr[mf][2] = ldw(ap + 8);
                afr[mf][3] = ldw(ap + 8*FSTR + 8);
            }
#pragma unroll
            for (int nf = 0; nf < 3; nf++) {
                const __half* bp = Ws + (wn + nf*8 + l4)*FSTR + kb + 2*l2;
                unsigned b0 = ldw(bp);
                unsigned b1 = ldw(bp + 8);
#pragma unroll
                for (int mf = 0; mf < 4; mf++)
                    mma_f16(acc[mf][nf], afr[mf], b0, b1);
            }
        }
        // epilogue: q,k -> QKs; v -> Vt (transposed)
#pragma unroll
        for (int nf = 0; nf < 3; nf++) {
            int col = wn + nf*8 + l2*2;
            float bb0 = bqkv[net*192 + col], bb1 = bqkv[net*192 + col + 1];
#pragma unroll
            for (int mf = 0; mf < 4; mf++) {
                int row = mf*16 + l4;
                float v0 = acc[mf][nf][0] + bb0, v1 = acc[mf][nf][1] + bb1;
                float v2 = acc[mf][nf][2] + bb0, v3 = acc[mf][nf][3] + bb1;
                if (col < 128) {
                    *(__half2*)(QKs + row*QKSTR + col)       = __floats2half2_rn(v0, v1);
                    *(__half2*)(QKs + (row + 8)*QKSTR + col) = __floats2half2_rn(v2, v3);
                } else {
                    int vc = col - 128;
                    Vt[vc*VTSTR + row]           = __float2half_rn(v0);
                    Vt[(vc + 1)*VTSTR + row]     = __float2half_rn(v1);
                    Vt[vc*VTSTR + row + 8]       = __float2half_rn(v2);
                    Vt[(vc + 1)*VTSTR + row + 8] = __float2half_rn(v3);
                }
            }
        }
    }
    __syncthreads();   // QKs + Vt ready; Xs reads done

    // ---- Phase B: MMA attention. 8 tasks (2 batches x 4 heads), one per warp ----
    {
        const int g = warp >> 2, h = warp & 3;

        unsigned qa[2][4];
#pragma unroll
        for (int mf = 0; mf < 2; mf++) {
            const __half* ap = QKs + (g*32 + mf*16 + l4)*QKSTR + h*16 + 2*l2;
            qa[mf][0] = ldw(ap);
            qa[mf][1] = ldw(ap + 8*QKSTR);
            qa[mf][2] = ldw(ap + 8);
            qa[mf][3] = ldw(ap + 8*QKSTR + 8);
        }
        float sacc[2][4][4];
#pragma unroll
        for (int a = 0; a < 2; a++)
#pragma unroll
            for (int b = 0; b < 4; b++)
#pragma unroll
                for (int c = 0; c < 4; c++) sacc[a][b][c] = 0.0f;
#pragma unroll
        for (int nf = 0; nf < 4; nf++) {
            const __half* bp = QKs + (g*32 + nf*8 + l4)*QKSTR + 64 + h*16 + 2*l2;
            unsigned b0 = ldw(bp), b1 = ldw(bp + 8);
#pragma unroll
            for (int mf = 0; mf < 2; mf++)
                mma_f16(sacc[mf][nf], qa[mf], b0, b1);
        }

        float rs[2][2];
        unsigned pa[2][2][4];
#pragma unroll
        for (int mf = 0; mf < 2; mf++) {
            float m0x = -1e30f, m1x = -1e30f;
#pragma unroll
            for (int nf = 0; nf < 4; nf++) {
                m0x = fmaxf(m0x, fmaxf(sacc[mf][nf][0], sacc[mf][nf][1]));
                m1x = fmaxf(m1x, fmaxf(sacc[mf][nf][2], sacc[mf][nf][3]));
            }
            m0x = fmaxf(m0x, __shfl_xor_sync(0xffffffffu, m0x, 1));
            m0x = fmaxf(m0x, __shfl_xor_sync(0xffffffffu, m0x, 2));
            m1x = fmaxf(m1x, __shfl_xor_sync(0xffffffffu, m1x, 1));
            m1x = fmaxf(m1x, __shfl_xor_sync(0xffffffffu, m1x, 2));

            float p[4][4];
            float s0 = 0.0f, s1 = 0.0f;
#pragma unroll
            for (int nf = 0; nf < 4; nf++) {
                p[nf][0] = __expf(0.25f * (sacc[mf][nf][0] - m0x));
                p[nf][1] = __expf(0.25f * (sacc[mf][nf][1] - m0x));
                p[nf][2] = __expf(0.25f * (sacc[mf][nf][2] - m1x));
                p[nf][3] = __expf(0.25f * (sacc[mf][nf][3] - m1x));
                s0 += p[nf][0] + p[nf][1];
                s1 += p[nf][2] + p[nf][3];
            }
            s0 += __shfl_xor_sync(0xffffffffu, s0, 1);
            s0 += __shfl_xor_sync(0xffffffffu, s0, 2);
            s1 += __shfl_xor_sync(0xffffffffu, s1, 1);
            s1 += __shfl_xor_sync(0xffffffffu, s1, 2);
            rs[mf][0] = 1.0f / s0;
            rs[mf][1] = 1.0f / s1;

            pa[mf][0][0] = pk(p[0][0], p[0][1]);
            pa[mf][0][1] = pk(p[0][2], p[0][3]);
            pa[mf][0][2] = pk(p[1][0], p[1][1]);
            pa[mf][0][3] = pk(p[1][2], p[1][3]);
            pa[mf][1][0] = pk(p[2][0], p[2][1]);
            pa[mf][1][1] = pk(p[2][2], p[2][3]);
            pa[mf][1][2] = pk(p[3][0], p[3][1]);
            pa[mf][1][3] = pk(p[3][2], p[3][3]);
        }

        float oacc[2][2][4];
#pragma unroll
        for (int a = 0; a < 2; a++)
#pragma unroll
            for (int b = 0; b < 2; b++)
#pragma unroll
                for (int c = 0; c < 4; c++) oacc[a][b][c] = 0.0f;
#pragma unroll
        for (int ks = 0; ks < 2; ks++)
#pragma unroll
            for (int nf = 0; nf < 2; nf++) {
                const __half* bp = Vt + (h*16 + nf*8 + l4)*VTSTR + g*32 + ks*16 + 2*l2;
                unsigned b0 = ldw(bp), b1 = ldw(bp + 8);
#pragma unroll
                for (int mf = 0; mf < 2; mf++)
                    mma_f16(oacc[mf][nf], pa[mf][ks], b0, b1);
            }

        __syncthreads();   // QKs/Vt reads done before Sa (overlay region) write

#pragma unroll
        for (int nf = 0; nf < 2; nf++) {
            int col = h*16 + nf*8 + 2*l2;
#pragma unroll
            for (int mf = 0; mf < 2; mf++) {
                int row = g*32 + mf*16 + l4;
                *(__half2*)(Sa + row*FSTR + col) =
                    __floats2half2_rn(oacc[mf][nf][0]*rs[mf][0], oacc[mf][nf][1]*rs[mf][0]);
                *(__half2*)(Sa + (row + 8)*FSTR + col) =
                    __floats2half2_rn(oacc[mf][nf][2]*rs[mf][1], oacc[mf][nf][3]*rs[mf][1]);
            }
        }
    }
    __syncthreads();   // Sa ready

    // ---- Phase C: Wo mma. M=64 (mf=4), N=64 (8 warps x 8), K=64 ----
    {
        const int wn = warp * 8;
        float acc[4][4];
#pragma unroll
        for (int a = 0; a < 4; a++)
#pragma unroll
            for (int c = 0; c < 4; c++) acc[a][c] = 0.0f;

#pragma unroll
        for (int kb = 0; kb < 64; kb += 16) {
            unsigned afr[4][4];
#pragma unroll
            for (int mf = 0; mf < 4; mf++) {
                const __half* ap = Sa + (mf*16 + l4)*FSTR + kb + 2*l2;
                afr[mf][0] = ldw(ap);
                afr[mf][1] = ldw(ap + 8*FSTR);
                afr[mf][2] = ldw(ap + 8);
                afr[mf][3] = ldw(ap + 8*FSTR + 8);
            }
            const __half* bp = Wo + (wn + l4)*FSTR + kb + 2*l2;
            unsigned b0 = ldw(bp);
            unsigned b1 = ldw(bp + 8);
#pragma unroll
            for (int mf = 0; mf < 4; mf++)
                mma_f16(acc[mf], afr[mf], b0, b1);
        }
        int col = wn + l2*2;
        float bb0 = bo[net*64 + col], bb1 = bo[net*64 + col + 1];
#pragma unroll
        for (int mf = 0; mf < 4; mf++) {
            int row = mf*16 + l4;
            *(__half2*)(g_mha_h + (size_t)(m0 + row) * 256 + net*64 + col) =
                __floats2half2_rn(acc[mf][0] + bb0, acc[mf][1] + bb1);
            *(__half2*)(g_mha_h + (size_t)(m0 + row + 8) * 256 + net*64 + col) =
                __floats2half2_rn(acc[mf][2] + bb0, acc[mf][3] + bb1);
        }
    }
}

// ---------------- reparameterise + softmax pooling: per batch ----------------
__global__ __launch_bounds__(256) void reparam_pool_kernel(
    const float* __restrict__ eps_intra, const float* __restrict__ eps_inter,
    const float* __restrict__ att_w, const float* __restrict__ att_b)
{
    __shared__ float sinter[32][65];
    __shared__ float ssc[32];
    const int b = blockIdx.x, tid = threadIdx.x;

#pragma unroll
    for (int i = 0; i < 8; i++) {
        int idx = tid + i*256;
        int r = idx >> 6, c = idx & 63;
        const __half* mh = g_mha_h + (size_t)(b*32 + r) * 256;
        float intra = __half2float(mh[c])
                    + softplusf(__half2float(mh[64 + c]) - 5.0f) * eps_intra[(size_t)(b*32 + r)*64 + c];
        g_emb_h[(size_t)(b*32 + r)*384 + 256 + c] = __float2half_rn(intra);
        float inter = __half2float(mh[128 + c])
                    + softplusf(__half2float(mh[192 + c]) - 5.0f) * eps_inter[(size_t)(b*32 + r)*64 + c];
        sinter[r][c] = inter;
    }
    __syncthreads();

    const int warp = tid >> 5, lane = tid & 31;
#pragma unroll
    for (int rr = 0; rr < 4; rr++) {
        int r = warp*4 + rr;
        float part = sinter[r][lane] * att_w[lane] + sinter[r][lane+32] * att_w[lane+32];
#pragma unroll
        for (int m = 16; m > 0; m >>= 1) part += __shfl_xor_sync(0xffffffffu, part, m);
        if (lane == 0) ssc[r] = part + att_b[0];
    }
    __syncthreads();

    if (warp == 0) {
        float l = ssc[lane];
        float mx = l;
#pragma unroll
        for (int m = 16; m > 0; m >>= 1) mx = fmaxf(mx, __shfl_xor_sync(0xffffffffu, mx, m));
        float e = __expf(l - mx);
        float sm = e;
#pragma unroll
        for (int m = 16; m > 0; m >>= 1) sm += __shfl_xor_sync(0xffffffffu, sm, m);
        ssc[lane] = e / sm;
    }
    __syncthreads();

    if (tid < 64) {
        float pooled = 0.0f;
#pragma unroll
        for (int r = 0; r < 32; r++) pooled += ssc[r] * sinter[r][tid];
        __half ph = __float2half_rn(pooled);
#pragma unroll
        for (int r = 0; r < 32; r++)
            g_emb_h[(size_t)(b*32 + r)*384 + 320 + tid] = ph;
    }
}

// ---------------- tensor-core action/value head: 128 rows per block ----------------
// out logits = h2 @ [Wa;Wv]^T : M=128, N=24 (16 actions + value col 16), K=256.
#define HD_STR 264
#define HD_H2  (128*HD_STR)
#define HD_W   (24*HD_STR)
#define HD_SMEM ((HD_H2 + HD_W)*2)   // 80256 bytes

__global__ __launch_bounds__(256, 2) void head_mma_kernel(
    const float* __restrict__ ba, const float* __restrict__ bv,
    float* __restrict__ out)
{
    extern __shared__ __half hs[];
    __half* H  = hs;             // [128][264]
    __half* Wv = hs + HD_H2;     // [24][264]

    const int tid = threadIdx.x, warp = tid >> 5, lane = tid & 31;
    const int l4 = lane >> 2, l2 = lane & 3;
    const int r0 = blockIdx.x * 128;

    // load h2 tile (2 threads per row, 128 halves each)
    {
        int row = tid >> 1, hb = (tid & 1) * 128;
        const __half* src = g_h2_h + (size_t)(r0 + row) * 256 + hb;
        unsigned dst = (unsigned)__cvta_generic_to_shared(H + row*HD_STR + hb);
#pragma unroll
        for (int q = 0; q < 16; q++) cp16(dst + q*16, src + q*8);
    }
    // load WaV (24 rows x 32 segs of 8 halves)
    for (int idx = tid; idx < 768; idx += 256) {
        int row = idx >> 5, seg = idx & 31;
        unsigned dst = (unsigned)__cvta_generic_to_shared(Wv + row*HD_STR + seg*8);
        cp16(dst, g_WaV_h + row*256 + seg*8);
    }
    asm volatile("cp.async.commit_group;\n");
    asm volatile("cp.async.wait_group 0;\n");
    __syncthreads();

    float acc[3][4];
#pragma unroll
    for (int b = 0; b < 3; b++)
#pragma unroll
        for (int c = 0; c < 4; c++) acc[b][c] = 0.0f;

#pragma unroll 4
    for (int kb = 0; kb < 256; kb += 16) {
        unsigned afr[4];
        const __half* ap = H + (warp*16 + l4)*HD_STR + kb + 2*l2;
        afr[0] = ldw(ap);
        afr[1] = ldw(ap + 8*HD_STR);
        afr[2] = ldw(ap + 8);
        afr[3] = ldw(ap + 8*HD_STR + 8);
#pragma unroll
        for (int nf = 0; nf < 3; nf++) {
            const __half* bp = Wv + (nf*8 + l4)*HD_STR + kb + 2*l2;
            unsigned b0 = ldw(bp);
            unsigned b1 = ldw(bp + 8);
            mma_f16(acc[nf], afr, b0, b1);
        }
    }

    // biases: cols 2l2/2l2+1 (nf0), 8+2l2/8+2l2+1 (nf1)
    float ba0 = ba[2*l2],     ba1 = ba[2*l2 + 1];
    float ba2 = ba[8 + 2*l2], ba3 = ba[8 + 2*l2 + 1];

    int row0 = r0 + warp*16 + l4;
    // rows l4 (c0,c1) and l4+8 (c2,c3)
#pragma unroll
    for (int rr = 0; rr < 2; rr++) {
        float a0 = acc[0][rr*2]     + ba0;
        float a1 = acc[0][rr*2 + 1] + ba1;
        float a2 = acc[1][rr*2]     + ba2;
        float a3 = acc[1][rr*2 + 1] + ba3;

        float mx = fmaxf(fmaxf(a0, a1), fmaxf(a2, a3));
        mx = fmaxf(mx, __shfl_xor_sync(0xffffffffu, mx, 1));
        mx = fmaxf(mx, __shfl_xor_sync(0xffffffffu, mx, 2));
        float e0 = __expf(a0 - mx), e1 = __expf(a1 - mx);
        float e2 = __expf(a2 - mx), e3 = __expf(a3 - mx);
        float sm = e0 + e1 + e2 + e3;
        sm += __shfl_xor_sync(0xffffffffu, sm, 1);
        sm += __shfl_xor_sync(0xffffffffu, sm, 2);
        float lse = mx + logf(sm);

        int row = row0 + rr*8;
        float2 o01; o01.x = a0 - lse; o01.y = a1 - lse;
        float2 o23; o23.x = a2 - lse; o23.y = a3 - lse;
        *(float2*)(out + (size_t)row * 16 + 2*l2)     = o01;
        *(float2*)(out + (size_t)row * 16 + 8 + 2*l2) = o23;

        if (l2 == 0)   // value = col 16 (nf2 c0/c2)
            out[(size_t)NROWS * 16 + row] = acc[2][rr*2] + bv[0];
    }
}

// ---------------- launch ----------------
extern "C" void kernel_launch(void* const* d_in, const int* in_sizes, int n_in,
                              void* d_out, int out_size) {
    const float* obs       = (const float*)d_in[0];
    const float* eps_intra = (const float*)d_in[1];
    const float* eps_inter = (const float*)d_in[2];
    const float* W_local   = (const float*)d_in[3];
    const float* b_local   = (const float*)d_in[4];
    const float* W_inter   = (const float*)d_in[5];
    const float* b_inter   = (const float*)d_in[6];
    const float* W_intra   = (const float*)d_in[7];
    const float* b_intra   = (const float*)d_in[8];
    const float* Wqkv      = (const float*)d_in[9];
    const float* bqkv      = (const float*)d_in[10];
    const float* Wo        = (const float*)d_in[11];
    const float* bo        = (const float*)d_in[12];
    const float* att_w     = (const float*)d_in[13];
    const float* att_b     = (const float*)d_in[14];
    const float* W1        = (const float*)d_in[15];
    const float* b1        = (const float*)d_in[16];
    const float* W2        = (const float*)d_in[17];
    const float* b2        = (const float*)d_in[18];
    const float* Wa        = (const float*)d_in[19];
    const float* ba        = (const float*)d_in[20];
    const float* Wv        = (const float*)d_in[21];
    const float* bv        = (const float*)d_in[22];
    float* out = (float*)d_out;

    __half *p_obs_h, *p_Wemb_h, *p_W1_h, *p_W2_h, *p_emb_h, *p_h1_h, *p_h2_h;
    float  *p_bemb;
    cudaGetSymbolAddress((void**)&p_obs_h,  g_obs_h);
    cudaGetSymbolAddress((void**)&p_Wemb_h, g_Wemb_h);
    cudaGetSymbolAddress((void**)&p_W1_h,   g_W1_h);
    cudaGetSymbolAddress((void**)&p_W2_h,   g_W2_h);
    cudaGetSymbolAddress((void**)&p_emb_h,  g_emb_h);
    cudaGetSymbolAddress((void**)&p_h1_h,   g_h1_h);
    cudaGetSymbolAddress((void**)&p_h2_h,   g_h2_h);
    cudaGetSymbolAddress((void**)&p_bemb,   g_bemb);

    cudaFuncSetAttribute(qkv_attn_wo_kernel, cudaFuncAttributeMaxDynamicSharedMemorySize, FQ_SMEM);
    cudaFuncSetAttribute(head_mma_kernel,    cudaFuncAttributeMaxDynamicSharedMemorySize, HD_SMEM);

    const int MB = NROWS / 128;   // 1024

    // 1) convert obs + pack weights
    conv_obs<<<NROWS*128/1024, 256>>>(obs);
    pack_w<<<384, 256>>>(W_local, b_local, W_inter, b_inter, W_intra, b_intra,
                         Wqkv, Wo, W1, W2, Wa, Wv);

    // 2) embeddings: [local | intra_e | inter_e] = tanh(obs @ Wemb^T + b) -> half
    gemm_h<1,1><<<dim3(MB, 3), 256, GEMMH_SMEM>>>(p_obs_h, 128, p_Wemb_h, p_bemb,
                                                  p_emb_h, 384, 128);

    // 3) fused qkv + MMA attention + Wo (writes g_mha_h fp16)
    qkv_attn_wo_kernel<<<dim3(NROWS/64, 4), 256, FQ_SMEM>>>(bqkv, bo);

    // 4) reparameterise + softmax pooling
    reparam_pool_kernel<<<BATCH, 256>>>(eps_intra, eps_inter, att_w, att_b);

    // 5) MLP: W1 -> h1 (half), W2 -> h2 (half)
    gemm_h<1,1><<<dim3(MB, 2), 256, GEMMH_SMEM>>>(p_emb_h, 384, p_W1_h, b1,
                                                  p_h1_h, 256, 384);
    gemm_h<1,1><<<dim3(MB, 2), 256, GEMMH_SMEM>>>(p_h1_h, 256, p_W2_h, b2,
                                                  p_h2_h, 256, 256);

    // 6) tensor-core action/value head with log-softmax
    head_mma_kernel<<<NROWS/128, 256, HD_SMEM>>>(ba, bv, out);
}

// round 14
// speedup vs baseline: 2.0178x; 1.0123x over previous
#include <cuda_runtime.h>
#include <cuda_fp16.h>
#include <math.h>

#define BATCH 4096
#define AGENTS 32
#define NROWS (BATCH*AGENTS)      // 131072
#define NACT 16

// ---------------- scratch (device globals; no allocation) ----------------
__device__ __half g_obs_h[(size_t)NROWS*128];
__device__ __half g_Wemb_h[384*128];
__device__ float  g_bemb[384];
__device__ __half g_Wqkv_h[768*64];            // [net][192][64]
__device__ __half g_Wo_h[4*64*64];             // [net][64][64]
__device__ __half g_W1_h[256*384];
__device__ __half g_W2_h[256*256];
__device__ __half g_WaV_h[24*256];             // rows 0..15 Wa, 16 Wv, 17..23 zero
__device__ __half g_emb_h[(size_t)NROWS*384];  // [local(256) | intra(64) | inter->pooled(64)]
__device__ __half g_mha_h[(size_t)NROWS*256];  // post-Wo fp16
__device__ __half g_h1_h[(size_t)NROWS*256];
__device__ __half g_h2_h[(size_t)NROWS*256];

__device__ __forceinline__ float softplusf(float x) {
    return x > 20.0f ? x : log1pf(__expf(x));
}
__device__ __forceinline__ unsigned ldw(const __half* p) {   // aligned half2 word
    return *(const unsigned*)p;
}
__device__ __forceinline__ unsigned pk(float a, float b) {
    __half2 t = __floats2half2_rn(a, b);
    return *(unsigned*)&t;
}
__device__ __forceinline__ void mma_f16(float* c, const unsigned* a, unsigned b0, unsigned b1) {
    asm volatile("mma.sync.aligned.m16n8k16.row.col.f32.f16.f16.f32 "
                 "{%0,%1,%2,%3},{%4,%5,%6,%7},{%8,%9},{%0,%1,%2,%3};"
                 : "+f"(c[0]), "+f"(c[1]), "+f"(c[2]), "+f"(c[3])
                 : "r"(a[0]), "r"(a[1]), "r"(a[2]), "r"(a[3]), "r"(b0), "r"(b1));
}
__device__ __forceinline__ void cp16(unsigned s, const void* g) {
    asm volatile("cp.async.ca.shared.global [%0], [%1], 16;\n" :: "r"(s), "l"(g));
}

// ---------------- merged: obs -> fp16 + pack all weights -> fp16 ----------------
__global__ void prep_kernel(const float* __restrict__ obs,
                            const float* __restrict__ Wl, const float* __restrict__ bl,
                            const float* __restrict__ Wi, const float* __restrict__ bi,
                            const float* __restrict__ Wt, const float* __restrict__ bt,
                            const float* __restrict__ Wqkv, const float* __restrict__ Wo,
                            const float* __restrict__ W1, const float* __restrict__ W2,
                            const float* __restrict__ Wa, const float* __restrict__ Wv) {
    int idx = blockIdx.x * blockDim.x + threadIdx.x;

    // obs conversion: 4 floats per thread
    {
        size_t i = (size_t)idx * 4;
        float4 v = *(const float4*)(obs + i);
        __half2* o = (__half2*)(g_obs_h + i);
        o[0] = __floats2half2_rn(v.x, v.y);
        o[1] = __floats2half2_rn(v.z, v.w);
    }

    // weight packing (low idx range only)
    if (idx < 384*128) {
        int row = idx >> 7, col = idx & 127;
        float v;
        if (row < 256)      v = Wl[row*128 + col];
        else if (row < 320) v = Wt[(row-256)*128 + col];
        else                v = Wi[(row-320)*128 + col];
        g_Wemb_h[idx] = __float2half_rn(v);
    }
    if (idx < 768*64)   g_Wqkv_h[idx] = __float2half_rn(Wqkv[idx]);
    if (idx < 4*64*64)  g_Wo_h[idx]   = __float2half_rn(Wo[idx]);
    if (idx < 256*384)  g_W1_h[idx]   = __float2half_rn(W1[idx]);
    if (idx < 256*256)  g_W2_h[idx]   = __float2half_rn(W2[idx]);
    if (idx < 24*256) {
        int row = idx >> 8, col = idx & 255;
        float v = (row < 16) ? Wa[row*256 + col] : (row == 16 ? Wv[col] : 0.0f);
        g_WaV_h[idx] = __float2half_rn(v);
    }
    if (idx < 384)
        g_bemb[idx] = (idx < 256) ? bl[idx] : (idx < 320 ? bt[idx-256] : bi[idx-320]);
}

// ---------------- FP16 tensor-core GEMM (validated r11-r13) ----------------
#define HSTR 40
template<int EPI, int OUTH>  // EPI: 1 = tanh; OUTH: 1 = half out, 0 = float out
__global__ __launch_bounds__(256, 2) void gemm_h(
    const __half* __restrict__ X, int ldx,
    const __half* __restrict__ W, const float* __restrict__ bias,
    void* __restrict__ Yv, int ldy, int K)
{
    extern __shared__ __half hsm[];
    __half* Xs = hsm;                        // [2][128*HSTR]
    __half* Ws = hsm + 2*128*HSTR;           // [2][128*HSTR]

    const int tid = threadIdx.x;
    const int m0 = blockIdx.x * 128, n0 = blockIdx.y * 128;
    const int warp = tid >> 5, lane = tid & 31;
    const int wm = (warp & 1) * 64, wn = (warp >> 1) * 32;
    const int l4 = lane >> 2, l2 = lane & 3;

    const int grow = tid & 127, gmat = tid >> 7;
    const __half* grsrc = gmat ? (W + (size_t)(n0 + grow) * K)
                               : (X + (size_t)(m0 + grow) * ldx);
    unsigned gdst0 = (unsigned)__cvta_generic_to_shared(
        (gmat ? Ws : Xs) + grow*HSTR);

    float acc[4][4][4];
#pragma unroll
    for (int a = 0; a < 4; a++)
#pragma unroll
        for (int b = 0; b < 4; b++)
#pragma unroll
            for (int c = 0; c < 4; c++) acc[a][b][c] = 0.0f;

    const int nstage = K >> 5;

#pragma unroll
    for (int q = 0; q < 4; q++)
        cp16(gdst0 + q*16, grsrc + q*8);
    asm volatile("cp.async.commit_group;\n");

    for (int s = 0; s < nstage; s++) {
        asm volatile("cp.async.wait_group 0;\n");
        __syncthreads();

        if (s + 1 < nstage) {
            int k0 = (s + 1) << 5;
            unsigned gd = gdst0 + ((s+1)&1) * 128*HSTR*2;
#pragma unroll
            for (int q = 0; q < 4; q++)
                cp16(gd + q*16, grsrc + k0 + q*8);
            asm volatile("cp.async.commit_group;\n");
        }

        const __half* Xb = Xs + (s & 1) * 128*HSTR;
        const __half* Wb = Ws + (s & 1) * 128*HSTR;
#pragma unroll
        for (int kb = 0; kb < 32; kb += 16) {
            unsigned afr[4][4];
#pragma unroll
            for (int mf = 0; mf < 4; mf++) {
                const __half* ap = Xb + (wm + mf*16 + l4)*HSTR + kb + 2*l2;
                afr[mf][0] = ldw(ap);
                afr[mf][1] = ldw(ap + 8*HSTR);
                afr[mf][2] = ldw(ap + 8);
                afr[mf][3] = ldw(ap + 8*HSTR + 8);
            }
#pragma unroll
            for (int nf = 0; nf < 4; nf++) {
                const __half* bp = Wb + (wn + nf*8 + l4)*HSTR + kb + 2*l2;
                unsigned b0 = ldw(bp);
                unsigned b1 = ldw(bp + 8);
#pragma unroll
                for (int mf = 0; mf < 4; mf++)
                    mma_f16(acc[mf][nf], afr[mf], b0, b1);
            }
        }
    }

#pragma unroll
    for (int nf = 0; nf < 4; nf++) {
        int col = n0 + wn + nf*8 + l2*2;
        float bb0 = bias[col], bb1 = bias[col + 1];
#pragma unroll
        for (int mf = 0; mf < 4; mf++) {
            int row = m0 + wm + mf*16 + l4;
            float v0 = acc[mf][nf][0] + bb0, v1 = acc[mf][nf][1] + bb1;
            float v2 = acc[mf][nf][2] + bb0, v3 = acc[mf][nf][3] + bb1;
            if (EPI == 1) { v0 = tanhf(v0); v1 = tanhf(v1); v2 = tanhf(v2); v3 = tanhf(v3); }
            if (OUTH) {
                __half* Y = (__half*)Yv;
                *(__half2*)(Y + (size_t)row * ldy + col)       = __floats2half2_rn(v0, v1);
                *(__half2*)(Y + (size_t)(row + 8) * ldy + col) = __floats2half2_rn(v2, v3);
            } else {
                float* Y = (float*)Yv;
                float2 o01; o01.x = v0; o01.y = v1;
                float2 o23; o23.x = v2; o23.y = v3;
                *(float2*)(Y + (size_t)row * ldy + col) = o01;
                *(float2*)(Y + (size_t)(row + 8) * ldy + col) = o23;
            }
        }
    }
}
#define GEMMH_SMEM (4*128*HSTR*2)   // 40960 bytes

// ---------------- fused qkv + MMA-attention + Wo (r13 + 3 CTAs/SM) ----------------
#define QKSTR 136
#define VTSTR 72
#define FSTR  72
#define SM_QK 0
#define SM_VT (64*QKSTR*2)                 // 17408
#define SM_XS (SM_VT + 64*VTSTR*2)         // 26624  (Xs in phase A, Sa in phase B/C)
#define SM_WS (SM_XS + 64*FSTR*2)          // 35840
#define SM_WO (SM_WS + 192*FSTR*2)         // 63488
#define FQ_SMEM (SM_WO + 64*FSTR*2)        // 72704

__global__ __launch_bounds__(256, 3) void qkv_attn_wo_kernel(
    const float* __restrict__ bqkv, const float* __restrict__ bo)
{
    extern __shared__ char sm[];
    __half* QKs = (__half*)(sm + SM_QK);    // [64][136]: q 0..63, k 64..127
    __half* Vt  = (__half*)(sm + SM_VT);    // [64 vcols][72 keys]
    __half* Xs  = (__half*)(sm + SM_XS);    // [64][72] input slice (phase A)
    __half* Sa  = Xs;                       // [64][72] attn out (overlays Xs)
    __half* Ws  = (__half*)(sm + SM_WS);    // [192][72]
    __half* Wo  = (__half*)(sm + SM_WO);    // [64][72]

    const int tid = threadIdx.x, warp = tid >> 5, lane = tid & 31;
    const int net = blockIdx.y;
    const int m0 = blockIdx.x * 64;
    const int l4 = lane >> 2, l2 = lane & 3;

    // ---- prologue loads ----
    const int xoff = 256 + ((net >= 2) ? 64 : 0);
    {
        int xrow = tid >> 2, seg = tid & 3;
        const __half* src = g_emb_h + (size_t)(m0 + xrow) * 384 + xoff + seg*16;
        unsigned dst = (unsigned)__cvta_generic_to_shared(Xs + xrow*FSTR + seg*16);
        cp16(dst, src); cp16(dst + 16, src + 8);
        if (tid < 192) {
            const __half* ws = g_Wqkv_h + ((size_t)net*192 + tid) * 64;
            unsigned wd = (unsigned)__cvta_generic_to_shared(Ws + tid*FSTR);
#pragma unroll
            for (int q = 0; q < 8; q++) cp16(wd + q*16, ws + q*8);
        } else {
            int row = tid - 192;
            const __half* os = g_Wo_h + (size_t)net*4096 + row*64;
            unsigned od = (unsigned)__cvta_generic_to_shared(Wo + row*FSTR);
#pragma unroll
            for (int q = 0; q < 8; q++) cp16(od + q*16, os + q*8);
        }
    }
    asm volatile("cp.async.commit_group;\n");
    asm volatile("cp.async.wait_group 0;\n");
    __syncthreads();

    // ---- Phase A: qkv mma. M=64 (mf=4), N=192 (8 warps x 24), K=64 ----
    {
        const int wn = warp * 24;
        float acc[4][3][4];
#pragma unroll
        for (int a = 0; a < 4; a++)
#pragma unroll
            for (int b = 0; b < 3; b++)
#pragma unroll
                for (int c = 0; c < 4; c++) acc[a][b][c] = 0.0f;

#pragma unroll
        for (int kb = 0; kb < 64; kb += 16) {
            unsigned afr[4][4];
#pragma unroll
            for (int mf = 0; mf < 4; mf++) {
                const __half* ap = Xs + (mf*16 + l4)*FSTR + kb + 2*l2;
                afr[mf][0] = ldw(ap);
                afr[mf][1] = ldw(ap + 8*FSTR);
                afr[mf][2] = ldw(ap + 8);
                afr[mf][3] = ldw(ap + 8*FSTR + 8);
            }
#pragma unroll
            for (int nf = 0; nf < 3; nf++) {
                const __half* bp = Ws + (wn + nf*8 + l4)*FSTR + kb + 2*l2;
                unsigned b0 = ldw(bp);
                unsigned b1 = ldw(bp + 8);
#pragma unroll
                for (int mf = 0; mf < 4; mf++)
                    mma_f16(acc[mf][nf], afr[mf], b0, b1);
            }
        }
        // epilogue: q,k -> QKs; v -> Vt (transposed)
#pragma unroll
        for (int nf = 0; nf < 3; nf++) {
            int col = wn + nf*8 + l2*2;
            float bb0 = bqkv[net*192 + col], bb1 = bqkv[net*192 + col + 1];
#pragma unroll
            for (int mf = 0; mf < 4; mf++) {
                int row = mf*16 + l4;
                float v0 = acc[mf][nf][0] + bb0, v1 = acc[mf][nf][1] + bb1;
                float v2 = acc[mf][nf][2] + bb0, v3 = acc[mf][nf][3] + bb1;
                if (col < 128) {
                    *(__half2*)(QKs + row*QKSTR + col)       = __floats2half2_rn(v0, v1);
                    *(__half2*)(QKs + (row + 8)*QKSTR + col) = __floats2half2_rn(v2, v3);
                } else {
                    int vc = col - 128;
                    Vt[vc*VTSTR + row]           = __float2half_rn(v0);
                    Vt[(vc + 1)*VTSTR + row]     = __float2half_rn(v1);
                    Vt[vc*VTSTR + row + 8]       = __float2half_rn(v2);
                    Vt[(vc + 1)*VTSTR + row + 8] = __float2half_rn(v3);
                }
            }
        }
    }
    __syncthreads();   // QKs + Vt ready; Xs reads done

    // ---- Phase B: MMA attention. 8 tasks (2 batches x 4 heads), one per warp ----
    {
        const int g = warp >> 2, h = warp & 3;

        unsigned qa[2][4];
#pragma unroll
        for (int mf = 0; mf < 2; mf++) {
            const __half* ap = QKs + (g*32 + mf*16 + l4)*QKSTR + h*16 + 2*l2;
            qa[mf][0] = ldw(ap);
            qa[mf][1] = ldw(ap + 8*QKSTR);
            qa[mf][2] = ldw(ap + 8);
            qa[mf][3] = ldw(ap + 8*QKSTR + 8);
        }
        float sacc[2][4][4];
#pragma unroll
        for (int a = 0; a < 2; a++)
#pragma unroll
            for (int b = 0; b < 4; b++)
#pragma unroll
                for (int c = 0; c < 4; c++) sacc[a][b][c] = 0.0f;
#pragma unroll
        for (int nf = 0; nf < 4; nf++) {
            const __half* bp = QKs + (g*32 + nf*8 + l4)*QKSTR + 64 + h*16 + 2*l2;
            unsigned b0 = ldw(bp), b1 = ldw(bp + 8);
#pragma unroll
            for (int mf = 0; mf < 2; mf++)
                mma_f16(sacc[mf][nf], qa[mf], b0, b1);
        }

        float rs[2][2];
        unsigned pa[2][2][4];
#pragma unroll
        for (int mf = 0; mf < 2; mf++) {
            float m0x = -1e30f, m1x = -1e30f;
#pragma unroll
            for (int nf = 0; nf < 4; nf++) {
                m0x = fmaxf(m0x, fmaxf(sacc[mf][nf][0], sacc[mf][nf][1]));
                m1x = fmaxf(m1x, fmaxf(sacc[mf][nf][2], sacc[mf][nf][3]));
            }
            m0x = fmaxf(m0x, __shfl_xor_sync(0xffffffffu, m0x, 1));
            m0x = fmaxf(m0x, __shfl_xor_sync(0xffffffffu, m0x, 2));
            m1x = fmaxf(m1x, __shfl_xor_sync(0xffffffffu, m1x, 1));
            m1x = fmaxf(m1x, __shfl_xor_sync(0xffffffffu, m1x, 2));

            float p[4][4];
            float s0 = 0.0f, s1 = 0.0f;
#pragma unroll
            for (int nf = 0; nf < 4; nf++) {
                p[nf][0] = __expf(0.25f * (sacc[mf][nf][0] - m0x));
                p[nf][1] = __expf(0.25f * (sacc[mf][nf][1] - m0x));
                p[nf][2] = __expf(0.25f * (sacc[mf][nf][2] - m1x));
                p[nf][3] = __expf(0.25f * (sacc[mf][nf][3] - m1x));
                s0 += p[nf][0] + p[nf][1];
                s1 += p[nf][2] + p[nf][3];
            }
            s0 += __shfl_xor_sync(0xffffffffu, s0, 1);
            s0 += __shfl_xor_sync(0xffffffffu, s0, 2);
            s1 += __shfl_xor_sync(0xffffffffu, s1, 1);
            s1 += __shfl_xor_sync(0xffffffffu, s1, 2);
            rs[mf][0] = 1.0f / s0;
            rs[mf][1] = 1.0f / s1;

            pa[mf][0][0] = pk(p[0][0], p[0][1]);
            pa[mf][0][1] = pk(p[0][2], p[0][3]);
            pa[mf][0][2] = pk(p[1][0], p[1][1]);
            pa[mf][0][3] = pk(p[1][2], p[1][3]);
            pa[mf][1][0] = pk(p[2][0], p[2][1]);
            pa[mf][1][1] = pk(p[2][2], p[2][3]);
            pa[mf][1][2] = pk(p[3][0], p[3][1]);
            pa[mf][1][3] = pk(p[3][2], p[3][3]);
        }

        float oacc[2][2][4];
#pragma unroll
        for (int a = 0; a < 2; a++)
#pragma unroll
            for (int b = 0; b < 2; b++)
#pragma unroll
                for (int c = 0; c < 4; c++) oacc[a][b][c] = 0.0f;
#pragma unroll
        for (int ks = 0; ks < 2; ks++)
#pragma unroll
            for (int nf = 0; nf < 2; nf++) {
                const __half* bp = Vt + (h*16 + nf*8 + l4)*VTSTR + g*32 + ks*16 + 2*l2;
                unsigned b0 = ldw(bp), b1 = ldw(bp + 8);
#pragma unroll
                for (int mf = 0; mf < 2; mf++)
                    mma_f16(oacc[mf][nf], pa[mf][ks], b0, b1);
            }

        __syncthreads();   // QKs/Vt reads done before Sa (overlay region) write

#pragma unroll
        for (int nf = 0; nf < 2; nf++) {
            int col = h*16 + nf*8 + 2*l2;
#pragma unroll
            for (int mf = 0; mf < 2; mf++) {
                int row = g*32 + mf*16 + l4;
                *(__half2*)(Sa + row*FSTR + col) =
                    __floats2half2_rn(oacc[mf][nf][0]*rs[mf][0], oacc[mf][nf][1]*rs[mf][0]);
                *(__half2*)(Sa + (row + 8)*FSTR + col) =
                    __floats2half2_rn(oacc[mf][nf][2]*rs[mf][1], oacc[mf][nf][3]*rs[mf][1]);
            }
        }
    }
    __syncthreads();   // Sa ready

    // ---- Phase C: Wo mma. M=64 (mf=4), N=64 (8 warps x 8), K=64 ----
    {
        const int wn = warp * 8;
        float acc[4][4];
#pragma unroll
        for (int a = 0; a < 4; a++)
#pragma unroll
            for (int c = 0; c < 4; c++) acc[a][c] = 0.0f;

#pragma unroll
        for (int kb = 0; kb < 64; kb += 16) {
            unsigned afr[4][4];
#pragma unroll
            for (int mf = 0; mf < 4; mf++) {
                const __half* ap = Sa + (mf*16 + l4)*FSTR + kb + 2*l2;
                afr[mf][0] = ldw(ap);
                afr[mf][1] = ldw(ap + 8*FSTR);
                afr[mf][2] = ldw(ap + 8);
                afr[mf][3] = ldw(ap + 8*FSTR + 8);
            }
            const __half* bp = Wo + (wn + l4)*FSTR + kb + 2*l2;
            unsigned b0 = ldw(bp);
            unsigned b1 = ldw(bp + 8);
#pragma unroll
            for (int mf = 0; mf < 4; mf++)
                mma_f16(acc[mf], afr[mf], b0, b1);
        }
        int col = wn + l2*2;
        float bb0 = bo[net*64 + col], bb1 = bo[net*64 + col + 1];
#pragma unroll
        for (int mf = 0; mf < 4; mf++) {
            int row = mf*16 + l4;
            *(__half2*)(g_mha_h + (size_t)(m0 + row) * 256 + net*64 + col) =
                __floats2half2_rn(acc[mf][0] + bb0, acc[mf][1] + bb1);
            *(__half2*)(g_mha_h + (size_t)(m0 + row + 8) * 256 + net*64 + col) =
                __floats2half2_rn(acc[mf][2] + bb0, acc[mf][3] + bb1);
        }
    }
}

// ---------------- reparameterise + softmax pooling: per batch ----------------
__global__ __launch_bounds__(256) void reparam_pool_kernel(
    const float* __restrict__ eps_intra, const float* __restrict__ eps_inter,
    const float* __restrict__ att_w, const float* __restrict__ att_b)
{
    __shared__ float sinter[32][65];
    __shared__ float ssc[32];
    const int b = blockIdx.x, tid = threadIdx.x;

#pragma unroll
    for (int i = 0; i < 8; i++) {
        int idx = tid + i*256;
        int r = idx >> 6, c = idx & 63;
        const __half* mh = g_mha_h + (size_t)(b*32 + r) * 256;
        float intra = __half2float(mh[c])
                    + softplusf(__half2float(mh[64 + c]) - 5.0f) * eps_intra[(size_t)(b*32 + r)*64 + c];
        g_emb_h[(size_t)(b*32 + r)*384 + 256 + c] = __float2half_rn(intra);
        float inter = __half2float(mh[128 + c])
                    + softplusf(__half2float(mh[192 + c]) - 5.0f) * eps_inter[(size_t)(b*32 + r)*64 + c];
        sinter[r][c] = inter;
    }
    __syncthreads();

    const int warp = tid >> 5, lane = tid & 31;
#pragma unroll
    for (int rr = 0; rr < 4; rr++) {
        int r = warp*4 + rr;
        float part = sinter[r][lane] * att_w[lane] + sinter[r][lane+32] * att_w[lane+32];
#pragma unroll
        for (int m = 16; m > 0; m >>= 1) part += __shfl_xor_sync(0xffffffffu, part, m);
        if (lane == 0) ssc[r] = part + att_b[0];
    }
    __syncthreads();

    if (warp == 0) {
        float l = ssc[lane];
        float mx = l;
#pragma unroll
        for (int m = 16; m > 0; m >>= 1) mx = fmaxf(mx, __shfl_xor_sync(0xffffffffu, mx, m));
        float e = __expf(l - mx);
        float sm = e;
#pragma unroll
        for (int m = 16; m > 0; m >>= 1) sm += __shfl_xor_sync(0xffffffffu, sm, m);
        ssc[lane] = e / sm;
    }
    __syncthreads();

    if (tid < 64) {
        float pooled = 0.0f;
#pragma unroll
        for (int r = 0; r < 32; r++) pooled += ssc[r] * sinter[r][tid];
        __half ph = __float2half_rn(pooled);
#pragma unroll
        for (int r = 0; r < 32; r++)
            g_emb_h[(size_t)(b*32 + r)*384 + 320 + tid] = ph;
    }
}

// ---------------- tensor-core action/value head (validated r13) ----------------
#define HD_STR 264
#define HD_H2  (128*HD_STR)
#define HD_W   (24*HD_STR)
#define HD_SMEM ((HD_H2 + HD_W)*2)   // 80256 bytes

__global__ __launch_bounds__(256, 2) void head_mma_kernel(
    const float* __restrict__ ba, const float* __restrict__ bv,
    float* __restrict__ out)
{
    extern __shared__ __half hs[];
    __half* H  = hs;             // [128][264]
    __half* Wv = hs + HD_H2;     // [24][264]

    const int tid = threadIdx.x, warp = tid >> 5, lane = tid & 31;
    const int l4 = lane >> 2, l2 = lane & 3;
    const int r0 = blockIdx.x * 128;

    {
        int row = tid >> 1, hb = (tid & 1) * 128;
        const __half* src = g_h2_h + (size_t)(r0 + row) * 256 + hb;
        unsigned dst = (unsigned)__cvta_generic_to_shared(H + row*HD_STR + hb);
#pragma unroll
        for (int q = 0; q < 16; q++) cp16(dst + q*16, src + q*8);
    }
    for (int idx = tid; idx < 768; idx += 256) {
        int row = idx >> 5, seg = idx & 31;
        unsigned dst = (unsigned)__cvta_generic_to_shared(Wv + row*HD_STR + seg*8);
        cp16(dst, g_WaV_h + row*256 + seg*8);
    }
    asm volatile("cp.async.commit_group;\n");
    asm volatile("cp.async.wait_group 0;\n");
    __syncthreads();

    float acc[3][4];
#pragma unroll
    for (int b = 0; b < 3; b++)
#pragma unroll
        for (int c = 0; c < 4; c++) acc[b][c] = 0.0f;

#pragma unroll 4
    for (int kb = 0; kb < 256; kb += 16) {
        unsigned afr[4];
        const __half* ap = H + (warp*16 + l4)*HD_STR + kb + 2*l2;
        afr[0] = ldw(ap);
        afr[1] = ldw(ap + 8*HD_STR);
        afr[2] = ldw(ap + 8);
        afr[3] = ldw(ap + 8*HD_STR + 8);
#pragma unroll
        for (int nf = 0; nf < 3; nf++) {
            const __half* bp = Wv + (nf*8 + l4)*HD_STR + kb + 2*l2;
            unsigned b0 = ldw(bp);
            unsigned b1 = ldw(bp + 8);
            mma_f16(acc[nf], afr, b0, b1);
        }
    }

    float ba0 = ba[2*l2],     ba1 = ba[2*l2 + 1];
    float ba2 = ba[8 + 2*l2], ba3 = ba[8 + 2*l2 + 1];

    int row0 = r0 + warp*16 + l4;
#pragma unroll
    for (int rr = 0; rr < 2; rr++) {
        float a0 = acc[0][rr*2]     + ba0;
        float a1 = acc[0][rr*2 + 1] + ba1;
        float a2 = acc[1][rr*2]     + ba2;
        float a3 = acc[1][rr*2 + 1] + ba3;

        float mx = fmaxf(fmaxf(a0, a1), fmaxf(a2, a3));
        mx = fmaxf(mx, __shfl_xor_sync(0xffffffffu, mx, 1));
        mx = fmaxf(mx, __shfl_xor_sync(0xffffffffu, mx, 2));
        float e0 = __expf(a0 - mx), e1 = __expf(a1 - mx);
        float e2 = __expf(a2 - mx), e3 = __expf(a3 - mx);
        float sm = e0 + e1 + e2 + e3;
        sm += __shfl_xor_sync(0xffffffffu, sm, 1);
        sm += __shfl_xor_sync(0xffffffffu, sm, 2);
        float lse = mx + logf(sm);

        int row = row0 + rr*8;
        float2 o01; o01.x = a0 - lse; o01.y = a1 - lse;
        float2 o23; o23.x = a2 - lse; o23.y = a3 - lse;
        *(float2*)(out + (size_t)row * 16 + 2*l2)     = o01;
        *(float2*)(out + (size_t)row * 16 + 8 + 2*l2) = o23;

        if (l2 == 0)
            out[(size_t)NROWS * 16 + row] = acc[2][rr*2] + bv[0];
    }
}

// ---------------- launch ----------------
extern "C" void kernel_launch(void* const* d_in, const int* in_sizes, int n_in,
                              void* d_out, int out_size) {
    const float* obs       = (const float*)d_in[0];
    const float* eps_intra = (const float*)d_in[1];
    const float* eps_inter = (const float*)d_in[2];
    const float* W_local   = (const float*)d_in[3];
    const float* b_local   = (const float*)d_in[4];
    const float* W_inter   = (const float*)d_in[5];
    const float* b_inter   = (const float*)d_in[6];
    const float* W_intra   = (const float*)d_in[7];
    const float* b_intra   = (const float*)d_in[8];
    const float* Wqkv      = (const float*)d_in[9];
    const float* bqkv      = (const float*)d_in[10];
    const float* Wo        = (const float*)d_in[11];
    const float* bo        = (const float*)d_in[12];
    const float* att_w     = (const float*)d_in[13];
    const float* att_b     = (const float*)d_in[14];
    const float* W1        = (const float*)d_in[15];
    const float* b1        = (const float*)d_in[16];
    const float* W2        = (const float*)d_in[17];
    const float* b2        = (const float*)d_in[18];
    const float* Wa        = (const float*)d_in[19];
    const float* ba        = (const float*)d_in[20];
    const float* Wv        = (const float*)d_in[21];
    const float* bv        = (const float*)d_in[22];
    float* out = (float*)d_out;

    __half *p_obs_h, *p_Wemb_h, *p_W1_h, *p_W2_h, *p_emb_h, *p_h1_h, *p_h2_h;
    float  *p_bemb;
    cudaGetSymbolAddress((void**)&p_obs_h,  g_obs_h);
    cudaGetSymbolAddress((void**)&p_Wemb_h, g_Wemb_h);
    cudaGetSymbolAddress((void**)&p_W1_h,   g_W1_h);
    cudaGetSymbolAddress((void**)&p_W2_h,   g_W2_h);
    cudaGetSymbolAddress((void**)&p_emb_h,  g_emb_h);
    cudaGetSymbolAddress((void**)&p_h1_h,   g_h1_h);
    cudaGetSymbolAddress((void**)&p_h2_h,   g_h2_h);
    cudaGetSymbolAddress((void**)&p_bemb,   g_bemb);

    cudaFuncSetAttribute(qkv_attn_wo_kernel, cudaFuncAttributeMaxDynamicSharedMemorySize, FQ_SMEM);
    cudaFuncSetAttribute(head_mma_kernel,    cudaFuncAttributeMaxDynamicSharedMemorySize, HD_SMEM);

    const int MB = NROWS / 128;   // 1024

    // 1) convert obs + pack weights (single launch)
    prep_kernel<<<NROWS*128/1024, 256>>>(obs, W_local, b_local, W_inter, b_inter,
                                         W_intra, b_intra, Wqkv, Wo, W1, W2, Wa, Wv);

    // 2) embeddings: [local | intra_e | inter_e] = tanh(obs @ Wemb^T + b) -> half
    gemm_h<1,1><<<dim3(MB, 3), 256, GEMMH_SMEM>>>(p_obs_h, 128, p_Wemb_h, p_bemb,
                                                  p_emb_h, 384, 128);

    // 3) fused qkv + MMA attention + Wo (writes g_mha_h fp16)
    qkv_attn_wo_kernel<<<dim3(NROWS/64, 4), 256, FQ_SMEM>>>(bqkv, bo);

    // 4) reparameterise + softmax pooling
    reparam_pool_kernel<<<BATCH, 256>>>(eps_intra, eps_inter, att_w, att_b);

    // 5) MLP: W1 -> h1 (half), W2 -> h2 (half)
    gemm_h<1,1><<<dim3(MB, 2), 256, GEMMH_SMEM>>>(p_emb_h, 384, p_W1_h, b1,
                                                  p_h1_h, 256, 384);
    gemm_h<1,1><<<dim3(MB, 2), 256, GEMMH_SMEM>>>(p_h1_h, 256, p_W2_h, b2,
                                                  p_h2_h, 256, 256);

    // 6) tensor-core action/value head with log-softmax
    head_mma_kernel<<<NROWS/128, 256, HD_SMEM>>>(ba, bv, out);
}

// round 15
// speedup vs baseline: 2.1018x; 1.0416x over previous
#include <cuda_runtime.h>
#include <cuda_fp16.h>
#include <math.h>

#define BATCH 4096
#define AGENTS 32
#define NROWS (BATCH*AGENTS)      // 131072
#define NACT 16

// ---------------- scratch (device globals; no allocation) ----------------
__device__ __half g_obs_h[(size_t)NROWS*128];
__device__ __half g_Wemb_h[384*128];
__device__ float  g_bemb[384];
__device__ __half g_Wqkv_h[768*64];            // [net][192][64]
__device__ __half g_Wo_h[4*64*64];             // [net][64][64]
__device__ __half g_W1_h[256*384];
__device__ __half g_W2_h[256*256];
__device__ __half g_WaV_h[24*256];             // rows 0..15 Wa, 16 Wv, 17..23 zero
__device__ __half g_emb_h[(size_t)NROWS*384];  // [local(256) | intra(64) | inter->pooled(64)]
__device__ __half g_mha_h[(size_t)NROWS*256];  // post-Wo fp16
__device__ __half g_h1_h[(size_t)NROWS*256];
__device__ __half g_h2_h[(size_t)NROWS*256];

__device__ __forceinline__ float softplusf(float x) {
    return x > 20.0f ? x : log1pf(__expf(x));
}
__device__ __forceinline__ unsigned pk(float a, float b) {
    __half2 t = __floats2half2_rn(a, b);
    return *(unsigned*)&t;
}
__device__ __forceinline__ void mma_f16(float* c, const unsigned* a, unsigned b0, unsigned b1) {
    asm volatile("mma.sync.aligned.m16n8k16.row.col.f32.f16.f16.f32 "
                 "{%0,%1,%2,%3},{%4,%5,%6,%7},{%8,%9},{%0,%1,%2,%3};"
                 : "+f"(c[0]), "+f"(c[1]), "+f"(c[2]), "+f"(c[3])
                 : "r"(a[0]), "r"(a[1]), "r"(a[2]), "r"(a[3]), "r"(b0), "r"(b1));
}
__device__ __forceinline__ void cp16(unsigned s, const void* g) {
    asm volatile("cp.async.ca.shared.global [%0], [%1], 16;\n" :: "r"(s), "l"(g));
}
__device__ __forceinline__ void ldsm4(unsigned* r, const __half* p) {
    unsigned a = (unsigned)__cvta_generic_to_shared(p);
    asm volatile("ldmatrix.sync.aligned.m8n8.x4.shared.b16 {%0,%1,%2,%3}, [%4];"
                 : "=r"(r[0]), "=r"(r[1]), "=r"(r[2]), "=r"(r[3]) : "r"(a));
}
__device__ __forceinline__ void ldsm2(unsigned* r, const __half* p) {
    unsigned a = (unsigned)__cvta_generic_to_shared(p);
    asm volatile("ldmatrix.sync.aligned.m8n8.x2.shared.b16 {%0,%1}, [%2];"
                 : "=r"(r[0]), "=r"(r[1]) : "r"(a));
}
// A-fragment (16x16 tile at base=&M[row0*str+col0]): lane -> row (lane&15), col (lane>>4)*8
#define LDSM_A(frag, base, str, lane) \
    ldsm4(frag, (base) + ((lane) & 15) * (str) + (((lane) >> 4) << 3))
// B-pair (two n8 tiles, rows row0..row0+15, cols kb..kb+15):
// lane -> row (lane>>4)*8 + (lane&7), col ((lane>>3)&1)*8
#define LDSM_B2(frag, base, str, lane) \
    ldsm4(frag, (base) + ((((lane) >> 4) << 3) + ((lane) & 7)) * (str) + ((((lane) >> 3) & 1) << 3))
// B-single (one n8 tile): lane -> row (lane&7), col ((lane>>3)&1)*8
#define LDSM_B1(frag, base, str, lane) \
    ldsm2(frag, (base) + ((lane) & 7) * (str) + ((((lane) >> 3) & 1) << 3))

// ---------------- merged: obs -> fp16 + pack all weights -> fp16 ----------------
__global__ void prep_kernel(const float* __restrict__ obs,
                            const float* __restrict__ Wl, const float* __restrict__ bl,
                            const float* __restrict__ Wi, const float* __restrict__ bi,
                            const float* __restrict__ Wt, const float* __restrict__ bt,
                            const float* __restrict__ Wqkv, const float* __restrict__ Wo,
                            const float* __restrict__ W1, const float* __restrict__ W2,
                            const float* __restrict__ Wa, const float* __restrict__ Wv) {
    int idx = blockIdx.x * blockDim.x + threadIdx.x;
    {
        size_t i = (size_t)idx * 4;
        float4 v = *(const float4*)(obs + i);
        __half2* o = (__half2*)(g_obs_h + i);
        o[0] = __floats2half2_rn(v.x, v.y);
        o[1] = __floats2half2_rn(v.z, v.w);
    }
    if (idx < 384*128) {
        int row = idx >> 7, col = idx & 127;
        float v;
        if (row < 256)      v = Wl[row*128 + col];
        else if (row < 320) v = Wt[(row-256)*128 + col];
        else                v = Wi[(row-320)*128 + col];
        g_Wemb_h[idx] = __float2half_rn(v);
    }
    if (idx < 768*64)   g_Wqkv_h[idx] = __float2half_rn(Wqkv[idx]);
    if (idx < 4*64*64)  g_Wo_h[idx]   = __float2half_rn(Wo[idx]);
    if (idx < 256*384)  g_W1_h[idx]   = __float2half_rn(W1[idx]);
    if (idx < 256*256)  g_W2_h[idx]   = __float2half_rn(W2[idx]);
    if (idx < 24*256) {
        int row = idx >> 8, col = idx & 255;
        float v = (row < 16) ? Wa[row*256 + col] : (row == 16 ? Wv[col] : 0.0f);
        g_WaV_h[idx] = __float2half_rn(v);
    }
    if (idx < 384)
        g_bemb[idx] = (idx < 256) ? bl[idx] : (idx < 320 ? bt[idx-256] : bi[idx-320]);
}

// ---------------- FP16 tensor-core GEMM (r11-r14 + LDSM fragments) ----------------
#define HSTR 40
template<int EPI, int OUTH>
__global__ __launch_bounds__(256, 2) void gemm_h(
    const __half* __restrict__ X, int ldx,
    const __half* __restrict__ W, const float* __restrict__ bias,
    void* __restrict__ Yv, int ldy, int K)
{
    extern __shared__ __half hsm[];
    __half* Xs = hsm;                        // [2][128*HSTR]
    __half* Ws = hsm + 2*128*HSTR;           // [2][128*HSTR]

    const int tid = threadIdx.x;
    const int m0 = blockIdx.x * 128, n0 = blockIdx.y * 128;
    const int warp = tid >> 5, lane = tid & 31;
    const int wm = (warp & 1) * 64, wn = (warp >> 1) * 32;
    const int l4 = lane >> 2, l2 = lane & 3;

    const int grow = tid & 127, gmat = tid >> 7;
    const __half* grsrc = gmat ? (W + (size_t)(n0 + grow) * K)
                               : (X + (size_t)(m0 + grow) * ldx);
    unsigned gdst0 = (unsigned)__cvta_generic_to_shared(
        (gmat ? Ws : Xs) + grow*HSTR);

    float acc[4][4][4];
#pragma unroll
    for (int a = 0; a < 4; a++)
#pragma unroll
        for (int b = 0; b < 4; b++)
#pragma unroll
            for (int c = 0; c < 4; c++) acc[a][b][c] = 0.0f;

    const int nstage = K >> 5;

#pragma unroll
    for (int q = 0; q < 4; q++)
        cp16(gdst0 + q*16, grsrc + q*8);
    asm volatile("cp.async.commit_group;\n");

    for (int s = 0; s < nstage; s++) {
        asm volatile("cp.async.wait_group 0;\n");
        __syncthreads();

        if (s + 1 < nstage) {
            int k0 = (s + 1) << 5;
            unsigned gd = gdst0 + ((s+1)&1) * 128*HSTR*2;
#pragma unroll
            for (int q = 0; q < 4; q++)
                cp16(gd + q*16, grsrc + k0 + q*8);
            asm volatile("cp.async.commit_group;\n");
        }

        const __half* Xb = Xs + (s & 1) * 128*HSTR;
        const __half* Wb = Ws + (s & 1) * 128*HSTR;
#pragma unroll
        for (int kb = 0; kb < 32; kb += 16) {
            unsigned afr[4][4], bfr[2][4];
#pragma unroll
            for (int mf = 0; mf < 4; mf++)
                LDSM_A(afr[mf], Xb + (wm + mf*16)*HSTR + kb, HSTR, lane);
            LDSM_B2(bfr[0], Wb + wn*HSTR + kb, HSTR, lane);
            LDSM_B2(bfr[1], Wb + (wn + 16)*HSTR + kb, HSTR, lane);
#pragma unroll
            for (int nf = 0; nf < 4; nf++) {
                unsigned b0 = bfr[nf >> 1][(nf & 1)*2];
                unsigned b1 = bfr[nf >> 1][(nf & 1)*2 + 1];
#pragma unroll
                for (int mf = 0; mf < 4; mf++)
                    mma_f16(acc[mf][nf], afr[mf], b0, b1);
            }
        }
    }

#pragma unroll
    for (int nf = 0; nf < 4; nf++) {
        int col = n0 + wn + nf*8 + l2*2;
        float bb0 = bias[col], bb1 = bias[col + 1];
#pragma unroll
        for (int mf = 0; mf < 4; mf++) {
            int row = m0 + wm + mf*16 + l4;
            float v0 = acc[mf][nf][0] + bb0, v1 = acc[mf][nf][1] + bb1;
            float v2 = acc[mf][nf][2] + bb0, v3 = acc[mf][nf][3] + bb1;
            if (EPI == 1) { v0 = tanhf(v0); v1 = tanhf(v1); v2 = tanhf(v2); v3 = tanhf(v3); }
            if (OUTH) {
                __half* Y = (__half*)Yv;
                *(__half2*)(Y + (size_t)row * ldy + col)       = __floats2half2_rn(v0, v1);
                *(__half2*)(Y + (size_t)(row + 8) * ldy + col) = __floats2half2_rn(v2, v3);
            } else {
                float* Y = (float*)Yv;
                float2 o01; o01.x = v0; o01.y = v1;
                float2 o23; o23.x = v2; o23.y = v3;
                *(float2*)(Y + (size_t)row * ldy + col) = o01;
                *(float2*)(Y + (size_t)(row + 8) * ldy + col) = o23;
            }
        }
    }
}
#define GEMMH_SMEM (4*128*HSTR*2)   // 40960 bytes

// ---------------- fused qkv + MMA-attention + Wo (r14 + LDSM) ----------------
#define QKSTR 136
#define VTSTR 72
#define FSTR  72
#define SM_QK 0
#define SM_VT (64*QKSTR*2)                 // 17408
#define SM_XS (SM_VT + 64*VTSTR*2)         // 26624
#define SM_WS (SM_XS + 64*FSTR*2)          // 35840
#define SM_WO (SM_WS + 192*FSTR*2)         // 63488
#define FQ_SMEM (SM_WO + 64*FSTR*2)        // 72704

__global__ __launch_bounds__(256, 3) void qkv_attn_wo_kernel(
    const float* __restrict__ bqkv, const float* __restrict__ bo)
{
    extern __shared__ char sm[];
    __half* QKs = (__half*)(sm + SM_QK);    // [64][136]
    __half* Vt  = (__half*)(sm + SM_VT);    // [64][72]
    __half* Xs  = (__half*)(sm + SM_XS);    // [64][72]
    __half* Sa  = Xs;
    __half* Ws  = (__half*)(sm + SM_WS);    // [192][72]
    __half* Wo  = (__half*)(sm + SM_WO);    // [64][72]

    const int tid = threadIdx.x, warp = tid >> 5, lane = tid & 31;
    const int net = blockIdx.y;
    const int m0 = blockIdx.x * 64;
    const int l4 = lane >> 2, l2 = lane & 3;

    const int xoff = 256 + ((net >= 2) ? 64 : 0);
    {
        int xrow = tid >> 2, seg = tid & 3;
        const __half* src = g_emb_h + (size_t)(m0 + xrow) * 384 + xoff + seg*16;
        unsigned dst = (unsigned)__cvta_generic_to_shared(Xs + xrow*FSTR + seg*16);
        cp16(dst, src); cp16(dst + 16, src + 8);
        if (tid < 192) {
            const __half* ws = g_Wqkv_h + ((size_t)net*192 + tid) * 64;
            unsigned wd = (unsigned)__cvta_generic_to_shared(Ws + tid*FSTR);
#pragma unroll
            for (int q = 0; q < 8; q++) cp16(wd + q*16, ws + q*8);
        } else {
            int row = tid - 192;
            const __half* os = g_Wo_h + (size_t)net*4096 + row*64;
            unsigned od = (unsigned)__cvta_generic_to_shared(Wo + row*FSTR);
#pragma unroll
            for (int q = 0; q < 8; q++) cp16(od + q*16, os + q*8);
        }
    }
    asm volatile("cp.async.commit_group;\n");
    asm volatile("cp.async.wait_group 0;\n");
    __syncthreads();

    // ---- Phase A: qkv mma. M=64 (mf=4), N=192 (8 warps x 24), K=64 ----
    {
        const int wn = warp * 24;
        float acc[4][3][4];
#pragma unroll
        for (int a = 0; a < 4; a++)
#pragma unroll
            for (int b = 0; b < 3; b++)
#pragma unroll
                for (int c = 0; c < 4; c++) acc[a][b][c] = 0.0f;

#pragma unroll
        for (int kb = 0; kb < 64; kb += 16) {
            unsigned afr[4][4], bfr01[4], bfr2[2];
#pragma unroll
            for (int mf = 0; mf < 4; mf++)
                LDSM_A(afr[mf], Xs + (mf*16)*FSTR + kb, FSTR, lane);
            LDSM_B2(bfr01, Ws + wn*FSTR + kb, FSTR, lane);
            LDSM_B1(bfr2,  Ws + (wn + 16)*FSTR + kb, FSTR, lane);
#pragma unroll
            for (int nf = 0; nf < 3; nf++) {
                unsigned b0 = (nf < 2) ? bfr01[nf*2]     : bfr2[0];
                unsigned b1 = (nf < 2) ? bfr01[nf*2 + 1] : bfr2[1];
#pragma unroll
                for (int mf = 0; mf < 4; mf++)
                    mma_f16(acc[mf][nf], afr[mf], b0, b1);
            }
        }
        // epilogue: q,k -> QKs; v -> Vt (transposed)
#pragma unroll
        for (int nf = 0; nf < 3; nf++) {
            int col = wn + nf*8 + l2*2;
            float bb0 = bqkv[net*192 + col], bb1 = bqkv[net*192 + col + 1];
#pragma unroll
            for (int mf = 0; mf < 4; mf++) {
                int row = mf*16 + l4;
                float v0 = acc[mf][nf][0] + bb0, v1 = acc[mf][nf][1] + bb1;
                float v2 = acc[mf][nf][2] + bb0, v3 = acc[mf][nf][3] + bb1;
                if (col < 128) {
                    *(__half2*)(QKs + row*QKSTR + col)       = __floats2half2_rn(v0, v1);
                    *(__half2*)(QKs + (row + 8)*QKSTR + col) = __floats2half2_rn(v2, v3);
                } else {
                    int vc = col - 128;
                    Vt[vc*VTSTR + row]           = __float2half_rn(v0);
                    Vt[(vc + 1)*VTSTR + row]     = __float2half_rn(v1);
                    Vt[vc*VTSTR + row + 8]       = __float2half_rn(v2);
                    Vt[(vc + 1)*VTSTR + row + 8] = __float2half_rn(v3);
                }
            }
        }
    }
    __syncthreads();   // QKs + Vt ready; Xs reads done

    // ---- Phase B: MMA attention. 8 tasks (2 batches x 4 heads), one per warp ----
    {
        const int g = warp >> 2, h = warp & 3;

        unsigned qa[2][4];
#pragma unroll
        for (int mf = 0; mf < 2; mf++)
            LDSM_A(qa[mf], QKs + (g*32 + mf*16)*QKSTR + h*16, QKSTR, lane);

        float sacc[2][4][4];
#pragma unroll
        for (int a = 0; a < 2; a++)
#pragma unroll
            for (int b = 0; b < 4; b++)
#pragma unroll
                for (int c = 0; c < 4; c++) sacc[a][b][c] = 0.0f;
        {
            unsigned kb01[4], kb23[4];
            LDSM_B2(kb01, QKs + (g*32)*QKSTR + 64 + h*16, QKSTR, lane);
            LDSM_B2(kb23, QKs + (g*32 + 16)*QKSTR + 64 + h*16, QKSTR, lane);
#pragma unroll
            for (int nf = 0; nf < 4; nf++) {
                unsigned b0 = (nf < 2) ? kb01[nf*2]     : kb23[(nf-2)*2];
                unsigned b1 = (nf < 2) ? kb01[nf*2 + 1] : kb23[(nf-2)*2 + 1];
#pragma unroll
                for (int mf = 0; mf < 2; mf++)
                    mma_f16(sacc[mf][nf], qa[mf], b0, b1);
            }
        }

        float rs[2][2];
        unsigned pa[2][2][4];
#pragma unroll
        for (int mf = 0; mf < 2; mf++) {
            float m0x = -1e30f, m1x = -1e30f;
#pragma unroll
            for (int nf = 0; nf < 4; nf++) {
                m0x = fmaxf(m0x, fmaxf(sacc[mf][nf][0], sacc[mf][nf][1]));
                m1x = fmaxf(m1x, fmaxf(sacc[mf][nf][2], sacc[mf][nf][3]));
            }
            m0x = fmaxf(m0x, __shfl_xor_sync(0xffffffffu, m0x, 1));
            m0x = fmaxf(m0x, __shfl_xor_sync(0xffffffffu, m0x, 2));
            m1x = fmaxf(m1x, __shfl_xor_sync(0xffffffffu, m1x, 1));
            m1x = fmaxf(m1x, __shfl_xor_sync(0xffffffffu, m1x, 2));

            float p[4][4];
            float s0 = 0.0f, s1 = 0.0f;
#pragma unroll
            for (int nf = 0; nf < 4; nf++) {
                p[nf][0] = __expf(0.25f * (sacc[mf][nf][0] - m0x));
                p[nf][1] = __expf(0.25f * (sacc[mf][nf][1] - m0x));
                p[nf][2] = __expf(0.25f * (sacc[mf][nf][2] - m1x));
                p[nf][3] = __expf(0.25f * (sacc[mf][nf][3] - m1x));
                s0 += p[nf][0] + p[nf][1];
                s1 += p[nf][2] + p[nf][3];
            }
            s0 += __shfl_xor_sync(0xffffffffu, s0, 1);
            s0 += __shfl_xor_sync(0xffffffffu, s0, 2);
            s1 += __shfl_xor_sync(0xffffffffu, s1, 1);
            s1 += __shfl_xor_sync(0xffffffffu, s1, 2);
            rs[mf][0] = 1.0f / s0;
            rs[mf][1] = 1.0f / s1;

            pa[mf][0][0] = pk(p[0][0], p[0][1]);
            pa[mf][0][1] = pk(p[0][2], p[0][3]);
            pa[mf][0][2] = pk(p[1][0], p[1][1]);
            pa[mf][0][3] = pk(p[1][2], p[1][3]);
            pa[mf][1][0] = pk(p[2][0], p[2][1]);
            pa[mf][1][1] = pk(p[2][2], p[2][3]);
            pa[mf][1][2] = pk(p[3][0], p[3][1]);
            pa[mf][1][3] = pk(p[3][2], p[3][3]);
        }

        float oacc[2][2][4];
#pragma unroll
        for (int a = 0; a < 2; a++)
#pragma unroll
            for (int b = 0; b < 2; b++)
#pragma unroll
                for (int c = 0; c < 4; c++) oacc[a][b][c] = 0.0f;
#pragma unroll
        for (int ks = 0; ks < 2; ks++) {
            unsigned vb[4];
            LDSM_B2(vb, Vt + (h*16)*VTSTR + g*32 + ks*16, VTSTR, lane);
#pragma unroll
            for (int nf = 0; nf < 2; nf++) {
                unsigned b0 = vb[nf*2], b1 = vb[nf*2 + 1];
#pragma unroll
                for (int mf = 0; mf < 2; mf++)
                    mma_f16(oacc[mf][nf], pa[mf][ks], b0, b1);
            }
        }

        __syncthreads();   // QKs/Vt reads done before Sa (overlay) write

#pragma unroll
        for (int nf = 0; nf < 2; nf++) {
            int col = h*16 + nf*8 + 2*l2;
#pragma unroll
            for (int mf = 0; mf < 2; mf++) {
                int row = g*32 + mf*16 + l4;
                *(__half2*)(Sa + row*FSTR + col) =
                    __floats2half2_rn(oacc[mf][nf][0]*rs[mf][0], oacc[mf][nf][1]*rs[mf][0]);
                *(__half2*)(Sa + (row + 8)*FSTR + col) =
                    __floats2half2_rn(oacc[mf][nf][2]*rs[mf][1], oacc[mf][nf][3]*rs[mf][1]);
            }
        }
    }
    __syncthreads();   // Sa ready

    // ---- Phase C: Wo mma. M=64 (mf=4), N=64 (8 warps x 8), K=64 ----
    {
        const int wn = warp * 8;
        float acc[4][4];
#pragma unroll
        for (int a = 0; a < 4; a++)
#pragma unroll
            for (int c = 0; c < 4; c++) acc[a][c] = 0.0f;

#pragma unroll
        for (int kb = 0; kb < 64; kb += 16) {
            unsigned afr[4][4], bfr[2];
#pragma unroll
            for (int mf = 0; mf < 4; mf++)
                LDSM_A(afr[mf], Sa + (mf*16)*FSTR + kb, FSTR, lane);
            LDSM_B1(bfr, Wo + wn*FSTR + kb, FSTR, lane);
#pragma unroll
            for (int mf = 0; mf < 4; mf++)
                mma_f16(acc[mf], afr[mf], bfr[0], bfr[1]);
        }
        int col = wn + l2*2;
        float bb0 = bo[net*64 + col], bb1 = bo[net*64 + col + 1];
#pragma unroll
        for (int mf = 0; mf < 4; mf++) {
            int row = mf*16 + l4;
            *(__half2*)(g_mha_h + (size_t)(m0 + row) * 256 + net*64 + col) =
                __floats2half2_rn(acc[mf][0] + bb0, acc[mf][1] + bb1);
            *(__half2*)(g_mha_h + (size_t)(m0 + row + 8) * 256 + net*64 + col) =
                __floats2half2_rn(acc[mf][2] + bb0, acc[mf][3] + bb1);
        }
    }
}

// ---------------- reparameterise + softmax pooling: per batch ----------------
__global__ __launch_bounds__(256) void reparam_pool_kernel(
    const float* __restrict__ eps_intra, const float* __restrict__ eps_inter,
    const float* __restrict__ att_w, const float* __restrict__ att_b)
{
    __shared__ float sinter[32][65];
    __shared__ float ssc[32];
    const int b = blockIdx.x, tid = threadIdx.x;

#pragma unroll
    for (int i = 0; i < 8; i++) {
        int idx = tid + i*256;
        int r = idx >> 6, c = idx & 63;
        const __half* mh = g_mha_h + (size_t)(b*32 + r) * 256;
        float intra = __half2float(mh[c])
                    + softplusf(__half2float(mh[64 + c]) - 5.0f) * eps_intra[(size_t)(b*32 + r)*64 + c];
        g_emb_h[(size_t)(b*32 + r)*384 + 256 + c] = __float2half_rn(intra);
        float inter = __half2float(mh[128 + c])
                    + softplusf(__half2float(mh[192 + c]) - 5.0f) * eps_inter[(size_t)(b*32 + r)*64 + c];
        sinter[r][c] = inter;
    }
    __syncthreads();

    const int warp = tid >> 5, lane = tid & 31;
#pragma unroll
    for (int rr = 0; rr < 4; rr++) {
        int r = warp*4 + rr;
        float part = sinter[r][lane] * att_w[lane] + sinter[r][lane+32] * att_w[lane+32];
#pragma unroll
        for (int m = 16; m > 0; m >>= 1) part += __shfl_xor_sync(0xffffffffu, part, m);
        if (lane == 0) ssc[r] = part + att_b[0];
    }
    __syncthreads();

    if (warp == 0) {
        float l = ssc[lane];
        float mx = l;
#pragma unroll
        for (int m = 16; m > 0; m >>= 1) mx = fmaxf(mx, __shfl_xor_sync(0xffffffffu, mx, m));
        float e = __expf(l - mx);
        float sm = e;
#pragma unroll
        for (int m = 16; m > 0; m >>= 1) sm += __shfl_xor_sync(0xffffffffu, sm, m);
        ssc[lane] = e / sm;
    }
    __syncthreads();

    if (tid < 64) {
        float pooled = 0.0f;
#pragma unroll
        for (int r = 0; r < 32; r++) pooled += ssc[r] * sinter[r][tid];
        __half ph = __float2half_rn(pooled);
#pragma unroll
        for (int r = 0; r < 32; r++)
            g_emb_h[(size_t)(b*32 + r)*384 + 320 + tid] = ph;
    }
}

// ---------------- tensor-core action/value head (r13 + LDSM) ----------------
#define HD_STR 264
#define HD_H2  (128*HD_STR)
#define HD_W   (24*HD_STR)
#define HD_SMEM ((HD_H2 + HD_W)*2)   // 80256 bytes

__global__ __launch_bounds__(256, 2) void head_mma_kernel(
    const float* __restrict__ ba, const float* __restrict__ bv,
    float* __restrict__ out)
{
    extern __shared__ __half hs[];
    __half* H  = hs;             // [128][264]
    __half* Wv = hs + HD_H2;     // [24][264]

    const int tid = threadIdx.x, warp = tid >> 5, lane = tid & 31;
    const int l4 = lane >> 2, l2 = lane & 3;
    const int r0 = blockIdx.x * 128;

    {
        int row = tid >> 1, hb = (tid & 1) * 128;
        const __half* src = g_h2_h + (size_t)(r0 + row) * 256 + hb;
        unsigned dst = (unsigned)__cvta_generic_to_shared(H + row*HD_STR + hb);
#pragma unroll
        for (int q = 0; q < 16; q++) cp16(dst + q*16, src + q*8);
    }
    for (int idx = tid; idx < 768; idx += 256) {
        int row = idx >> 5, seg = idx & 31;
        unsigned dst = (unsigned)__cvta_generic_to_shared(Wv + row*HD_STR + seg*8);
        cp16(dst, g_WaV_h + row*256 + seg*8);
    }
    asm volatile("cp.async.commit_group;\n");
    asm volatile("cp.async.wait_group 0;\n");
    __syncthreads();

    float acc[3][4];
#pragma unroll
    for (int b = 0; b < 3; b++)
#pragma unroll
        for (int c = 0; c < 4; c++) acc[b][c] = 0.0f;

#pragma unroll 4
    for (int kb = 0; kb < 256; kb += 16) {
        unsigned afr[4], bfr01[4], bfr2[2];
        LDSM_A(afr, H + (warp*16)*HD_STR + kb, HD_STR, lane);
        LDSM_B2(bfr01, Wv + kb, HD_STR, lane);
        LDSM_B1(bfr2,  Wv + 16*HD_STR + kb, HD_STR, lane);
        mma_f16(acc[0], afr, bfr01[0], bfr01[1]);
        mma_f16(acc[1], afr, bfr01[2], bfr01[3]);
        mma_f16(acc[2], afr, bfr2[0],  bfr2[1]);
    }

    float ba0 = ba[2*l2],     ba1 = ba[2*l2 + 1];
    float ba2 = ba[8 + 2*l2], ba3 = ba[8 + 2*l2 + 1];

    int row0 = r0 + warp*16 + l4;
#pragma unroll
    for (int rr = 0; rr < 2; rr++) {
        float a0 = acc[0][rr*2]     + ba0;
        float a1 = acc[0][rr*2 + 1] + ba1;
        float a2 = acc[1][rr*2]     + ba2;
        float a3 = acc[1][rr*2 + 1] + ba3;

        float mx = fmaxf(fmaxf(a0, a1), fmaxf(a2, a3));
        mx = fmaxf(mx, __shfl_xor_sync(0xffffffffu, mx, 1));
        mx = fmaxf(mx, __shfl_xor_sync(0xffffffffu, mx, 2));
        float e0 = __expf(a0 - mx), e1 = __expf(a1 - mx);
        float e2 = __expf(a2 - mx), e3 = __expf(a3 - mx);
        float sm = e0 + e1 + e2 + e3;
        sm += __shfl_xor_sync(0xffffffffu, sm, 1);
        sm += __shfl_xor_sync(0xffffffffu, sm, 2);
        float lse = mx + logf(sm);

        int row = row0 + rr*8;
        float2 o01; o01.x = a0 - lse; o01.y = a1 - lse;
        float2 o23; o23.x = a2 - lse; o23.y = a3 - lse;
        *(float2*)(out + (size_t)row * 16 + 2*l2)     = o01;
        *(float2*)(out + (size_t)row * 16 + 8 + 2*l2) = o23;

        if (l2 == 0)
            out[(size_t)NROWS * 16 + row] = acc[2][rr*2] + bv[0];
    }
}

// ---------------- launch ----------------
extern "C" void kernel_launch(void* const* d_in, const int* in_sizes, int n_in,
                              void* d_out, int out_size) {
    const float* obs       = (const float*)d_in[0];
    const float* eps_intra = (const float*)d_in[1];
    const float* eps_inter = (const float*)d_in[2];
    const float* W_local   = (const float*)d_in[3];
    const float* b_local   = (const float*)d_in[4];
    const float* W_inter   = (const float*)d_in[5];
    const float* b_inter   = (const float*)d_in[6];
    const float* W_intra   = (const float*)d_in[7];
    const float* b_intra   = (const float*)d_in[8];
    const float* Wqkv      = (const float*)d_in[9];
    const float* bqkv      = (const float*)d_in[10];
    const float* Wo        = (const float*)d_in[11];
    const float* bo        = (const float*)d_in[12];
    const float* att_w     = (const float*)d_in[13];
    const float* att_b     = (const float*)d_in[14];
    const float* W1        = (const float*)d_in[15];
    const float* b1        = (const float*)d_in[16];
    const float* W2        = (const float*)d_in[17];
    const float* b2        = (const float*)d_in[18];
    const float* Wa        = (const float*)d_in[19];
    const float* ba        = (const float*)d_in[20];
    const float* Wv        = (const float*)d_in[21];
    const float* bv        = (const float*)d_in[22];
    float* out = (float*)d_out;

    __half *p_obs_h, *p_Wemb_h, *p_W1_h, *p_W2_h, *p_emb_h, *p_h1_h, *p_h2_h;
    float  *p_bemb;
    cudaGetSymbolAddress((void**)&p_obs_h,  g_obs_h);
    cudaGetSymbolAddress((void**)&p_Wemb_h, g_Wemb_h);
    cudaGetSymbolAddress((void**)&p_W1_h,   g_W1_h);
    cudaGetSymbolAddress((void**)&p_W2_h,   g_W2_h);
    cudaGetSymbolAddress((void**)&p_emb_h,  g_emb_h);
    cudaGetSymbolAddress((void**)&p_h1_h,   g_h1_h);
    cudaGetSymbolAddress((void**)&p_h2_h,   g_h2_h);
    cudaGetSymbolAddress((void**)&p_bemb,   g_bemb);

    cudaFuncSetAttribute(qkv_attn_wo_kernel, cudaFuncAttributeMaxDynamicSharedMemorySize, FQ_SMEM);
    cudaFuncSetAttribute(head_mma_kernel,    cudaFuncAttributeMaxDynamicSharedMemorySize, HD_SMEM);

    const int MB = NROWS / 128;   // 1024

    // 1) convert obs + pack weights
    prep_kernel<<<NROWS*128/1024, 256>>>(obs, W_local, b_local, W_inter, b_inter,
                                         W_intra, b_intra, Wqkv, Wo, W1, W2, Wa, Wv);

    // 2) embeddings
    gemm_h<1,1><<<dim3(MB, 3), 256, GEMMH_SMEM>>>(p_obs_h, 128, p_Wemb_h, p_bemb,
                                                  p_emb_h, 384, 128);

    // 3) fused qkv + MMA attention + Wo
    qkv_attn_wo_kernel<<<dim3(NROWS/64, 4), 256, FQ_SMEM>>>(bqkv, bo);

    // 4) reparameterise + softmax pooling
    reparam_pool_kernel<<<BATCH, 256>>>(eps_intra, eps_inter, att_w, att_b);

    // 5) MLP
    gemm_h<1,1><<<dim3(MB, 2), 256, GEMMH_SMEM>>>(p_emb_h, 384, p_W1_h, b1,
                                                  p_h1_h, 256, 384);
    gemm_h<1,1><<<dim3(MB, 2), 256, GEMMH_SMEM>>>(p_h1_h, 256, p_W2_h, b2,
                                                  p_h2_h, 256, 256);

    // 6) tensor-core action/value head
    head_mma_kernel<<<NROWS/128, 256, HD_SMEM>>>(ba, bv, out);
}